// round 7
// baseline (speedup 1.0000x reference)
#include <cuda_runtime.h>
#include <cuda_bf16.h>
#include <math.h>

#define BB 2
#define QLEN 1024
#define MLEN 1024
#define KLEN 2048
#define EE 1024
#define HH 16
#define DH 64
#define HD 1024   // HH*DH
#define FF 4096

// ---------------- scratch ----------------
static __device__ float g_cat[(size_t)BB * KLEN * EE];
static __device__ float g_q  [(size_t)BB * QLEN * HD];   // used as bf16
static __device__ float g_k  [(size_t)BB * KLEN * HD];   // used as bf16
static __device__ float g_v  [(size_t)BB * KLEN * HD];   // used as bf16
static __device__ float g_r  [(size_t)KLEN * HD];        // used as bf16
static __device__ float g_att[(size_t)BB * QLEN * HD];
static __device__ float g_o  [(size_t)BB * QLEN * EE];
static __device__ float g_x  [(size_t)BB * QLEN * EE];
static __device__ float g_ffn[(size_t)BB * QLEN * FF];
static __device__ float g_y  [(size_t)BB * QLEN * EE];

// ---------------- helpers ----------------
__device__ __forceinline__ unsigned pack_bf2(float lo, float hi) {
    unsigned u; asm("cvt.rn.bf16x2.f32 %0, %1, %2;" : "=r"(u) : "f"(hi), "f"(lo)); return u;
}
__device__ __forceinline__ void mma8(float* c, const unsigned* a, const unsigned* b) {
    asm volatile("mma.sync.aligned.m16n8k8.row.col.f32.tf32.tf32.f32 "
        "{%0,%1,%2,%3}, {%4,%5,%6,%7}, {%8,%9}, {%0,%1,%2,%3};\n"
        : "+f"(c[0]), "+f"(c[1]), "+f"(c[2]), "+f"(c[3])
        : "r"(a[0]), "r"(a[1]), "r"(a[2]), "r"(a[3]), "r"(b[0]), "r"(b[1]));
}
__device__ __forceinline__ void mma16(float* c, const unsigned* a, const unsigned* b) {
    asm volatile("mma.sync.aligned.m16n8k16.row.col.f32.bf16.bf16.f32 "
        "{%0,%1,%2,%3}, {%4,%5,%6,%7}, {%8,%9}, {%0,%1,%2,%3};\n"
        : "+f"(c[0]), "+f"(c[1]), "+f"(c[2]), "+f"(c[3])
        : "r"(a[0]), "r"(a[1]), "r"(a[2]), "r"(a[3]), "r"(b[0]), "r"(b[1]));
}
__device__ __forceinline__ void cpa16(unsigned saddr, const void* g) {
    asm volatile("cp.async.cg.shared.global [%0], [%1], 16;" :: "r"(saddr), "l"(g));
}
__device__ __forceinline__ void cpa_commit() { asm volatile("cp.async.commit_group;"); }
__device__ __forceinline__ void cpa_wait2() { asm volatile("cp.async.wait_group 2;"); }
__device__ __forceinline__ void cpa_waitall() { asm volatile("cp.async.wait_group 0;"); }

// ---------------- cat = concat(member, w) ----------------
__global__ __launch_bounds__(256) void copy_cat_kernel(
    const float4* __restrict__ w, const float4* __restrict__ member, float4* __restrict__ cat)
{
    size_t i = (size_t)blockIdx.x * 256 + threadIdx.x;
    int e4 = (int)(i % (EE / 4));
    size_t t2 = i / (EE / 4);
    int kl = (int)(t2 % KLEN);
    int b  = (int)(t2 / KLEN);
    float4 v;
    if (kl < MLEN) v = member[((size_t)b * MLEN + kl) * (EE / 4) + e4];
    else           v = w[((size_t)b * QLEN + (kl - MLEN)) * (EE / 4) + e4];
    cat[i] = v;
}

// ================= tf32 MMA GEMM, NN; 4-stage cp.async pipeline =================
// stage = As[128][20] (2560 w) + Bs[16][136] (2176 w) = 4736 words
#define GSTG 4736
#define GEMM_SMEM (4 * GSTG * 4)   // 75776 bytes
__global__ __launch_bounds__(256, 2) void gemm_nn_tf32(
    const float* __restrict__ A, int lda, const float* __restrict__ B, int ldb,
    float* __restrict__ C, int ldc, int N, int K, int relu, int obf)
{
    extern __shared__ __align__(16) unsigned dsm[];
    const unsigned sbase = (unsigned)__cvta_generic_to_shared(dsm);

    const int t = threadIdx.x;
    const int lane = t & 31, warp = t >> 5;
    const int g = lane >> 2, tig = lane & 3;
    const int wm0 = (warp >> 2) * 64, wn0 = (warp & 3) * 32;
    const int m0 = blockIdx.y * 128, n0 = blockIdx.x * 128;

    // loader indices (2 chunks of 16B each for A and B per thread)
    const int ar0 = t >> 1,        acw = (t & 1) * 8;     // A: rows t>>1, 2x16B -> cols acw, acw+4
    const int br0 = t >> 5,        bcw = (t & 31) * 4;    // B: row pairs

    const int nk = K / 16;

    // prologue: issue stages 0..2
    #pragma unroll
    for (int s = 0; s < 3; s++) {
        unsigned base = sbase + (s & 3) * (GSTG * 4);
        int k0 = s * 16;
        #pragma unroll
        for (int i = 0; i < 2; i++) {
            int id = t + 256 * i;
            int row = id >> 2, ch = (id & 3) * 4;
            cpa16(base + (row * 20 + ch) * 4, A + (size_t)(m0 + row) * lda + k0 + ch);
        }
        #pragma unroll
        for (int i = 0; i < 2; i++) {
            int id = t + 256 * i;
            int row = id >> 5, ch = (id & 31) * 4;
            cpa16(base + (2560 + row * 136 + ch) * 4, B + (size_t)(k0 + row) * ldb + n0 + ch);
        }
        cpa_commit();
    }

    float c[4][4][4] = {};

    for (int kt = 0; kt < nk; kt++) {
        cpa_wait2();
        __syncthreads();

        // issue stage kt+3 into buffer (kt+3)&3 (freed: computed at kt-1)
        if (kt + 3 < nk) {
            unsigned base = sbase + ((kt + 3) & 3) * (GSTG * 4);
            int k0 = (kt + 3) * 16;
            #pragma unroll
            for (int i = 0; i < 2; i++) {
                int id = t + 256 * i;
                int row = id >> 2, ch = (id & 3) * 4;
                cpa16(base + (row * 20 + ch) * 4, A + (size_t)(m0 + row) * lda + k0 + ch);
            }
            #pragma unroll
            for (int i = 0; i < 2; i++) {
                int id = t + 256 * i;
                int row = id >> 5, ch = (id & 31) * 4;
                cpa16(base + (2560 + row * 136 + ch) * 4, B + (size_t)(k0 + row) * ldb + n0 + ch);
            }
        }
        cpa_commit();   // always commit to keep group count invariant

        // compute stage kt
        const unsigned* As = dsm + (kt & 3) * GSTG;
        const unsigned* Bs = As + 2560;
        #pragma unroll
        for (int ksx = 0; ksx < 2; ksx++) {
            int ks = ksx * 8;
            unsigned af[4][4], bf[4][2];
            #pragma unroll
            for (int mi = 0; mi < 4; mi++) {
                int m = wm0 + mi * 16 + g;
                af[mi][0] = As[m * 20 + ks + tig];
                af[mi][1] = As[(m + 8) * 20 + ks + tig];
                af[mi][2] = As[m * 20 + ks + tig + 4];
                af[mi][3] = As[(m + 8) * 20 + ks + tig + 4];
            }
            #pragma unroll
            for (int ni = 0; ni < 4; ni++) {
                int n = wn0 + ni * 8 + g;
                bf[ni][0] = Bs[(ks + tig) * 136 + n];
                bf[ni][1] = Bs[(ks + tig + 4) * 136 + n];
            }
            #pragma unroll
            for (int mi = 0; mi < 4; mi++)
                #pragma unroll
                for (int ni = 0; ni < 4; ni++)
                    mma8(c[mi][ni], af[mi], bf[ni]);
        }
    }

    #pragma unroll
    for (int mi = 0; mi < 4; mi++) {
        int row = m0 + wm0 + mi * 16 + g;
        #pragma unroll
        for (int ni = 0; ni < 4; ni++) {
            int col = n0 + wn0 + ni * 8 + 2 * tig;
            float2 v0 = make_float2(c[mi][ni][0], c[mi][ni][1]);
            float2 v1 = make_float2(c[mi][ni][2], c[mi][ni][3]);
            if (relu) {
                v0.x = fmaxf(v0.x, 0.f); v0.y = fmaxf(v0.y, 0.f);
                v1.x = fmaxf(v1.x, 0.f); v1.y = fmaxf(v1.y, 0.f);
            }
            if (obf) {
                unsigned* Cu = (unsigned*)C;
                Cu[((size_t)row * ldc + col) / 2]       = pack_bf2(v0.x, v0.y);
                Cu[((size_t)(row + 8) * ldc + col) / 2] = pack_bf2(v1.x, v1.y);
            } else {
                *(float2*)&C[(size_t)row * ldc + col] = v0;
                *(float2*)&C[(size_t)(row + 8) * ldc + col] = v1;
            }
        }
    }
}

// ================= bf16 pipelined flash attention with rel-shift (R5, proven) =================
#define QS 36        // word stride (72 bf16)
#define GS 264       // sG stride, bf16
#define PS 68        // P word stride (136 bf16)
#define OFF_QW 0
#define OFF_QR 18432
#define OFF_K  36864
#define OFF_V  73728
#define OFF_R  110592
#define OFF_G  147456
#define OFF_RED 215040
#define FA_SMEM 219136

__global__ __launch_bounds__(256, 1) void flash_attn(
    const __nv_bfloat16* __restrict__ Qb, const __nv_bfloat16* __restrict__ Kb,
    const __nv_bfloat16* __restrict__ Vb, const __nv_bfloat16* __restrict__ Rb,
    const float* __restrict__ rwb, const float* __restrict__ rrb,
    float* __restrict__ Om)
{
    extern __shared__ __align__(16) char smem[];
    unsigned*  uQw = (unsigned*)(smem + OFF_QW);
    unsigned*  uQr = (unsigned*)(smem + OFF_QR);
    unsigned*  uG  = (unsigned*)(smem + OFF_G);
    __nv_bfloat16* hG = (__nv_bfloat16*)(smem + OFF_G);
    float* redM = (float*)(smem + OFF_RED);
    float* redS = redM + 512;
    const unsigned sb = (unsigned)__cvta_generic_to_shared(smem);

    const int t = threadIdx.x;
    const int lane = t & 31, warp = t >> 5;
    const int g = lane >> 2, tig = lane & 3;
    const int wm0 = (warp >> 2) * 64;
    const int wn  = warp & 3;
    const int wn0 = wn * 32;
    const int wn0p = wn * 16;

    const int bh = blockIdx.z, b = bh >> 4, h = bh & 15;
    const int q0 = (gridDim.y - 1 - blockIdx.y) * 128;
    const int ntiles = q0 / 128 + 9;

    const __nv_bfloat16* gK = Kb + ((size_t)b * KLEN) * HD + h * DH;
    const __nv_bfloat16* gV = Vb + ((size_t)b * KLEN) * HD + h * DH;
    const __nv_bfloat16* gR = Rb + h * DH;

    {
        #pragma unroll
        for (int i = 0; i < 4; i++) {
            int id = t + 256 * i, row = id >> 3, ch = id & 7;
            cpa16(sb + OFF_K + row * 144 + ch * 16, gK + (size_t)row * HD + ch * 8);
            cpa16(sb + OFF_V + row * 144 + ch * 16, gV + (size_t)row * HD + ch * 8);
        }
        cpa_commit();
        int j0 = 0 - q0 + (QLEN - 128);
        #pragma unroll
        for (int i = 0; i < 8; i++) {
            int id = t + 256 * i, row = id >> 3, ch = id & 7;
            int j = j0 + row; if (j > KLEN - 1) j = KLEN - 1;
            cpa16(sb + OFF_R + row * 144 + ch * 16, gR + (size_t)j * HD + ch * 8);
        }
        cpa_commit();
    }

    {
        const __nv_bfloat16* qsrc = Qb + ((size_t)b * QLEN + q0) * HD + h * DH;
        int lr = t >> 1, lc0 = (t & 1) * 32;
        #pragma unroll
        for (int i = 0; i < 8; i++) {
            int c = lc0 + i * 4;
            uint2 u = *(const uint2*)&qsrc[(size_t)lr * HD + c];
            __nv_bfloat162 q01 = *(__nv_bfloat162*)&u.x;
            __nv_bfloat162 q23 = *(__nv_bfloat162*)&u.y;
            float4 bw = *(const float4*)&rwb[h * DH + c];
            float4 br = *(const float4*)&rrb[h * DH + c];
            float f0 = __bfloat162float(q01.x), f1 = __bfloat162float(q01.y);
            float f2 = __bfloat162float(q23.x), f3 = __bfloat162float(q23.y);
            uQw[lr * QS + c / 2]     = pack_bf2(f0 + bw.x, f1 + bw.y);
            uQw[lr * QS + c / 2 + 1] = pack_bf2(f2 + bw.z, f3 + bw.w);
            uQr[lr * QS + c / 2]     = pack_bf2(f0 + br.x, f1 + br.y);
            uQr[lr * QS + c / 2 + 1] = pack_bf2(f2 + br.z, f3 + br.w);
        }
    }

    float o[4][2][4] = {};
    float mrun[4][2], lrun[4][2];
    #pragma unroll
    for (int mi = 0; mi < 4; mi++)
        #pragma unroll
        for (int hh = 0; hh < 2; hh++) { mrun[mi][hh] = -INFINITY; lrun[mi][hh] = 0.f; }

    int buf = 0;
    for (int kt = 0; kt < ntiles; kt++) {
        const int k0 = kt * 128;
        cpa_waitall();
        __syncthreads();

        if (kt + 1 < ntiles) {
            const __nv_bfloat16* nK = gK + (size_t)(k0 + 128) * HD;
            const __nv_bfloat16* nV = gV + (size_t)(k0 + 128) * HD;
            unsigned kb = OFF_K + (buf ^ 1) * 18432, vb2 = OFF_V + (buf ^ 1) * 18432;
            #pragma unroll
            for (int i = 0; i < 4; i++) {
                int id = t + 256 * i, row = id >> 3, ch = id & 7;
                cpa16(sb + kb + row * 144 + ch * 16, nK + (size_t)row * HD + ch * 8);
                cpa16(sb + vb2 + row * 144 + ch * 16, nV + (size_t)row * HD + ch * 8);
            }
            cpa_commit();
        }

        float acc[4][4][4] = {};
        {
            const unsigned* uK = (const unsigned*)(smem + OFF_K + buf * 18432);
            #pragma unroll
            for (int ks = 0; ks < 4; ks++) {
                unsigned af[4][4], bf[4][2];
                #pragma unroll
                for (int mi = 0; mi < 4; mi++) {
                    int m = wm0 + mi * 16 + g;
                    af[mi][0] = uQw[m * QS + ks * 8 + tig];
                    af[mi][1] = uQw[(m + 8) * QS + ks * 8 + tig];
                    af[mi][2] = uQw[m * QS + ks * 8 + tig + 4];
                    af[mi][3] = uQw[(m + 8) * QS + ks * 8 + tig + 4];
                }
                #pragma unroll
                for (int ni = 0; ni < 4; ni++) {
                    int n = wn0 + ni * 8 + g;
                    bf[ni][0] = uK[n * QS + ks * 8 + tig];
                    bf[ni][1] = uK[n * QS + ks * 8 + tig + 4];
                }
                #pragma unroll
                for (int mi = 0; mi < 4; mi++)
                    #pragma unroll
                    for (int ni = 0; ni < 4; ni++)
                        mma16(acc[mi][ni], af[mi], bf[ni]);
            }
        }

        {
            const unsigned* uR = (const unsigned*)(smem + OFF_R);
            #pragma unroll
            for (int h2 = 0; h2 < 2; h2++) {
                float ga[4][4][4] = {};
                #pragma unroll
                for (int ks = 0; ks < 4; ks++) {
                    unsigned af[4][4], bf[4][2];
                    #pragma unroll
                    for (int mi = 0; mi < 4; mi++) {
                        int m = wm0 + mi * 16 + g;
                        af[mi][0] = uQr[m * QS + ks * 8 + tig];
                        af[mi][1] = uQr[(m + 8) * QS + ks * 8 + tig];
                        af[mi][2] = uQr[m * QS + ks * 8 + tig + 4];
                        af[mi][3] = uQr[(m + 8) * QS + ks * 8 + tig + 4];
                    }
                    #pragma unroll
                    for (int ni = 0; ni < 4; ni++) {
                        int n = h2 * 128 + wn0 + ni * 8 + g;
                        bf[ni][0] = uR[n * QS + ks * 8 + tig];
                        bf[ni][1] = uR[n * QS + ks * 8 + tig + 4];
                    }
                    #pragma unroll
                    for (int mi = 0; mi < 4; mi++)
                        #pragma unroll
                        for (int ni = 0; ni < 4; ni++)
                            mma16(ga[mi][ni], af[mi], bf[ni]);
                }
                #pragma unroll
                for (int mi = 0; mi < 4; mi++)
                    #pragma unroll
                    for (int ni = 0; ni < 4; ni++)
                        #pragma unroll
                        for (int hh = 0; hh < 2; hh++) {
                            int r = wm0 + mi * 16 + g + 8 * hh;
                            int col = h2 * 128 + wn0 + ni * 8 + 2 * tig;
                            uG[(r * GS + col) / 2] = pack_bf2(ga[mi][ni][2 * hh], ga[mi][ni][2 * hh + 1]);
                        }
            }
        }
        __syncthreads();

        if (kt + 1 < ntiles) {
            int j0n = (k0 + 128) - q0 + (QLEN - 128);
            #pragma unroll
            for (int i = 0; i < 8; i++) {
                int id = t + 256 * i, row = id >> 3, ch = id & 7;
                int j = j0n + row; if (j > KLEN - 1) j = KLEN - 1;
                cpa16(sb + OFF_R + row * 144 + ch * 16, gR + (size_t)j * HD + ch * 8);
            }
            cpa_commit();
        }

        #pragma unroll
        for (int mi = 0; mi < 4; mi++)
            #pragma unroll
            for (int ni = 0; ni < 4; ni++)
                #pragma unroll
                for (int hh = 0; hh < 2; hh++)
                    #pragma unroll
                    for (int e = 0; e < 2; e++) {
                        int r = wm0 + mi * 16 + g + 8 * hh;
                        int col = wn0 + ni * 8 + 2 * tig + e;
                        float s = acc[mi][ni][2 * hh + e]
                                + __bfloat162float(hG[r * GS + (col - r + 127)]);
                        acc[mi][ni][2 * hh + e] =
                            ((k0 + col) <= (q0 + r) + MLEN) ? s * 0.03125f : -1e30f;
                    }

        float mw[4][2];
        #pragma unroll
        for (int mi = 0; mi < 4; mi++)
            #pragma unroll
            for (int hh = 0; hh < 2; hh++) {
                float m8 = -INFINITY;
                #pragma unroll
                for (int ni = 0; ni < 4; ni++) {
                    m8 = fmaxf(m8, fmaxf(acc[mi][ni][2 * hh], acc[mi][ni][2 * hh + 1]));
                }
                m8 = fmaxf(m8, __shfl_xor_sync(0xffffffffu, m8, 1));
                m8 = fmaxf(m8, __shfl_xor_sync(0xffffffffu, m8, 2));
                mw[mi][hh] = m8;
                float sw = 0.f;
                #pragma unroll
                for (int ni = 0; ni < 4; ni++)
                    #pragma unroll
                    for (int e = 0; e < 2; e++) {
                        float p = __expf(acc[mi][ni][2 * hh + e] - m8);
                        acc[mi][ni][2 * hh + e] = p;
                        sw += p;
                    }
                sw += __shfl_xor_sync(0xffffffffu, sw, 1);
                sw += __shfl_xor_sync(0xffffffffu, sw, 2);
                if (tig == 0) {
                    int r = wm0 + mi * 16 + g + 8 * hh;
                    redM[wn * 128 + r] = m8;
                    redS[wn * 128 + r] = sw;
                }
            }
        __syncthreads();

        float fsc[4][2];
        #pragma unroll
        for (int mi = 0; mi < 4; mi++)
            #pragma unroll
            for (int hh = 0; hh < 2; hh++) {
                int r = wm0 + mi * 16 + g + 8 * hh;
                float m0v = redM[r], m1v = redM[128 + r], m2v = redM[256 + r], m3v = redM[384 + r];
                float mnew = fmaxf(mrun[mi][hh],
                              fmaxf(fmaxf(m0v, m1v), fmaxf(m2v, m3v)));
                float ladd = redS[r] * __expf(m0v - mnew) + redS[128 + r] * __expf(m1v - mnew)
                           + redS[256 + r] * __expf(m2v - mnew) + redS[384 + r] * __expf(m3v - mnew);
                float alpha = __expf(mrun[mi][hh] - mnew);
                lrun[mi][hh] = lrun[mi][hh] * alpha + ladd;
                mrun[mi][hh] = mnew;
                fsc[mi][hh] = __expf(mw[mi][hh] - mnew);
                #pragma unroll
                for (int ni2 = 0; ni2 < 2; ni2++) {
                    o[mi][ni2][2 * hh]     *= alpha;
                    o[mi][ni2][2 * hh + 1] *= alpha;
                }
            }
        #pragma unroll
        for (int mi = 0; mi < 4; mi++)
            #pragma unroll
            for (int ni = 0; ni < 4; ni++)
                #pragma unroll
                for (int hh = 0; hh < 2; hh++) {
                    int r = wm0 + mi * 16 + g + 8 * hh;
                    int col = wn0 + ni * 8 + 2 * tig;
                    uG[r * PS + col / 2] = pack_bf2(
                        acc[mi][ni][2 * hh] * fsc[mi][hh],
                        acc[mi][ni][2 * hh + 1] * fsc[mi][hh]);
                }
        __syncthreads();

        {
            const unsigned short* hV = (const unsigned short*)(smem + OFF_V + buf * 18432);
            #pragma unroll
            for (int ks = 0; ks < 8; ks++) {
                unsigned af[4][4], bf[2][2];
                #pragma unroll
                for (int mi = 0; mi < 4; mi++) {
                    int m = wm0 + mi * 16 + g;
                    af[mi][0] = uG[m * PS + ks * 8 + tig];
                    af[mi][1] = uG[(m + 8) * PS + ks * 8 + tig];
                    af[mi][2] = uG[m * PS + ks * 8 + tig + 4];
                    af[mi][3] = uG[(m + 8) * PS + ks * 8 + tig + 4];
                }
                #pragma unroll
                for (int ni2 = 0; ni2 < 2; ni2++) {
                    int n = wn0p + ni2 * 8 + g;
                    unsigned lo0 = hV[(ks * 16 + 2 * tig) * 72 + n];
                    unsigned hi0 = hV[(ks * 16 + 2 * tig + 1) * 72 + n];
                    unsigned lo1 = hV[(ks * 16 + 2 * tig + 8) * 72 + n];
                    unsigned hi1 = hV[(ks * 16 + 2 * tig + 9) * 72 + n];
                    bf[ni2][0] = lo0 | (hi0 << 16);
                    bf[ni2][1] = lo1 | (hi1 << 16);
                }
                #pragma unroll
                for (int mi = 0; mi < 4; mi++)
                    #pragma unroll
                    for (int ni2 = 0; ni2 < 2; ni2++)
                        mma16(o[mi][ni2], af[mi], bf[ni2]);
            }
        }
        buf ^= 1;
    }

    #pragma unroll
    for (int mi = 0; mi < 4; mi++)
        #pragma unroll
        for (int ni2 = 0; ni2 < 2; ni2++)
            #pragma unroll
            for (int hh = 0; hh < 2; hh++) {
                int r = wm0 + mi * 16 + g + 8 * hh;
                int d = wn0p + ni2 * 8 + 2 * tig;
                float inv = 1.0f / lrun[mi][hh];
                *(float2*)&Om[((size_t)b * QLEN + q0 + r) * HD + h * DH + d] =
                    make_float2(o[mi][ni2][2 * hh] * inv, o[mi][ni2][2 * hh + 1] * inv);
            }
}

// ---------------- out = LayerNorm(a + b), rows of EE ----------------
__global__ __launch_bounds__(256) void add_ln_kernel(
    const float* __restrict__ A, const float* __restrict__ Bv,
    const float* __restrict__ gamma, const float* __restrict__ beta,
    float* __restrict__ out)
{
    __shared__ float red[256];
    const size_t row = blockIdx.x;
    const int t = threadIdx.x;
    float4 va = ((const float4*)(A + row * EE))[t];
    float4 vb = ((const float4*)(Bv + row * EE))[t];
    float4 v = make_float4(va.x + vb.x, va.y + vb.y, va.z + vb.z, va.w + vb.w);

    red[t] = v.x + v.y + v.z + v.w; __syncthreads();
    for (int s = 128; s > 0; s >>= 1) { if (t < s) red[t] += red[t + s]; __syncthreads(); }
    const float mean = red[0] * (1.0f / EE); __syncthreads();

    float dx = v.x - mean, dy = v.y - mean, dz = v.z - mean, dw = v.w - mean;
    red[t] = dx * dx + dy * dy + dz * dz + dw * dw; __syncthreads();
    for (int s = 128; s > 0; s >>= 1) { if (t < s) red[t] += red[t + s]; __syncthreads(); }
    const float inv = rsqrtf(red[0] * (1.0f / EE) + 1e-3f);

    float4 gm = ((const float4*)gamma)[t];
    float4 bt = ((const float4*)beta)[t];
    float4 o;
    o.x = dx * inv * gm.x + bt.x; o.y = dy * inv * gm.y + bt.y;
    o.z = dz * inv * gm.z + bt.z; o.w = dw * inv * gm.w + bt.w;
    ((float4*)(out + row * EE))[t] = o;
}

// ---------------- launch ----------------
extern "C" void kernel_launch(void* const* d_in, const int* in_sizes, int n_in,
                              void* d_out, int out_size)
{
    const float* w      = (const float*)d_in[0];
    const float* r      = (const float*)d_in[1];
    const float* member = (const float*)d_in[2];
    const float* Wq  = (const float*)d_in[4];
    const float* Wk  = (const float*)d_in[5];
    const float* Wv  = (const float*)d_in[6];
    const float* Wr  = (const float*)d_in[7];
    const float* Wo  = (const float*)d_in[8];
    const float* rwb = (const float*)d_in[9];
    const float* rrb = (const float*)d_in[10];
    const float* ln1g = (const float*)d_in[11];
    const float* ln1b = (const float*)d_in[12];
    const float* W1  = (const float*)d_in[13];
    const float* W2  = (const float*)d_in[14];
    const float* ln2g = (const float*)d_in[15];
    const float* ln2b = (const float*)d_in[16];
    float* out = (float*)d_out;

    static float *p_cat = nullptr, *p_q, *p_k, *p_v, *p_r,
                 *p_att, *p_o, *p_x, *p_ffn, *p_y;
    if (!p_cat) {
        cudaGetSymbolAddress((void**)&p_cat, g_cat);
        cudaGetSymbolAddress((void**)&p_q,   g_q);
        cudaGetSymbolAddress((void**)&p_k,   g_k);
        cudaGetSymbolAddress((void**)&p_v,   g_v);
        cudaGetSymbolAddress((void**)&p_r,   g_r);
        cudaGetSymbolAddress((void**)&p_att, g_att);
        cudaGetSymbolAddress((void**)&p_o,   g_o);
        cudaGetSymbolAddress((void**)&p_x,   g_x);
        cudaGetSymbolAddress((void**)&p_ffn, g_ffn);
        cudaGetSymbolAddress((void**)&p_y,   g_y);
        cudaFuncSetAttribute(flash_attn, cudaFuncAttributeMaxDynamicSharedMemorySize, FA_SMEM);
        cudaFuncSetAttribute(gemm_nn_tf32, cudaFuncAttributeMaxDynamicSharedMemorySize, GEMM_SMEM);
    }

    // 1. cat
    copy_cat_kernel<<<(BB * KLEN * EE / 4) / 256, 256>>>(
        (const float4*)w, (const float4*)member, (float4*)p_cat);

    // 2. projections (tf32 MMA, bf16 output)
    gemm_nn_tf32<<<dim3(HD / 128, (BB * QLEN) / 128), 256, GEMM_SMEM>>>(
        w, EE, Wq, HD, p_q, HD, HD, EE, 0, 1);
    gemm_nn_tf32<<<dim3(HD / 128, (BB * KLEN) / 128), 256, GEMM_SMEM>>>(
        p_cat, EE, Wk, HD, p_k, HD, HD, EE, 0, 1);
    gemm_nn_tf32<<<dim3(HD / 128, (BB * KLEN) / 128), 256, GEMM_SMEM>>>(
        p_cat, EE, Wv, HD, p_v, HD, HD, EE, 0, 1);
    gemm_nn_tf32<<<dim3(HD / 128, KLEN / 128), 256, GEMM_SMEM>>>(
        r, EE, Wr, HD, p_r, HD, HD, EE, 0, 1);

    // 3. fused attention
    flash_attn<<<dim3(1, QLEN / 128, BB * HH), 256, FA_SMEM>>>(
        (const __nv_bfloat16*)p_q, (const __nv_bfloat16*)p_k,
        (const __nv_bfloat16*)p_v, (const __nv_bfloat16*)p_r,
        rwb, rrb, p_att);

    // 4. output projection + LN1
    gemm_nn_tf32<<<dim3(EE / 128, (BB * QLEN) / 128), 256, GEMM_SMEM>>>(
        p_att, HD, Wo, EE, p_o, EE, EE, HD, 0, 0);
    add_ln_kernel<<<BB * QLEN, 256>>>(w, p_o, ln1g, ln1b, p_x);

    // 5. FFN + LN2 -> out
    gemm_nn_tf32<<<dim3(FF / 128, (BB * QLEN) / 128), 256, GEMM_SMEM>>>(
        p_x, EE, W1, FF, p_ffn, FF, FF, EE, 1, 0);
    gemm_nn_tf32<<<dim3(EE / 128, (BB * QLEN) / 128), 256, GEMM_SMEM>>>(
        p_ffn, FF, W2, EE, p_y, EE, EE, FF, 0, 0);
    add_ln_kernel<<<BB * QLEN, 256>>>(p_y, p_x, ln2g, ln2b, out);
}

// round 8
// speedup vs baseline: 1.2492x; 1.2492x over previous
#include <cuda_runtime.h>
#include <cuda_bf16.h>
#include <math.h>

#define BB 2
#define QLEN 1024
#define MLEN 1024
#define KLEN 2048
#define EE 1024
#define HH 16
#define DH 64
#define HD 1024   // HH*DH
#define FF 4096

// ---------------- scratch ----------------
static __device__ float g_cat[(size_t)BB * KLEN * EE];
static __device__ float g_q  [(size_t)BB * QLEN * HD];   // used as bf16
static __device__ float g_k  [(size_t)BB * KLEN * HD];   // used as bf16
static __device__ float g_v  [(size_t)BB * KLEN * HD];   // used as bf16
static __device__ float g_r  [(size_t)KLEN * HD];        // used as bf16
static __device__ float g_att[(size_t)BB * QLEN * HD];
static __device__ float g_o  [(size_t)BB * QLEN * EE];
static __device__ float g_x  [(size_t)BB * QLEN * EE];
static __device__ float g_ffn[(size_t)BB * QLEN * FF];
static __device__ float g_y  [(size_t)BB * QLEN * EE];

// ---------------- helpers ----------------
__device__ __forceinline__ unsigned f2t(float x) {
    unsigned u; asm("cvt.rna.tf32.f32 %0, %1;" : "=r"(u) : "f"(x)); return u;
}
__device__ __forceinline__ unsigned pack_bf2(float lo, float hi) {
    unsigned u; asm("cvt.rn.bf16x2.f32 %0, %1, %2;" : "=r"(u) : "f"(hi), "f"(lo)); return u;
}
__device__ __forceinline__ void mma8(float* c, const unsigned* a, const unsigned* b) {
    asm volatile("mma.sync.aligned.m16n8k8.row.col.f32.tf32.tf32.f32 "
        "{%0,%1,%2,%3}, {%4,%5,%6,%7}, {%8,%9}, {%0,%1,%2,%3};\n"
        : "+f"(c[0]), "+f"(c[1]), "+f"(c[2]), "+f"(c[3])
        : "r"(a[0]), "r"(a[1]), "r"(a[2]), "r"(a[3]), "r"(b[0]), "r"(b[1]));
}
__device__ __forceinline__ void mma16(float* c, const unsigned* a, const unsigned* b) {
    asm volatile("mma.sync.aligned.m16n8k16.row.col.f32.bf16.bf16.f32 "
        "{%0,%1,%2,%3}, {%4,%5,%6,%7}, {%8,%9}, {%0,%1,%2,%3};\n"
        : "+f"(c[0]), "+f"(c[1]), "+f"(c[2]), "+f"(c[3])
        : "r"(a[0]), "r"(a[1]), "r"(a[2]), "r"(a[3]), "r"(b[0]), "r"(b[1]));
}
__device__ __forceinline__ void cpa16(unsigned saddr, const void* g) {
    asm volatile("cp.async.cg.shared.global [%0], [%1], 16;" :: "r"(saddr), "l"(g));
}
__device__ __forceinline__ void cpa_commit() { asm volatile("cp.async.commit_group;"); }
__device__ __forceinline__ void cpa_waitall() { asm volatile("cp.async.wait_group 0;"); }

// ---------------- cat = concat(member, w) ----------------
__global__ __launch_bounds__(256) void copy_cat_kernel(
    const float4* __restrict__ w, const float4* __restrict__ member, float4* __restrict__ cat)
{
    size_t i = (size_t)blockIdx.x * 256 + threadIdx.x;
    int e4 = (int)(i % (EE / 4));
    size_t t2 = i / (EE / 4);
    int kl = (int)(t2 % KLEN);
    int b  = (int)(t2 / KLEN);
    float4 v;
    if (kl < MLEN) v = member[((size_t)b * MLEN + kl) * (EE / 4) + e4];
    else           v = w[((size_t)b * QLEN + (kl - MLEN)) * (EE / 4) + e4];
    cat[i] = v;
}

// ================= tf32 MMA GEMM, NN (R5, proven); obf=1 writes bf16 =================
__global__ __launch_bounds__(256, 2) void gemm_nn_tf32(
    const float* __restrict__ A, int lda, const float* __restrict__ B, int ldb,
    float* __restrict__ C, int ldc, int N, int K, int relu, int obf)
{
    __shared__ __align__(16) unsigned As[2][128][20];
    __shared__ __align__(16) unsigned Bs[2][16][136];

    const int t = threadIdx.x;
    const int lane = t & 31, warp = t >> 5;
    const int g = lane >> 2, tig = lane & 3;
    const int wm0 = (warp >> 2) * 64, wn0 = (warp & 3) * 32;
    const int m0 = blockIdx.y * 128, n0 = blockIdx.x * 128;

    const int arow = t >> 2,  akc = (t & 3) * 4;
    const int brow = t >> 5,  bnc = (t & 31) * 4;

    float c[4][4][4] = {};

    {
        #pragma unroll
        for (int j = 0; j < 2; j++) {
            int row = arow + 64 * j;
            float4 f = *(const float4*)&A[(size_t)(m0 + row) * lda + akc];
            As[0][row][akc + 0] = f2t(f.x); As[0][row][akc + 1] = f2t(f.y);
            As[0][row][akc + 2] = f2t(f.z); As[0][row][akc + 3] = f2t(f.w);
        }
        #pragma unroll
        for (int j = 0; j < 2; j++) {
            int row = brow + 8 * j;
            int n = n0 + bnc;
            float4 f = make_float4(0.f, 0.f, 0.f, 0.f);
            if (n < N) f = *(const float4*)&B[(size_t)row * ldb + n];
            Bs[0][row][bnc + 0] = f2t(f.x); Bs[0][row][bnc + 1] = f2t(f.y);
            Bs[0][row][bnc + 2] = f2t(f.z); Bs[0][row][bnc + 3] = f2t(f.w);
        }
    }
    __syncthreads();

    const int nk = K / 16;
    int buf = 0;
    for (int kt = 0; kt < nk; kt++) {
        float4 ra[2], rb[2];
        if (kt + 1 < nk) {
            int k0 = (kt + 1) * 16;
            #pragma unroll
            for (int j = 0; j < 2; j++)
                ra[j] = *(const float4*)&A[(size_t)(m0 + arow + 64 * j) * lda + k0 + akc];
            #pragma unroll
            for (int j = 0; j < 2; j++) {
                int n = n0 + bnc;
                rb[j] = make_float4(0.f, 0.f, 0.f, 0.f);
                if (n < N) rb[j] = *(const float4*)&B[(size_t)(k0 + brow + 8 * j) * ldb + n];
            }
        }
        #pragma unroll
        for (int ks = 0; ks < 16; ks += 8) {
            unsigned af[4][4], bf[4][2];
            #pragma unroll
            for (int mi = 0; mi < 4; mi++) {
                int m = wm0 + mi * 16 + g;
                af[mi][0] = As[buf][m][ks + tig];
                af[mi][1] = As[buf][m + 8][ks + tig];
                af[mi][2] = As[buf][m][ks + tig + 4];
                af[mi][3] = As[buf][m + 8][ks + tig + 4];
            }
            #pragma unroll
            for (int ni = 0; ni < 4; ni++) {
                int n = wn0 + ni * 8 + g;
                bf[ni][0] = Bs[buf][ks + tig][n];
                bf[ni][1] = Bs[buf][ks + tig + 4][n];
            }
            #pragma unroll
            for (int mi = 0; mi < 4; mi++)
                #pragma unroll
                for (int ni = 0; ni < 4; ni++)
                    mma8(c[mi][ni], af[mi], bf[ni]);
        }
        if (kt + 1 < nk) {
            int nb = buf ^ 1;
            #pragma unroll
            for (int j = 0; j < 2; j++) {
                int row = arow + 64 * j;
                As[nb][row][akc + 0] = f2t(ra[j].x); As[nb][row][akc + 1] = f2t(ra[j].y);
                As[nb][row][akc + 2] = f2t(ra[j].z); As[nb][row][akc + 3] = f2t(ra[j].w);
            }
            #pragma unroll
            for (int j = 0; j < 2; j++) {
                int row = brow + 8 * j;
                Bs[nb][row][bnc + 0] = f2t(rb[j].x); Bs[nb][row][bnc + 1] = f2t(rb[j].y);
                Bs[nb][row][bnc + 2] = f2t(rb[j].z); Bs[nb][row][bnc + 3] = f2t(rb[j].w);
            }
            __syncthreads();
        }
        buf ^= 1;
    }

    #pragma unroll
    for (int mi = 0; mi < 4; mi++) {
        int row = m0 + wm0 + mi * 16 + g;
        #pragma unroll
        for (int ni = 0; ni < 4; ni++) {
            int col = n0 + wn0 + ni * 8 + 2 * tig;
            if (col < N) {
                float2 v0 = make_float2(c[mi][ni][0], c[mi][ni][1]);
                float2 v1 = make_float2(c[mi][ni][2], c[mi][ni][3]);
                if (relu) {
                    v0.x = fmaxf(v0.x, 0.f); v0.y = fmaxf(v0.y, 0.f);
                    v1.x = fmaxf(v1.x, 0.f); v1.y = fmaxf(v1.y, 0.f);
                }
                if (obf) {
                    unsigned* Cu = (unsigned*)C;
                    Cu[((size_t)row * ldc + col) / 2]       = pack_bf2(v0.x, v0.y);
                    Cu[((size_t)(row + 8) * ldc + col) / 2] = pack_bf2(v1.x, v1.y);
                } else {
                    *(float2*)&C[(size_t)row * ldc + col] = v0;
                    *(float2*)&C[(size_t)(row + 8) * ldc + col] = v1;
                }
            }
        }
    }
}

// ================= bf16 MMA GEMM, NN — projections only (M,N,K mult of 128/16) =================
// A packed bf16x2 along k: As[m][kp], stride 12 words; B transposed-packed: Bs[n][kp], stride 12.
#define PBS 12
__global__ __launch_bounds__(256, 2) void gemm_nn_bf16(
    const float* __restrict__ A, int lda, const float* __restrict__ B, int ldb,
    float* __restrict__ C, int ldc, int K)
{
    __shared__ __align__(16) unsigned As[2][128 * PBS];
    __shared__ __align__(16) unsigned Bs[2][128 * PBS];

    const int t = threadIdx.x;
    const int lane = t & 31, warp = t >> 5;
    const int g = lane >> 2, tig = lane & 3;
    const int wm0 = (warp >> 2) * 64, wn0 = (warp & 3) * 32;
    const int m0 = blockIdx.y * 128, n0 = blockIdx.x * 128;

    const int arow = t >> 1, akc = (t & 1) * 8;   // A: row, 8 k-values (2 float4)
    const int bkp = t & 7,  bn4 = (t >> 3) * 4;   // B: k-pair 2bkp/2bkp+1, 4 n-values

    float c[4][4][4] = {};

    // preload tile 0
    {
        float4 fa0 = *(const float4*)&A[(size_t)(m0 + arow) * lda + akc];
        float4 fa1 = *(const float4*)&A[(size_t)(m0 + arow) * lda + akc + 4];
        unsigned* ap = &As[0][arow * PBS + akc / 2];
        ap[0] = pack_bf2(fa0.x, fa0.y); ap[1] = pack_bf2(fa0.z, fa0.w);
        ap[2] = pack_bf2(fa1.x, fa1.y); ap[3] = pack_bf2(fa1.z, fa1.w);
        float4 fb0 = *(const float4*)&B[(size_t)(2 * bkp)     * ldb + n0 + bn4];
        float4 fb1 = *(const float4*)&B[(size_t)(2 * bkp + 1) * ldb + n0 + bn4];
        Bs[0][(bn4 + 0) * PBS + bkp] = pack_bf2(fb0.x, fb1.x);
        Bs[0][(bn4 + 1) * PBS + bkp] = pack_bf2(fb0.y, fb1.y);
        Bs[0][(bn4 + 2) * PBS + bkp] = pack_bf2(fb0.z, fb1.z);
        Bs[0][(bn4 + 3) * PBS + bkp] = pack_bf2(fb0.w, fb1.w);
    }
    __syncthreads();

    const int nk = K / 16;
    int buf = 0;
    for (int kt = 0; kt < nk; kt++) {
        float4 ra0, ra1, rb0, rb1;
        if (kt + 1 < nk) {
            int k0 = (kt + 1) * 16;
            ra0 = *(const float4*)&A[(size_t)(m0 + arow) * lda + k0 + akc];
            ra1 = *(const float4*)&A[(size_t)(m0 + arow) * lda + k0 + akc + 4];
            rb0 = *(const float4*)&B[(size_t)(k0 + 2 * bkp)     * ldb + n0 + bn4];
            rb1 = *(const float4*)&B[(size_t)(k0 + 2 * bkp + 1) * ldb + n0 + bn4];
        }
        const unsigned* Ab = As[buf];
        const unsigned* Bb = Bs[buf];
        unsigned af[4][4], bf[4][2];
        #pragma unroll
        for (int mi = 0; mi < 4; mi++) {
            int m = wm0 + mi * 16 + g;
            af[mi][0] = Ab[m * PBS + tig];
            af[mi][1] = Ab[(m + 8) * PBS + tig];
            af[mi][2] = Ab[m * PBS + tig + 4];
            af[mi][3] = Ab[(m + 8) * PBS + tig + 4];
        }
        #pragma unroll
        for (int ni = 0; ni < 4; ni++) {
            int n = wn0 + ni * 8 + g;
            bf[ni][0] = Bb[n * PBS + tig];
            bf[ni][1] = Bb[n * PBS + tig + 4];
        }
        #pragma unroll
        for (int mi = 0; mi < 4; mi++)
            #pragma unroll
            for (int ni = 0; ni < 4; ni++)
                mma16(c[mi][ni], af[mi], bf[ni]);
        if (kt + 1 < nk) {
            int nb = buf ^ 1;
            unsigned* ap = &As[nb][arow * PBS + akc / 2];
            ap[0] = pack_bf2(ra0.x, ra0.y); ap[1] = pack_bf2(ra0.z, ra0.w);
            ap[2] = pack_bf2(ra1.x, ra1.y); ap[3] = pack_bf2(ra1.z, ra1.w);
            Bs[nb][(bn4 + 0) * PBS + bkp] = pack_bf2(rb0.x, rb1.x);
            Bs[nb][(bn4 + 1) * PBS + bkp] = pack_bf2(rb0.y, rb1.y);
            Bs[nb][(bn4 + 2) * PBS + bkp] = pack_bf2(rb0.z, rb1.z);
            Bs[nb][(bn4 + 3) * PBS + bkp] = pack_bf2(rb0.w, rb1.w);
            __syncthreads();
        }
        buf ^= 1;
    }

    // epilogue: bf16 output
    #pragma unroll
    for (int mi = 0; mi < 4; mi++) {
        int row = m0 + wm0 + mi * 16 + g;
        #pragma unroll
        for (int ni = 0; ni < 4; ni++) {
            int col = n0 + wn0 + ni * 8 + 2 * tig;
            unsigned* Cu = (unsigned*)C;
            Cu[((size_t)row * ldc + col) / 2]       = pack_bf2(c[mi][ni][0], c[mi][ni][1]);
            Cu[((size_t)(row + 8) * ldc + col) / 2] = pack_bf2(c[mi][ni][2], c[mi][ni][3]);
        }
    }
}

// ================= bf16 pipelined flash attention with rel-shift (R5, proven) =================
#define QS 36        // word stride (72 bf16)
#define GS 264       // sG stride, bf16
#define PS 68        // P word stride (136 bf16)
#define OFF_QW 0
#define OFF_QR 18432
#define OFF_K  36864
#define OFF_V  73728
#define OFF_R  110592
#define OFF_G  147456
#define OFF_RED 215040
#define FA_SMEM 219136

__global__ __launch_bounds__(256, 1) void flash_attn(
    const __nv_bfloat16* __restrict__ Qb, const __nv_bfloat16* __restrict__ Kb,
    const __nv_bfloat16* __restrict__ Vb, const __nv_bfloat16* __restrict__ Rb,
    const float* __restrict__ rwb, const float* __restrict__ rrb,
    float* __restrict__ Om)
{
    extern __shared__ __align__(16) char smem[];
    unsigned*  uQw = (unsigned*)(smem + OFF_QW);
    unsigned*  uQr = (unsigned*)(smem + OFF_QR);
    unsigned*  uG  = (unsigned*)(smem + OFF_G);
    __nv_bfloat16* hG = (__nv_bfloat16*)(smem + OFF_G);
    float* redM = (float*)(smem + OFF_RED);
    float* redS = redM + 512;
    const unsigned sb = (unsigned)__cvta_generic_to_shared(smem);

    const int t = threadIdx.x;
    const int lane = t & 31, warp = t >> 5;
    const int g = lane >> 2, tig = lane & 3;
    const int wm0 = (warp >> 2) * 64;
    const int wn  = warp & 3;
    const int wn0 = wn * 32;
    const int wn0p = wn * 16;

    const int bh = blockIdx.z, b = bh >> 4, h = bh & 15;
    const int q0 = (gridDim.y - 1 - blockIdx.y) * 128;
    const int ntiles = q0 / 128 + 9;

    const __nv_bfloat16* gK = Kb + ((size_t)b * KLEN) * HD + h * DH;
    const __nv_bfloat16* gV = Vb + ((size_t)b * KLEN) * HD + h * DH;
    const __nv_bfloat16* gR = Rb + h * DH;

    {
        #pragma unroll
        for (int i = 0; i < 4; i++) {
            int id = t + 256 * i, row = id >> 3, ch = id & 7;
            cpa16(sb + OFF_K + row * 144 + ch * 16, gK + (size_t)row * HD + ch * 8);
            cpa16(sb + OFF_V + row * 144 + ch * 16, gV + (size_t)row * HD + ch * 8);
        }
        cpa_commit();
        int j0 = 0 - q0 + (QLEN - 128);
        #pragma unroll
        for (int i = 0; i < 8; i++) {
            int id = t + 256 * i, row = id >> 3, ch = id & 7;
            int j = j0 + row; if (j > KLEN - 1) j = KLEN - 1;
            cpa16(sb + OFF_R + row * 144 + ch * 16, gR + (size_t)j * HD + ch * 8);
        }
        cpa_commit();
    }

    {
        const __nv_bfloat16* qsrc = Qb + ((size_t)b * QLEN + q0) * HD + h * DH;
        int lr = t >> 1, lc0 = (t & 1) * 32;
        #pragma unroll
        for (int i = 0; i < 8; i++) {
            int c = lc0 + i * 4;
            uint2 u = *(const uint2*)&qsrc[(size_t)lr * HD + c];
            __nv_bfloat162 q01 = *(__nv_bfloat162*)&u.x;
            __nv_bfloat162 q23 = *(__nv_bfloat162*)&u.y;
            float4 bw = *(const float4*)&rwb[h * DH + c];
            float4 br = *(const float4*)&rrb[h * DH + c];
            float f0 = __bfloat162float(q01.x), f1 = __bfloat162float(q01.y);
            float f2 = __bfloat162float(q23.x), f3 = __bfloat162float(q23.y);
            uQw[lr * QS + c / 2]     = pack_bf2(f0 + bw.x, f1 + bw.y);
            uQw[lr * QS + c / 2 + 1] = pack_bf2(f2 + bw.z, f3 + bw.w);
            uQr[lr * QS + c / 2]     = pack_bf2(f0 + br.x, f1 + br.y);
            uQr[lr * QS + c / 2 + 1] = pack_bf2(f2 + br.z, f3 + br.w);
        }
    }

    float o[4][2][4] = {};
    float mrun[4][2], lrun[4][2];
    #pragma unroll
    for (int mi = 0; mi < 4; mi++)
        #pragma unroll
        for (int hh = 0; hh < 2; hh++) { mrun[mi][hh] = -INFINITY; lrun[mi][hh] = 0.f; }

    int buf = 0;
    for (int kt = 0; kt < ntiles; kt++) {
        const int k0 = kt * 128;
        cpa_waitall();
        __syncthreads();

        if (kt + 1 < ntiles) {
            const __nv_bfloat16* nK = gK + (size_t)(k0 + 128) * HD;
            const __nv_bfloat16* nV = gV + (size_t)(k0 + 128) * HD;
            unsigned kb = OFF_K + (buf ^ 1) * 18432, vb2 = OFF_V + (buf ^ 1) * 18432;
            #pragma unroll
            for (int i = 0; i < 4; i++) {
                int id = t + 256 * i, row = id >> 3, ch = id & 7;
                cpa16(sb + kb + row * 144 + ch * 16, nK + (size_t)row * HD + ch * 8);
                cpa16(sb + vb2 + row * 144 + ch * 16, nV + (size_t)row * HD + ch * 8);
            }
            cpa_commit();
        }

        float acc[4][4][4] = {};
        {
            const unsigned* uK = (const unsigned*)(smem + OFF_K + buf * 18432);
            #pragma unroll
            for (int ks = 0; ks < 4; ks++) {
                unsigned af[4][4], bf[4][2];
                #pragma unroll
                for (int mi = 0; mi < 4; mi++) {
                    int m = wm0 + mi * 16 + g;
                    af[mi][0] = uQw[m * QS + ks * 8 + tig];
                    af[mi][1] = uQw[(m + 8) * QS + ks * 8 + tig];
                    af[mi][2] = uQw[m * QS + ks * 8 + tig + 4];
                    af[mi][3] = uQw[(m + 8) * QS + ks * 8 + tig + 4];
                }
                #pragma unroll
                for (int ni = 0; ni < 4; ni++) {
                    int n = wn0 + ni * 8 + g;
                    bf[ni][0] = uK[n * QS + ks * 8 + tig];
                    bf[ni][1] = uK[n * QS + ks * 8 + tig + 4];
                }
                #pragma unroll
                for (int mi = 0; mi < 4; mi++)
                    #pragma unroll
                    for (int ni = 0; ni < 4; ni++)
                        mma16(acc[mi][ni], af[mi], bf[ni]);
            }
        }

        {
            const unsigned* uR = (const unsigned*)(smem + OFF_R);
            #pragma unroll
            for (int h2 = 0; h2 < 2; h2++) {
                float ga[4][4][4] = {};
                #pragma unroll
                for (int ks = 0; ks < 4; ks++) {
                    unsigned af[4][4], bf[4][2];
                    #pragma unroll
                    for (int mi = 0; mi < 4; mi++) {
                        int m = wm0 + mi * 16 + g;
                        af[mi][0] = uQr[m * QS + ks * 8 + tig];
                        af[mi][1] = uQr[(m + 8) * QS + ks * 8 + tig];
                        af[mi][2] = uQr[m * QS + ks * 8 + tig + 4];
                        af[mi][3] = uQr[(m + 8) * QS + ks * 8 + tig + 4];
                    }
                    #pragma unroll
                    for (int ni = 0; ni < 4; ni++) {
                        int n = h2 * 128 + wn0 + ni * 8 + g;
                        bf[ni][0] = uR[n * QS + ks * 8 + tig];
                        bf[ni][1] = uR[n * QS + ks * 8 + tig + 4];
                    }
                    #pragma unroll
                    for (int mi = 0; mi < 4; mi++)
                        #pragma unroll
                        for (int ni = 0; ni < 4; ni++)
                            mma16(ga[mi][ni], af[mi], bf[ni]);
                }
                #pragma unroll
                for (int mi = 0; mi < 4; mi++)
                    #pragma unroll
                    for (int ni = 0; ni < 4; ni++)
                        #pragma unroll
                        for (int hh = 0; hh < 2; hh++) {
                            int r = wm0 + mi * 16 + g + 8 * hh;
                            int col = h2 * 128 + wn0 + ni * 8 + 2 * tig;
                            uG[(r * GS + col) / 2] = pack_bf2(ga[mi][ni][2 * hh], ga[mi][ni][2 * hh + 1]);
                        }
            }
        }
        __syncthreads();

        if (kt + 1 < ntiles) {
            int j0n = (k0 + 128) - q0 + (QLEN - 128);
            #pragma unroll
            for (int i = 0; i < 8; i++) {
                int id = t + 256 * i, row = id >> 3, ch = id & 7;
                int j = j0n + row; if (j > KLEN - 1) j = KLEN - 1;
                cpa16(sb + OFF_R + row * 144 + ch * 16, gR + (size_t)j * HD + ch * 8);
            }
            cpa_commit();
        }

        #pragma unroll
        for (int mi = 0; mi < 4; mi++)
            #pragma unroll
            for (int ni = 0; ni < 4; ni++)
                #pragma unroll
                for (int hh = 0; hh < 2; hh++)
                    #pragma unroll
                    for (int e = 0; e < 2; e++) {
                        int r = wm0 + mi * 16 + g + 8 * hh;
                        int col = wn0 + ni * 8 + 2 * tig + e;
                        float s = acc[mi][ni][2 * hh + e]
                                + __bfloat162float(hG[r * GS + (col - r + 127)]);
                        acc[mi][ni][2 * hh + e] =
                            ((k0 + col) <= (q0 + r) + MLEN) ? s * 0.03125f : -1e30f;
                    }

        float mw[4][2];
        #pragma unroll
        for (int mi = 0; mi < 4; mi++)
            #pragma unroll
            for (int hh = 0; hh < 2; hh++) {
                float m8 = -INFINITY;
                #pragma unroll
                for (int ni = 0; ni < 4; ni++) {
                    m8 = fmaxf(m8, fmaxf(acc[mi][ni][2 * hh], acc[mi][ni][2 * hh + 1]));
                }
                m8 = fmaxf(m8, __shfl_xor_sync(0xffffffffu, m8, 1));
                m8 = fmaxf(m8, __shfl_xor_sync(0xffffffffu, m8, 2));
                mw[mi][hh] = m8;
                float sw = 0.f;
                #pragma unroll
                for (int ni = 0; ni < 4; ni++)
                    #pragma unroll
                    for (int e = 0; e < 2; e++) {
                        float p = __expf(acc[mi][ni][2 * hh + e] - m8);
                        acc[mi][ni][2 * hh + e] = p;
                        sw += p;
                    }
                sw += __shfl_xor_sync(0xffffffffu, sw, 1);
                sw += __shfl_xor_sync(0xffffffffu, sw, 2);
                if (tig == 0) {
                    int r = wm0 + mi * 16 + g + 8 * hh;
                    redM[wn * 128 + r] = m8;
                    redS[wn * 128 + r] = sw;
                }
            }
        __syncthreads();

        float fsc[4][2];
        #pragma unroll
        for (int mi = 0; mi < 4; mi++)
            #pragma unroll
            for (int hh = 0; hh < 2; hh++) {
                int r = wm0 + mi * 16 + g + 8 * hh;
                float m0v = redM[r], m1v = redM[128 + r], m2v = redM[256 + r], m3v = redM[384 + r];
                float mnew = fmaxf(mrun[mi][hh],
                              fmaxf(fmaxf(m0v, m1v), fmaxf(m2v, m3v)));
                float ladd = redS[r] * __expf(m0v - mnew) + redS[128 + r] * __expf(m1v - mnew)
                           + redS[256 + r] * __expf(m2v - mnew) + redS[384 + r] * __expf(m3v - mnew);
                float alpha = __expf(mrun[mi][hh] - mnew);
                lrun[mi][hh] = lrun[mi][hh] * alpha + ladd;
                mrun[mi][hh] = mnew;
                fsc[mi][hh] = __expf(mw[mi][hh] - mnew);
                #pragma unroll
                for (int ni2 = 0; ni2 < 2; ni2++) {
                    o[mi][ni2][2 * hh]     *= alpha;
                    o[mi][ni2][2 * hh + 1] *= alpha;
                }
            }
        #pragma unroll
        for (int mi = 0; mi < 4; mi++)
            #pragma unroll
            for (int ni = 0; ni < 4; ni++)
                #pragma unroll
                for (int hh = 0; hh < 2; hh++) {
                    int r = wm0 + mi * 16 + g + 8 * hh;
                    int col = wn0 + ni * 8 + 2 * tig;
                    uG[r * PS + col / 2] = pack_bf2(
                        acc[mi][ni][2 * hh] * fsc[mi][hh],
                        acc[mi][ni][2 * hh + 1] * fsc[mi][hh]);
                }
        __syncthreads();

        {
            const unsigned short* hV = (const unsigned short*)(smem + OFF_V + buf * 18432);
            #pragma unroll
            for (int ks = 0; ks < 8; ks++) {
                unsigned af[4][4], bf[2][2];
                #pragma unroll
                for (int mi = 0; mi < 4; mi++) {
                    int m = wm0 + mi * 16 + g;
                    af[mi][0] = uG[m * PS + ks * 8 + tig];
                    af[mi][1] = uG[(m + 8) * PS + ks * 8 + tig];
                    af[mi][2] = uG[m * PS + ks * 8 + tig + 4];
                    af[mi][3] = uG[(m + 8) * PS + ks * 8 + tig + 4];
                }
                #pragma unroll
                for (int ni2 = 0; ni2 < 2; ni2++) {
                    int n = wn0p + ni2 * 8 + g;
                    unsigned lo0 = hV[(ks * 16 + 2 * tig) * 72 + n];
                    unsigned hi0 = hV[(ks * 16 + 2 * tig + 1) * 72 + n];
                    unsigned lo1 = hV[(ks * 16 + 2 * tig + 8) * 72 + n];
                    unsigned hi1 = hV[(ks * 16 + 2 * tig + 9) * 72 + n];
                    bf[ni2][0] = lo0 | (hi0 << 16);
                    bf[ni2][1] = lo1 | (hi1 << 16);
                }
                #pragma unroll
                for (int mi = 0; mi < 4; mi++)
                    #pragma unroll
                    for (int ni2 = 0; ni2 < 2; ni2++)
                        mma16(o[mi][ni2], af[mi], bf[ni2]);
            }
        }
        buf ^= 1;
    }

    #pragma unroll
    for (int mi = 0; mi < 4; mi++)
        #pragma unroll
        for (int ni2 = 0; ni2 < 2; ni2++)
            #pragma unroll
            for (int hh = 0; hh < 2; hh++) {
                int r = wm0 + mi * 16 + g + 8 * hh;
                int d = wn0p + ni2 * 8 + 2 * tig;
                float inv = 1.0f / lrun[mi][hh];
                *(float2*)&Om[((size_t)b * QLEN + q0 + r) * HD + h * DH + d] =
                    make_float2(o[mi][ni2][2 * hh] * inv, o[mi][ni2][2 * hh + 1] * inv);
            }
}

// ---------------- out = LayerNorm(a + b), rows of EE ----------------
__global__ __launch_bounds__(256) void add_ln_kernel(
    const float* __restrict__ A, const float* __restrict__ Bv,
    const float* __restrict__ gamma, const float* __restrict__ beta,
    float* __restrict__ out)
{
    __shared__ float red[256];
    const size_t row = blockIdx.x;
    const int t = threadIdx.x;
    float4 va = ((const float4*)(A + row * EE))[t];
    float4 vb = ((const float4*)(Bv + row * EE))[t];
    float4 v = make_float4(va.x + vb.x, va.y + vb.y, va.z + vb.z, va.w + vb.w);

    red[t] = v.x + v.y + v.z + v.w; __syncthreads();
    for (int s = 128; s > 0; s >>= 1) { if (t < s) red[t] += red[t + s]; __syncthreads(); }
    const float mean = red[0] * (1.0f / EE); __syncthreads();

    float dx = v.x - mean, dy = v.y - mean, dz = v.z - mean, dw = v.w - mean;
    red[t] = dx * dx + dy * dy + dz * dz + dw * dw; __syncthreads();
    for (int s = 128; s > 0; s >>= 1) { if (t < s) red[t] += red[t + s]; __syncthreads(); }
    const float inv = rsqrtf(red[0] * (1.0f / EE) + 1e-3f);

    float4 gm = ((const float4*)gamma)[t];
    float4 bt = ((const float4*)beta)[t];
    float4 o;
    o.x = dx * inv * gm.x + bt.x; o.y = dy * inv * gm.y + bt.y;
    o.z = dz * inv * gm.z + bt.z; o.w = dw * inv * gm.w + bt.w;
    ((float4*)(out + row * EE))[t] = o;
}

// ---------------- launch ----------------
extern "C" void kernel_launch(void* const* d_in, const int* in_sizes, int n_in,
                              void* d_out, int out_size)
{
    const float* w      = (const float*)d_in[0];
    const float* r      = (const float*)d_in[1];
    const float* member = (const float*)d_in[2];
    const float* Wq  = (const float*)d_in[4];
    const float* Wk  = (const float*)d_in[5];
    const float* Wv  = (const float*)d_in[6];
    const float* Wr  = (const float*)d_in[7];
    const float* Wo  = (const float*)d_in[8];
    const float* rwb = (const float*)d_in[9];
    const float* rrb = (const float*)d_in[10];
    const float* ln1g = (const float*)d_in[11];
    const float* ln1b = (const float*)d_in[12];
    const float* W1  = (const float*)d_in[13];
    const float* W2  = (const float*)d_in[14];
    const float* ln2g = (const float*)d_in[15];
    const float* ln2b = (const float*)d_in[16];
    float* out = (float*)d_out;

    static float *p_cat = nullptr, *p_q, *p_k, *p_v, *p_r,
                 *p_att, *p_o, *p_x, *p_ffn, *p_y;
    if (!p_cat) {
        cudaGetSymbolAddress((void**)&p_cat, g_cat);
        cudaGetSymbolAddress((void**)&p_q,   g_q);
        cudaGetSymbolAddress((void**)&p_k,   g_k);
        cudaGetSymbolAddress((void**)&p_v,   g_v);
        cudaGetSymbolAddress((void**)&p_r,   g_r);
        cudaGetSymbolAddress((void**)&p_att, g_att);
        cudaGetSymbolAddress((void**)&p_o,   g_o);
        cudaGetSymbolAddress((void**)&p_x,   g_x);
        cudaGetSymbolAddress((void**)&p_ffn, g_ffn);
        cudaGetSymbolAddress((void**)&p_y,   g_y);
        cudaFuncSetAttribute(flash_attn, cudaFuncAttributeMaxDynamicSharedMemorySize, FA_SMEM);
    }

    // 1. cat
    copy_cat_kernel<<<(BB * KLEN * EE / 4) / 256, 256>>>(
        (const float4*)w, (const float4*)member, (float4*)p_cat);

    // 2. projections (bf16 MMA, bf16 output)
    gemm_nn_bf16<<<dim3(HD / 128, (BB * QLEN) / 128), 256>>>(w,     EE, Wq, HD, p_q, HD, EE);
    gemm_nn_bf16<<<dim3(HD / 128, (BB * KLEN) / 128), 256>>>(p_cat, EE, Wk, HD, p_k, HD, EE);
    gemm_nn_bf16<<<dim3(HD / 128, (BB * KLEN) / 128), 256>>>(p_cat, EE, Wv, HD, p_v, HD, EE);
    gemm_nn_bf16<<<dim3(HD / 128, KLEN / 128),        256>>>(r,     EE, Wr, HD, p_r, HD, EE);

    // 3. fused attention
    flash_attn<<<dim3(1, QLEN / 128, BB * HH), 256, FA_SMEM>>>(
        (const __nv_bfloat16*)p_q, (const __nv_bfloat16*)p_k,
        (const __nv_bfloat16*)p_v, (const __nv_bfloat16*)p_r,
        rwb, rrb, p_att);

    // 4. output projection + LN1 (tf32)
    gemm_nn_tf32<<<dim3(EE / 128, (BB * QLEN) / 128), 256>>>(p_att, HD, Wo, EE, p_o, EE, EE, HD, 0, 0);
    add_ln_kernel<<<BB * QLEN, 256>>>(w, p_o, ln1g, ln1b, p_x);

    // 5. FFN + LN2 -> out (tf32)
    gemm_nn_tf32<<<dim3(FF / 128, (BB * QLEN) / 128), 256>>>(p_x,   EE, W1, FF, p_ffn, FF, FF, EE, 1, 0);
    gemm_nn_tf32<<<dim3(EE / 128, (BB * QLEN) / 128), 256>>>(p_ffn, FF, W2, EE, p_y,   EE, EE, FF, 0, 0);
    add_ln_kernel<<<BB * QLEN, 256>>>(p_y, p_x, ln2g, ln2b, out);
}

// round 9
// speedup vs baseline: 1.2525x; 1.0026x over previous
#include <cuda_runtime.h>
#include <cuda_bf16.h>
#include <math.h>

#define BB 2
#define QLEN 1024
#define MLEN 1024
#define KLEN 2048
#define EE 1024
#define HH 16
#define DH 64
#define HD 1024   // HH*DH
#define FF 4096

// ---------------- scratch ----------------
static __device__ float g_cat[(size_t)BB * KLEN * EE];
static __device__ float g_q  [(size_t)BB * QLEN * HD];   // used as bf16
static __device__ float g_k  [(size_t)BB * KLEN * HD];   // used as bf16
static __device__ float g_v  [(size_t)BB * KLEN * HD];   // used as bf16
static __device__ float g_r  [(size_t)KLEN * HD];        // used as bf16
static __device__ float g_att[(size_t)BB * QLEN * HD];
static __device__ float g_o  [(size_t)BB * QLEN * EE];
static __device__ float g_x  [(size_t)BB * QLEN * EE];
static __device__ float g_ffn[(size_t)BB * QLEN * FF];
static __device__ float g_y  [(size_t)BB * QLEN * EE];

// ---------------- helpers ----------------
__device__ __forceinline__ unsigned f2t(float x) {
    unsigned u; asm("cvt.rna.tf32.f32 %0, %1;" : "=r"(u) : "f"(x)); return u;
}
__device__ __forceinline__ unsigned pack_bf2(float lo, float hi) {
    unsigned u; asm("cvt.rn.bf16x2.f32 %0, %1, %2;" : "=r"(u) : "f"(hi), "f"(lo)); return u;
}
__device__ __forceinline__ void mma8(float* c, const unsigned* a, const unsigned* b) {
    asm volatile("mma.sync.aligned.m16n8k8.row.col.f32.tf32.tf32.f32 "
        "{%0,%1,%2,%3}, {%4,%5,%6,%7}, {%8,%9}, {%0,%1,%2,%3};\n"
        : "+f"(c[0]), "+f"(c[1]), "+f"(c[2]), "+f"(c[3])
        : "r"(a[0]), "r"(a[1]), "r"(a[2]), "r"(a[3]), "r"(b[0]), "r"(b[1]));
}
__device__ __forceinline__ void mma16(float* c, const unsigned* a, const unsigned* b) {
    asm volatile("mma.sync.aligned.m16n8k16.row.col.f32.bf16.bf16.f32 "
        "{%0,%1,%2,%3}, {%4,%5,%6,%7}, {%8,%9}, {%0,%1,%2,%3};\n"
        : "+f"(c[0]), "+f"(c[1]), "+f"(c[2]), "+f"(c[3])
        : "r"(a[0]), "r"(a[1]), "r"(a[2]), "r"(a[3]), "r"(b[0]), "r"(b[1]));
}
__device__ __forceinline__ void cpa16(unsigned saddr, const void* g) {
    asm volatile("cp.async.cg.shared.global [%0], [%1], 16;" :: "r"(saddr), "l"(g));
}
__device__ __forceinline__ void cpa_commit() { asm volatile("cp.async.commit_group;"); }
__device__ __forceinline__ void cpa_waitall() { asm volatile("cp.async.wait_group 0;"); }

// ---------------- cat = concat(member, w) ----------------
__global__ __launch_bounds__(256) void copy_cat_kernel(
    const float4* __restrict__ w, const float4* __restrict__ member, float4* __restrict__ cat)
{
    size_t i = (size_t)blockIdx.x * 256 + threadIdx.x;
    int e4 = (int)(i % (EE / 4));
    size_t t2 = i / (EE / 4);
    int kl = (int)(t2 % KLEN);
    int b  = (int)(t2 / KLEN);
    float4 v;
    if (kl < MLEN) v = member[((size_t)b * MLEN + kl) * (EE / 4) + e4];
    else           v = w[((size_t)b * QLEN + (kl - MLEN)) * (EE / 4) + e4];
    cat[i] = v;
}

// ================= tf32 MMA GEMM, NN (R5, proven); obf=1 writes bf16 =================
__global__ __launch_bounds__(256, 2) void gemm_nn_tf32(
    const float* __restrict__ A, int lda, const float* __restrict__ B, int ldb,
    float* __restrict__ C, int ldc, int N, int K, int relu, int obf)
{
    __shared__ __align__(16) unsigned As[2][128][20];
    __shared__ __align__(16) unsigned Bs[2][16][136];

    const int t = threadIdx.x;
    const int lane = t & 31, warp = t >> 5;
    const int g = lane >> 2, tig = lane & 3;
    const int wm0 = (warp >> 2) * 64, wn0 = (warp & 3) * 32;
    const int m0 = blockIdx.y * 128, n0 = blockIdx.x * 128;

    const int arow = t >> 2,  akc = (t & 3) * 4;
    const int brow = t >> 5,  bnc = (t & 31) * 4;

    float c[4][4][4] = {};

    {
        #pragma unroll
        for (int j = 0; j < 2; j++) {
            int row = arow + 64 * j;
            float4 f = *(const float4*)&A[(size_t)(m0 + row) * lda + akc];
            As[0][row][akc + 0] = f2t(f.x); As[0][row][akc + 1] = f2t(f.y);
            As[0][row][akc + 2] = f2t(f.z); As[0][row][akc + 3] = f2t(f.w);
        }
        #pragma unroll
        for (int j = 0; j < 2; j++) {
            int row = brow + 8 * j;
            int n = n0 + bnc;
            float4 f = make_float4(0.f, 0.f, 0.f, 0.f);
            if (n < N) f = *(const float4*)&B[(size_t)row * ldb + n];
            Bs[0][row][bnc + 0] = f2t(f.x); Bs[0][row][bnc + 1] = f2t(f.y);
            Bs[0][row][bnc + 2] = f2t(f.z); Bs[0][row][bnc + 3] = f2t(f.w);
        }
    }
    __syncthreads();

    const int nk = K / 16;
    int buf = 0;
    for (int kt = 0; kt < nk; kt++) {
        float4 ra[2], rb[2];
        if (kt + 1 < nk) {
            int k0 = (kt + 1) * 16;
            #pragma unroll
            for (int j = 0; j < 2; j++)
                ra[j] = *(const float4*)&A[(size_t)(m0 + arow + 64 * j) * lda + k0 + akc];
            #pragma unroll
            for (int j = 0; j < 2; j++) {
                int n = n0 + bnc;
                rb[j] = make_float4(0.f, 0.f, 0.f, 0.f);
                if (n < N) rb[j] = *(const float4*)&B[(size_t)(k0 + brow + 8 * j) * ldb + n];
            }
        }
        #pragma unroll
        for (int ks = 0; ks < 16; ks += 8) {
            unsigned af[4][4], bf[4][2];
            #pragma unroll
            for (int mi = 0; mi < 4; mi++) {
                int m = wm0 + mi * 16 + g;
                af[mi][0] = As[buf][m][ks + tig];
                af[mi][1] = As[buf][m + 8][ks + tig];
                af[mi][2] = As[buf][m][ks + tig + 4];
                af[mi][3] = As[buf][m + 8][ks + tig + 4];
            }
            #pragma unroll
            for (int ni = 0; ni < 4; ni++) {
                int n = wn0 + ni * 8 + g;
                bf[ni][0] = Bs[buf][ks + tig][n];
                bf[ni][1] = Bs[buf][ks + tig + 4][n];
            }
            #pragma unroll
            for (int mi = 0; mi < 4; mi++)
                #pragma unroll
                for (int ni = 0; ni < 4; ni++)
                    mma8(c[mi][ni], af[mi], bf[ni]);
        }
        if (kt + 1 < nk) {
            int nb = buf ^ 1;
            #pragma unroll
            for (int j = 0; j < 2; j++) {
                int row = arow + 64 * j;
                As[nb][row][akc + 0] = f2t(ra[j].x); As[nb][row][akc + 1] = f2t(ra[j].y);
                As[nb][row][akc + 2] = f2t(ra[j].z); As[nb][row][akc + 3] = f2t(ra[j].w);
            }
            #pragma unroll
            for (int j = 0; j < 2; j++) {
                int row = brow + 8 * j;
                Bs[nb][row][bnc + 0] = f2t(rb[j].x); Bs[nb][row][bnc + 1] = f2t(rb[j].y);
                Bs[nb][row][bnc + 2] = f2t(rb[j].z); Bs[nb][row][bnc + 3] = f2t(rb[j].w);
            }
            __syncthreads();
        }
        buf ^= 1;
    }

    #pragma unroll
    for (int mi = 0; mi < 4; mi++) {
        int row = m0 + wm0 + mi * 16 + g;
        #pragma unroll
        for (int ni = 0; ni < 4; ni++) {
            int col = n0 + wn0 + ni * 8 + 2 * tig;
            if (col < N) {
                float2 v0 = make_float2(c[mi][ni][0], c[mi][ni][1]);
                float2 v1 = make_float2(c[mi][ni][2], c[mi][ni][3]);
                if (relu) {
                    v0.x = fmaxf(v0.x, 0.f); v0.y = fmaxf(v0.y, 0.f);
                    v1.x = fmaxf(v1.x, 0.f); v1.y = fmaxf(v1.y, 0.f);
                }
                if (obf) {
                    unsigned* Cu = (unsigned*)C;
                    Cu[((size_t)row * ldc + col) / 2]       = pack_bf2(v0.x, v0.y);
                    Cu[((size_t)(row + 8) * ldc + col) / 2] = pack_bf2(v1.x, v1.y);
                } else {
                    *(float2*)&C[(size_t)row * ldc + col] = v0;
                    *(float2*)&C[(size_t)(row + 8) * ldc + col] = v1;
                }
            }
        }
    }
}

// ================= bf16 MMA GEMM, NN — projections (R5 skeleton, K=32/tile) =================
// As: [128][20] words, 16 data words = 32 k packed bf16x2. Bs: [n=128][21] words, kp-major.
#define ABS 20
#define BBS 21
__global__ __launch_bounds__(256, 2) void gemm_nn_bf16(
    const float* __restrict__ A, int lda, const float* __restrict__ B, int ldb,
    float* __restrict__ C, int ldc, int K)
{
    __shared__ __align__(16) unsigned As[2][128 * ABS];
    __shared__ __align__(16) unsigned Bs[2][128 * BBS];

    const int t = threadIdx.x;
    const int lane = t & 31, warp = t >> 5;
    const int g = lane >> 2, tig = lane & 3;
    const int wm0 = (warp >> 2) * 64, wn0 = (warp & 3) * 32;
    const int m0 = blockIdx.y * 128, n0 = blockIdx.x * 128;

    const int arow = t >> 1, akw = (t & 1) * 8;   // A: row, word-half (k-half 0/16)
    const int bkp = t & 15,  bn8 = (t >> 4) * 8;  // B: k-row pair 2bkp/2bkp+1, 8 n-values

    float c[4][4][4] = {};

    // preload tile 0 (packed)
    {
        #pragma unroll
        for (int i = 0; i < 4; i++) {
            float4 f = *(const float4*)&A[(size_t)(m0 + arow) * lda + (t & 1) * 16 + i * 4];
            As[0][arow * ABS + akw + 2 * i]     = pack_bf2(f.x, f.y);
            As[0][arow * ABS + akw + 2 * i + 1] = pack_bf2(f.z, f.w);
        }
        #pragma unroll
        for (int i = 0; i < 2; i++) {
            float4 f0 = *(const float4*)&B[(size_t)(2 * bkp)     * ldb + n0 + bn8 + i * 4];
            float4 f1 = *(const float4*)&B[(size_t)(2 * bkp + 1) * ldb + n0 + bn8 + i * 4];
            Bs[0][(bn8 + i * 4 + 0) * BBS + bkp] = pack_bf2(f0.x, f1.x);
            Bs[0][(bn8 + i * 4 + 1) * BBS + bkp] = pack_bf2(f0.y, f1.y);
            Bs[0][(bn8 + i * 4 + 2) * BBS + bkp] = pack_bf2(f0.z, f1.z);
            Bs[0][(bn8 + i * 4 + 3) * BBS + bkp] = pack_bf2(f0.w, f1.w);
        }
    }
    __syncthreads();

    const int nk = K / 32;
    int buf = 0;
    for (int kt = 0; kt < nk; kt++) {
        unsigned sa[8], sbv[8];
        if (kt + 1 < nk) {
            int k0 = (kt + 1) * 32;
            #pragma unroll
            for (int i = 0; i < 4; i++) {
                float4 f = *(const float4*)&A[(size_t)(m0 + arow) * lda + k0 + (t & 1) * 16 + i * 4];
                sa[2 * i] = pack_bf2(f.x, f.y); sa[2 * i + 1] = pack_bf2(f.z, f.w);
            }
            #pragma unroll
            for (int i = 0; i < 2; i++) {
                float4 f0 = *(const float4*)&B[(size_t)(k0 + 2 * bkp)     * ldb + n0 + bn8 + i * 4];
                float4 f1 = *(const float4*)&B[(size_t)(k0 + 2 * bkp + 1) * ldb + n0 + bn8 + i * 4];
                sbv[4 * i + 0] = pack_bf2(f0.x, f1.x); sbv[4 * i + 1] = pack_bf2(f0.y, f1.y);
                sbv[4 * i + 2] = pack_bf2(f0.z, f1.z); sbv[4 * i + 3] = pack_bf2(f0.w, f1.w);
            }
        }
        // compute K=32: two k16 halves, 32 mma16 total
        const unsigned* Ab = As[buf];
        const unsigned* Bb = Bs[buf];
        #pragma unroll
        for (int ksx = 0; ksx < 2; ksx++) {
            unsigned af[4][4], bf[4][2];
            #pragma unroll
            for (int mi = 0; mi < 4; mi++) {
                int m = wm0 + mi * 16 + g;
                af[mi][0] = Ab[m * ABS + ksx * 8 + tig];
                af[mi][1] = Ab[(m + 8) * ABS + ksx * 8 + tig];
                af[mi][2] = Ab[m * ABS + ksx * 8 + tig + 4];
                af[mi][3] = Ab[(m + 8) * ABS + ksx * 8 + tig + 4];
            }
            #pragma unroll
            for (int ni = 0; ni < 4; ni++) {
                int n = wn0 + ni * 8 + g;
                bf[ni][0] = Bb[n * BBS + ksx * 8 + tig];
                bf[ni][1] = Bb[n * BBS + ksx * 8 + tig + 4];
            }
            #pragma unroll
            for (int mi = 0; mi < 4; mi++)
                #pragma unroll
                for (int ni = 0; ni < 4; ni++)
                    mma16(c[mi][ni], af[mi], bf[ni]);
        }
        if (kt + 1 < nk) {
            int nb = buf ^ 1;
            unsigned* ap = &As[nb][arow * ABS + akw];
            *(uint4*)ap       = make_uint4(sa[0], sa[1], sa[2], sa[3]);
            *(uint4*)(ap + 4) = make_uint4(sa[4], sa[5], sa[6], sa[7]);
            #pragma unroll
            for (int j = 0; j < 8; j++)
                Bs[nb][(bn8 + j) * BBS + bkp] = sbv[j];
            __syncthreads();
        }
        buf ^= 1;
    }

    // epilogue: bf16 output
    #pragma unroll
    for (int mi = 0; mi < 4; mi++) {
        int row = m0 + wm0 + mi * 16 + g;
        #pragma unroll
        for (int ni = 0; ni < 4; ni++) {
            int col = n0 + wn0 + ni * 8 + 2 * tig;
            unsigned* Cu = (unsigned*)C;
            Cu[((size_t)row * ldc + col) / 2]       = pack_bf2(c[mi][ni][0], c[mi][ni][1]);
            Cu[((size_t)(row + 8) * ldc + col) / 2] = pack_bf2(c[mi][ni][2], c[mi][ni][3]);
        }
    }
}

// ================= bf16 pipelined flash attention with rel-shift (R5, proven) =================
#define QS 36        // word stride (72 bf16)
#define GS 264       // sG stride, bf16
#define PS 68        // P word stride (136 bf16)
#define OFF_QW 0
#define OFF_QR 18432
#define OFF_K  36864
#define OFF_V  73728
#define OFF_R  110592
#define OFF_G  147456
#define OFF_RED 215040
#define FA_SMEM 219136

__global__ __launch_bounds__(256, 1) void flash_attn(
    const __nv_bfloat16* __restrict__ Qb, const __nv_bfloat16* __restrict__ Kb,
    const __nv_bfloat16* __restrict__ Vb, const __nv_bfloat16* __restrict__ Rb,
    const float* __restrict__ rwb, const float* __restrict__ rrb,
    float* __restrict__ Om)
{
    extern __shared__ __align__(16) char smem[];
    unsigned*  uQw = (unsigned*)(smem + OFF_QW);
    unsigned*  uQr = (unsigned*)(smem + OFF_QR);
    unsigned*  uG  = (unsigned*)(smem + OFF_G);
    __nv_bfloat16* hG = (__nv_bfloat16*)(smem + OFF_G);
    float* redM = (float*)(smem + OFF_RED);
    float* redS = redM + 512;
    const unsigned sb = (unsigned)__cvta_generic_to_shared(smem);

    const int t = threadIdx.x;
    const int lane = t & 31, warp = t >> 5;
    const int g = lane >> 2, tig = lane & 3;
    const int wm0 = (warp >> 2) * 64;
    const int wn  = warp & 3;
    const int wn0 = wn * 32;
    const int wn0p = wn * 16;

    const int bh = blockIdx.z, b = bh >> 4, h = bh & 15;
    const int q0 = (gridDim.y - 1 - blockIdx.y) * 128;
    const int ntiles = q0 / 128 + 9;

    const __nv_bfloat16* gK = Kb + ((size_t)b * KLEN) * HD + h * DH;
    const __nv_bfloat16* gV = Vb + ((size_t)b * KLEN) * HD + h * DH;
    const __nv_bfloat16* gR = Rb + h * DH;

    {
        #pragma unroll
        for (int i = 0; i < 4; i++) {
            int id = t + 256 * i, row = id >> 3, ch = id & 7;
            cpa16(sb + OFF_K + row * 144 + ch * 16, gK + (size_t)row * HD + ch * 8);
            cpa16(sb + OFF_V + row * 144 + ch * 16, gV + (size_t)row * HD + ch * 8);
        }
        cpa_commit();
        int j0 = 0 - q0 + (QLEN - 128);
        #pragma unroll
        for (int i = 0; i < 8; i++) {
            int id = t + 256 * i, row = id >> 3, ch = id & 7;
            int j = j0 + row; if (j > KLEN - 1) j = KLEN - 1;
            cpa16(sb + OFF_R + row * 144 + ch * 16, gR + (size_t)j * HD + ch * 8);
        }
        cpa_commit();
    }

    {
        const __nv_bfloat16* qsrc = Qb + ((size_t)b * QLEN + q0) * HD + h * DH;
        int lr = t >> 1, lc0 = (t & 1) * 32;
        #pragma unroll
        for (int i = 0; i < 8; i++) {
            int c = lc0 + i * 4;
            uint2 u = *(const uint2*)&qsrc[(size_t)lr * HD + c];
            __nv_bfloat162 q01 = *(__nv_bfloat162*)&u.x;
            __nv_bfloat162 q23 = *(__nv_bfloat162*)&u.y;
            float4 bw = *(const float4*)&rwb[h * DH + c];
            float4 br = *(const float4*)&rrb[h * DH + c];
            float f0 = __bfloat162float(q01.x), f1 = __bfloat162float(q01.y);
            float f2 = __bfloat162float(q23.x), f3 = __bfloat162float(q23.y);
            uQw[lr * QS + c / 2]     = pack_bf2(f0 + bw.x, f1 + bw.y);
            uQw[lr * QS + c / 2 + 1] = pack_bf2(f2 + bw.z, f3 + bw.w);
            uQr[lr * QS + c / 2]     = pack_bf2(f0 + br.x, f1 + br.y);
            uQr[lr * QS + c / 2 + 1] = pack_bf2(f2 + br.z, f3 + br.w);
        }
    }

    float o[4][2][4] = {};
    float mrun[4][2], lrun[4][2];
    #pragma unroll
    for (int mi = 0; mi < 4; mi++)
        #pragma unroll
        for (int hh = 0; hh < 2; hh++) { mrun[mi][hh] = -INFINITY; lrun[mi][hh] = 0.f; }

    int buf = 0;
    for (int kt = 0; kt < ntiles; kt++) {
        const int k0 = kt * 128;
        cpa_waitall();
        __syncthreads();

        if (kt + 1 < ntiles) {
            const __nv_bfloat16* nK = gK + (size_t)(k0 + 128) * HD;
            const __nv_bfloat16* nV = gV + (size_t)(k0 + 128) * HD;
            unsigned kb = OFF_K + (buf ^ 1) * 18432, vb2 = OFF_V + (buf ^ 1) * 18432;
            #pragma unroll
            for (int i = 0; i < 4; i++) {
                int id = t + 256 * i, row = id >> 3, ch = id & 7;
                cpa16(sb + kb + row * 144 + ch * 16, nK + (size_t)row * HD + ch * 8);
                cpa16(sb + vb2 + row * 144 + ch * 16, nV + (size_t)row * HD + ch * 8);
            }
            cpa_commit();
        }

        float acc[4][4][4] = {};
        {
            const unsigned* uK = (const unsigned*)(smem + OFF_K + buf * 18432);
            #pragma unroll
            for (int ks = 0; ks < 4; ks++) {
                unsigned af[4][4], bf[4][2];
                #pragma unroll
                for (int mi = 0; mi < 4; mi++) {
                    int m = wm0 + mi * 16 + g;
                    af[mi][0] = uQw[m * QS + ks * 8 + tig];
                    af[mi][1] = uQw[(m + 8) * QS + ks * 8 + tig];
                    af[mi][2] = uQw[m * QS + ks * 8 + tig + 4];
                    af[mi][3] = uQw[(m + 8) * QS + ks * 8 + tig + 4];
                }
                #pragma unroll
                for (int ni = 0; ni < 4; ni++) {
                    int n = wn0 + ni * 8 + g;
                    bf[ni][0] = uK[n * QS + ks * 8 + tig];
                    bf[ni][1] = uK[n * QS + ks * 8 + tig + 4];
                }
                #pragma unroll
                for (int mi = 0; mi < 4; mi++)
                    #pragma unroll
                    for (int ni = 0; ni < 4; ni++)
                        mma16(acc[mi][ni], af[mi], bf[ni]);
            }
        }

        {
            const unsigned* uR = (const unsigned*)(smem + OFF_R);
            #pragma unroll
            for (int h2 = 0; h2 < 2; h2++) {
                float ga[4][4][4] = {};
                #pragma unroll
                for (int ks = 0; ks < 4; ks++) {
                    unsigned af[4][4], bf[4][2];
                    #pragma unroll
                    for (int mi = 0; mi < 4; mi++) {
                        int m = wm0 + mi * 16 + g;
                        af[mi][0] = uQr[m * QS + ks * 8 + tig];
                        af[mi][1] = uQr[(m + 8) * QS + ks * 8 + tig];
                        af[mi][2] = uQr[m * QS + ks * 8 + tig + 4];
                        af[mi][3] = uQr[(m + 8) * QS + ks * 8 + tig + 4];
                    }
                    #pragma unroll
                    for (int ni = 0; ni < 4; ni++) {
                        int n = h2 * 128 + wn0 + ni * 8 + g;
                        bf[ni][0] = uR[n * QS + ks * 8 + tig];
                        bf[ni][1] = uR[n * QS + ks * 8 + tig + 4];
                    }
                    #pragma unroll
                    for (int mi = 0; mi < 4; mi++)
                        #pragma unroll
                        for (int ni = 0; ni < 4; ni++)
                            mma16(ga[mi][ni], af[mi], bf[ni]);
                }
                #pragma unroll
                for (int mi = 0; mi < 4; mi++)
                    #pragma unroll
                    for (int ni = 0; ni < 4; ni++)
                        #pragma unroll
                        for (int hh = 0; hh < 2; hh++) {
                            int r = wm0 + mi * 16 + g + 8 * hh;
                            int col = h2 * 128 + wn0 + ni * 8 + 2 * tig;
                            uG[(r * GS + col) / 2] = pack_bf2(ga[mi][ni][2 * hh], ga[mi][ni][2 * hh + 1]);
                        }
            }
        }
        __syncthreads();

        if (kt + 1 < ntiles) {
            int j0n = (k0 + 128) - q0 + (QLEN - 128);
            #pragma unroll
            for (int i = 0; i < 8; i++) {
                int id = t + 256 * i, row = id >> 3, ch = id & 7;
                int j = j0n + row; if (j > KLEN - 1) j = KLEN - 1;
                cpa16(sb + OFF_R + row * 144 + ch * 16, gR + (size_t)j * HD + ch * 8);
            }
            cpa_commit();
        }

        #pragma unroll
        for (int mi = 0; mi < 4; mi++)
            #pragma unroll
            for (int ni = 0; ni < 4; ni++)
                #pragma unroll
                for (int hh = 0; hh < 2; hh++)
                    #pragma unroll
                    for (int e = 0; e < 2; e++) {
                        int r = wm0 + mi * 16 + g + 8 * hh;
                        int col = wn0 + ni * 8 + 2 * tig + e;
                        float s = acc[mi][ni][2 * hh + e]
                                + __bfloat162float(hG[r * GS + (col - r + 127)]);
                        acc[mi][ni][2 * hh + e] =
                            ((k0 + col) <= (q0 + r) + MLEN) ? s * 0.03125f : -1e30f;
                    }

        float mw[4][2];
        #pragma unroll
        for (int mi = 0; mi < 4; mi++)
            #pragma unroll
            for (int hh = 0; hh < 2; hh++) {
                float m8 = -INFINITY;
                #pragma unroll
                for (int ni = 0; ni < 4; ni++) {
                    m8 = fmaxf(m8, fmaxf(acc[mi][ni][2 * hh], acc[mi][ni][2 * hh + 1]));
                }
                m8 = fmaxf(m8, __shfl_xor_sync(0xffffffffu, m8, 1));
                m8 = fmaxf(m8, __shfl_xor_sync(0xffffffffu, m8, 2));
                mw[mi][hh] = m8;
                float sw = 0.f;
                #pragma unroll
                for (int ni = 0; ni < 4; ni++)
                    #pragma unroll
                    for (int e = 0; e < 2; e++) {
                        float p = __expf(acc[mi][ni][2 * hh + e] - m8);
                        acc[mi][ni][2 * hh + e] = p;
                        sw += p;
                    }
                sw += __shfl_xor_sync(0xffffffffu, sw, 1);
                sw += __shfl_xor_sync(0xffffffffu, sw, 2);
                if (tig == 0) {
                    int r = wm0 + mi * 16 + g + 8 * hh;
                    redM[wn * 128 + r] = m8;
                    redS[wn * 128 + r] = sw;
                }
            }
        __syncthreads();

        float fsc[4][2];
        #pragma unroll
        for (int mi = 0; mi < 4; mi++)
            #pragma unroll
            for (int hh = 0; hh < 2; hh++) {
                int r = wm0 + mi * 16 + g + 8 * hh;
                float m0v = redM[r], m1v = redM[128 + r], m2v = redM[256 + r], m3v = redM[384 + r];
                float mnew = fmaxf(mrun[mi][hh],
                              fmaxf(fmaxf(m0v, m1v), fmaxf(m2v, m3v)));
                float ladd = redS[r] * __expf(m0v - mnew) + redS[128 + r] * __expf(m1v - mnew)
                           + redS[256 + r] * __expf(m2v - mnew) + redS[384 + r] * __expf(m3v - mnew);
                float alpha = __expf(mrun[mi][hh] - mnew);
                lrun[mi][hh] = lrun[mi][hh] * alpha + ladd;
                mrun[mi][hh] = mnew;
                fsc[mi][hh] = __expf(mw[mi][hh] - mnew);
                #pragma unroll
                for (int ni2 = 0; ni2 < 2; ni2++) {
                    o[mi][ni2][2 * hh]     *= alpha;
                    o[mi][ni2][2 * hh + 1] *= alpha;
                }
            }
        #pragma unroll
        for (int mi = 0; mi < 4; mi++)
            #pragma unroll
            for (int ni = 0; ni < 4; ni++)
                #pragma unroll
                for (int hh = 0; hh < 2; hh++) {
                    int r = wm0 + mi * 16 + g + 8 * hh;
                    int col = wn0 + ni * 8 + 2 * tig;
                    uG[r * PS + col / 2] = pack_bf2(
                        acc[mi][ni][2 * hh] * fsc[mi][hh],
                        acc[mi][ni][2 * hh + 1] * fsc[mi][hh]);
                }
        __syncthreads();

        {
            const unsigned short* hV = (const unsigned short*)(smem + OFF_V + buf * 18432);
            #pragma unroll
            for (int ks = 0; ks < 8; ks++) {
                unsigned af[4][4], bf[2][2];
                #pragma unroll
                for (int mi = 0; mi < 4; mi++) {
                    int m = wm0 + mi * 16 + g;
                    af[mi][0] = uG[m * PS + ks * 8 + tig];
                    af[mi][1] = uG[(m + 8) * PS + ks * 8 + tig];
                    af[mi][2] = uG[m * PS + ks * 8 + tig + 4];
                    af[mi][3] = uG[(m + 8) * PS + ks * 8 + tig + 4];
                }
                #pragma unroll
                for (int ni2 = 0; ni2 < 2; ni2++) {
                    int n = wn0p + ni2 * 8 + g;
                    unsigned lo0 = hV[(ks * 16 + 2 * tig) * 72 + n];
                    unsigned hi0 = hV[(ks * 16 + 2 * tig + 1) * 72 + n];
                    unsigned lo1 = hV[(ks * 16 + 2 * tig + 8) * 72 + n];
                    unsigned hi1 = hV[(ks * 16 + 2 * tig + 9) * 72 + n];
                    bf[ni2][0] = lo0 | (hi0 << 16);
                    bf[ni2][1] = lo1 | (hi1 << 16);
                }
                #pragma unroll
                for (int mi = 0; mi < 4; mi++)
                    #pragma unroll
                    for (int ni2 = 0; ni2 < 2; ni2++)
                        mma16(o[mi][ni2], af[mi], bf[ni2]);
            }
        }
        buf ^= 1;
    }

    #pragma unroll
    for (int mi = 0; mi < 4; mi++)
        #pragma unroll
        for (int ni2 = 0; ni2 < 2; ni2++)
            #pragma unroll
            for (int hh = 0; hh < 2; hh++) {
                int r = wm0 + mi * 16 + g + 8 * hh;
                int d = wn0p + ni2 * 8 + 2 * tig;
                float inv = 1.0f / lrun[mi][hh];
                *(float2*)&Om[((size_t)b * QLEN + q0 + r) * HD + h * DH + d] =
                    make_float2(o[mi][ni2][2 * hh] * inv, o[mi][ni2][2 * hh + 1] * inv);
            }
}

// ---------------- out = LayerNorm(a + b), rows of EE ----------------
__global__ __launch_bounds__(256) void add_ln_kernel(
    const float* __restrict__ A, const float* __restrict__ Bv,
    const float* __restrict__ gamma, const float* __restrict__ beta,
    float* __restrict__ out)
{
    __shared__ float red[256];
    const size_t row = blockIdx.x;
    const int t = threadIdx.x;
    float4 va = ((const float4*)(A + row * EE))[t];
    float4 vb = ((const float4*)(Bv + row * EE))[t];
    float4 v = make_float4(va.x + vb.x, va.y + vb.y, va.z + vb.z, va.w + vb.w);

    red[t] = v.x + v.y + v.z + v.w; __syncthreads();
    for (int s = 128; s > 0; s >>= 1) { if (t < s) red[t] += red[t + s]; __syncthreads(); }
    const float mean = red[0] * (1.0f / EE); __syncthreads();

    float dx = v.x - mean, dy = v.y - mean, dz = v.z - mean, dw = v.w - mean;
    red[t] = dx * dx + dy * dy + dz * dz + dw * dw; __syncthreads();
    for (int s = 128; s > 0; s >>= 1) { if (t < s) red[t] += red[t + s]; __syncthreads(); }
    const float inv = rsqrtf(red[0] * (1.0f / EE) + 1e-3f);

    float4 gm = ((const float4*)gamma)[t];
    float4 bt = ((const float4*)beta)[t];
    float4 o;
    o.x = dx * inv * gm.x + bt.x; o.y = dy * inv * gm.y + bt.y;
    o.z = dz * inv * gm.z + bt.z; o.w = dw * inv * gm.w + bt.w;
    ((float4*)(out + row * EE))[t] = o;
}

// ---------------- launch ----------------
extern "C" void kernel_launch(void* const* d_in, const int* in_sizes, int n_in,
                              void* d_out, int out_size)
{
    const float* w      = (const float*)d_in[0];
    const float* r      = (const float*)d_in[1];
    const float* member = (const float*)d_in[2];
    const float* Wq  = (const float*)d_in[4];
    const float* Wk  = (const float*)d_in[5];
    const float* Wv  = (const float*)d_in[6];
    const float* Wr  = (const float*)d_in[7];
    const float* Wo  = (const float*)d_in[8];
    const float* rwb = (const float*)d_in[9];
    const float* rrb = (const float*)d_in[10];
    const float* ln1g = (const float*)d_in[11];
    const float* ln1b = (const float*)d_in[12];
    const float* W1  = (const float*)d_in[13];
    const float* W2  = (const float*)d_in[14];
    const float* ln2g = (const float*)d_in[15];
    const float* ln2b = (const float*)d_in[16];
    float* out = (float*)d_out;

    static float *p_cat = nullptr, *p_q, *p_k, *p_v, *p_r,
                 *p_att, *p_o, *p_x, *p_ffn, *p_y;
    if (!p_cat) {
        cudaGetSymbolAddress((void**)&p_cat, g_cat);
        cudaGetSymbolAddress((void**)&p_q,   g_q);
        cudaGetSymbolAddress((void**)&p_k,   g_k);
        cudaGetSymbolAddress((void**)&p_v,   g_v);
        cudaGetSymbolAddress((void**)&p_r,   g_r);
        cudaGetSymbolAddress((void**)&p_att, g_att);
        cudaGetSymbolAddress((void**)&p_o,   g_o);
        cudaGetSymbolAddress((void**)&p_x,   g_x);
        cudaGetSymbolAddress((void**)&p_ffn, g_ffn);
        cudaGetSymbolAddress((void**)&p_y,   g_y);
        cudaFuncSetAttribute(flash_attn, cudaFuncAttributeMaxDynamicSharedMemorySize, FA_SMEM);
    }

    // 1. cat
    copy_cat_kernel<<<(BB * KLEN * EE / 4) / 256, 256>>>(
        (const float4*)w, (const float4*)member, (float4*)p_cat);

    // 2. projections (bf16 MMA, K=32/tile, bf16 output)
    gemm_nn_bf16<<<dim3(HD / 128, (BB * QLEN) / 128), 256>>>(w,     EE, Wq, HD, p_q, HD, EE);
    gemm_nn_bf16<<<dim3(HD / 128, (BB * KLEN) / 128), 256>>>(p_cat, EE, Wk, HD, p_k, HD, EE);
    gemm_nn_bf16<<<dim3(HD / 128, (BB * KLEN) / 128), 256>>>(p_cat, EE, Wv, HD, p_v, HD, EE);
    gemm_nn_bf16<<<dim3(HD / 128, KLEN / 128),        256>>>(r,     EE, Wr, HD, p_r, HD, EE);

    // 3. fused attention
    flash_attn<<<dim3(1, QLEN / 128, BB * HH), 256, FA_SMEM>>>(
        (const __nv_bfloat16*)p_q, (const __nv_bfloat16*)p_k,
        (const __nv_bfloat16*)p_v, (const __nv_bfloat16*)p_r,
        rwb, rrb, p_att);

    // 4. output projection + LN1 (tf32)
    gemm_nn_tf32<<<dim3(EE / 128, (BB * QLEN) / 128), 256>>>(p_att, HD, Wo, EE, p_o, EE, EE, HD, 0, 0);
    add_ln_kernel<<<BB * QLEN, 256>>>(w, p_o, ln1g, ln1b, p_x);

    // 5. FFN + LN2 -> out (tf32)
    gemm_nn_tf32<<<dim3(FF / 128, (BB * QLEN) / 128), 256>>>(p_x,   EE, W1, FF, p_ffn, FF, FF, EE, 1, 0);
    gemm_nn_tf32<<<dim3(EE / 128, (BB * QLEN) / 128), 256>>>(p_ffn, FF, W2, EE, p_y,   EE, EE, FF, 0, 0);
    add_ln_kernel<<<BB * QLEN, 256>>>(p_y, p_x, ln2g, ln2b, out);
}

// round 10
// speedup vs baseline: 1.4041x; 1.1210x over previous
#include <cuda_runtime.h>
#include <cuda_bf16.h>
#include <math.h>

#define BB 2
#define QLEN 1024
#define MLEN 1024
#define KLEN 2048
#define EE 1024
#define HH 16
#define DH 64
#define HD 1024   // HH*DH
#define FF 4096

// ---------------- scratch ----------------
static __device__ float g_cat[(size_t)BB * KLEN * EE];
static __device__ float g_q  [(size_t)BB * QLEN * HD];   // used as bf16
static __device__ float g_k  [(size_t)BB * KLEN * HD];   // used as bf16
static __device__ float g_v  [(size_t)BB * KLEN * HD];   // used as bf16
static __device__ float g_r  [(size_t)KLEN * HD];        // used as bf16
static __device__ float g_att[(size_t)BB * QLEN * HD];
static __device__ float g_o  [(size_t)BB * QLEN * EE];
static __device__ float g_x  [(size_t)BB * QLEN * EE];
static __device__ float g_ffn[(size_t)BB * QLEN * FF];
static __device__ float g_y  [(size_t)BB * QLEN * EE];

// ---------------- helpers ----------------
__device__ __forceinline__ unsigned f2t(float x) {
    unsigned u; asm("cvt.rna.tf32.f32 %0, %1;" : "=r"(u) : "f"(x)); return u;
}
__device__ __forceinline__ unsigned pack_bf2(float lo, float hi) {
    unsigned u; asm("cvt.rn.bf16x2.f32 %0, %1, %2;" : "=r"(u) : "f"(hi), "f"(lo)); return u;
}
__device__ __forceinline__ void mma8(float* c, const unsigned* a, const unsigned* b) {
    asm volatile("mma.sync.aligned.m16n8k8.row.col.f32.tf32.tf32.f32 "
        "{%0,%1,%2,%3}, {%4,%5,%6,%7}, {%8,%9}, {%0,%1,%2,%3};\n"
        : "+f"(c[0]), "+f"(c[1]), "+f"(c[2]), "+f"(c[3])
        : "r"(a[0]), "r"(a[1]), "r"(a[2]), "r"(a[3]), "r"(b[0]), "r"(b[1]));
}
__device__ __forceinline__ void mma16(float* c, const unsigned* a, const unsigned* b) {
    asm volatile("mma.sync.aligned.m16n8k16.row.col.f32.bf16.bf16.f32 "
        "{%0,%1,%2,%3}, {%4,%5,%6,%7}, {%8,%9}, {%0,%1,%2,%3};\n"
        : "+f"(c[0]), "+f"(c[1]), "+f"(c[2]), "+f"(c[3])
        : "r"(a[0]), "r"(a[1]), "r"(a[2]), "r"(a[3]), "r"(b[0]), "r"(b[1]));
}
__device__ __forceinline__ void ldsm4(unsigned* r, unsigned saddr) {
    asm volatile("ldmatrix.sync.aligned.m8n8.x4.shared.b16 {%0,%1,%2,%3}, [%4];"
        : "=r"(r[0]), "=r"(r[1]), "=r"(r[2]), "=r"(r[3]) : "r"(saddr));
}
__device__ __forceinline__ void ldsm4t(unsigned* r, unsigned saddr) {
    asm volatile("ldmatrix.sync.aligned.m8n8.x4.trans.shared.b16 {%0,%1,%2,%3}, [%4];"
        : "=r"(r[0]), "=r"(r[1]), "=r"(r[2]), "=r"(r[3]) : "r"(saddr));
}
__device__ __forceinline__ void cpa16(unsigned saddr, const void* g) {
    asm volatile("cp.async.cg.shared.global [%0], [%1], 16;" :: "r"(saddr), "l"(g));
}
__device__ __forceinline__ void cpa_commit() { asm volatile("cp.async.commit_group;"); }
__device__ __forceinline__ void cpa_waitall() { asm volatile("cp.async.wait_group 0;"); }

// ---------------- cat = concat(member, w) ----------------
__global__ __launch_bounds__(256) void copy_cat_kernel(
    const float4* __restrict__ w, const float4* __restrict__ member, float4* __restrict__ cat)
{
    size_t i = (size_t)blockIdx.x * 256 + threadIdx.x;
    int e4 = (int)(i % (EE / 4));
    size_t t2 = i / (EE / 4);
    int kl = (int)(t2 % KLEN);
    int b  = (int)(t2 / KLEN);
    float4 v;
    if (kl < MLEN) v = member[((size_t)b * MLEN + kl) * (EE / 4) + e4];
    else           v = w[((size_t)b * QLEN + (kl - MLEN)) * (EE / 4) + e4];
    cat[i] = v;
}

// ================= tf32 MMA GEMM, NN (R5, proven); obf=1 writes bf16 =================
__global__ __launch_bounds__(256, 2) void gemm_nn_tf32(
    const float* __restrict__ A, int lda, const float* __restrict__ B, int ldb,
    float* __restrict__ C, int ldc, int N, int K, int relu, int obf)
{
    __shared__ __align__(16) unsigned As[2][128][20];
    __shared__ __align__(16) unsigned Bs[2][16][136];

    const int t = threadIdx.x;
    const int lane = t & 31, warp = t >> 5;
    const int g = lane >> 2, tig = lane & 3;
    const int wm0 = (warp >> 2) * 64, wn0 = (warp & 3) * 32;
    const int m0 = blockIdx.y * 128, n0 = blockIdx.x * 128;

    const int arow = t >> 2,  akc = (t & 3) * 4;
    const int brow = t >> 5,  bnc = (t & 31) * 4;

    float c[4][4][4] = {};

    {
        #pragma unroll
        for (int j = 0; j < 2; j++) {
            int row = arow + 64 * j;
            float4 f = *(const float4*)&A[(size_t)(m0 + row) * lda + akc];
            As[0][row][akc + 0] = f2t(f.x); As[0][row][akc + 1] = f2t(f.y);
            As[0][row][akc + 2] = f2t(f.z); As[0][row][akc + 3] = f2t(f.w);
        }
        #pragma unroll
        for (int j = 0; j < 2; j++) {
            int row = brow + 8 * j;
            int n = n0 + bnc;
            float4 f = make_float4(0.f, 0.f, 0.f, 0.f);
            if (n < N) f = *(const float4*)&B[(size_t)row * ldb + n];
            Bs[0][row][bnc + 0] = f2t(f.x); Bs[0][row][bnc + 1] = f2t(f.y);
            Bs[0][row][bnc + 2] = f2t(f.z); Bs[0][row][bnc + 3] = f2t(f.w);
        }
    }
    __syncthreads();

    const int nk = K / 16;
    int buf = 0;
    for (int kt = 0; kt < nk; kt++) {
        float4 ra[2], rb[2];
        if (kt + 1 < nk) {
            int k0 = (kt + 1) * 16;
            #pragma unroll
            for (int j = 0; j < 2; j++)
                ra[j] = *(const float4*)&A[(size_t)(m0 + arow + 64 * j) * lda + k0 + akc];
            #pragma unroll
            for (int j = 0; j < 2; j++) {
                int n = n0 + bnc;
                rb[j] = make_float4(0.f, 0.f, 0.f, 0.f);
                if (n < N) rb[j] = *(const float4*)&B[(size_t)(k0 + brow + 8 * j) * ldb + n];
            }
        }
        #pragma unroll
        for (int ks = 0; ks < 16; ks += 8) {
            unsigned af[4][4], bf[4][2];
            #pragma unroll
            for (int mi = 0; mi < 4; mi++) {
                int m = wm0 + mi * 16 + g;
                af[mi][0] = As[buf][m][ks + tig];
                af[mi][1] = As[buf][m + 8][ks + tig];
                af[mi][2] = As[buf][m][ks + tig + 4];
                af[mi][3] = As[buf][m + 8][ks + tig + 4];
            }
            #pragma unroll
            for (int ni = 0; ni < 4; ni++) {
                int n = wn0 + ni * 8 + g;
                bf[ni][0] = Bs[buf][ks + tig][n];
                bf[ni][1] = Bs[buf][ks + tig + 4][n];
            }
            #pragma unroll
            for (int mi = 0; mi < 4; mi++)
                #pragma unroll
                for (int ni = 0; ni < 4; ni++)
                    mma8(c[mi][ni], af[mi], bf[ni]);
        }
        if (kt + 1 < nk) {
            int nb = buf ^ 1;
            #pragma unroll
            for (int j = 0; j < 2; j++) {
                int row = arow + 64 * j;
                As[nb][row][akc + 0] = f2t(ra[j].x); As[nb][row][akc + 1] = f2t(ra[j].y);
                As[nb][row][akc + 2] = f2t(ra[j].z); As[nb][row][akc + 3] = f2t(ra[j].w);
            }
            #pragma unroll
            for (int j = 0; j < 2; j++) {
                int row = brow + 8 * j;
                Bs[nb][row][bnc + 0] = f2t(rb[j].x); Bs[nb][row][bnc + 1] = f2t(rb[j].y);
                Bs[nb][row][bnc + 2] = f2t(rb[j].z); Bs[nb][row][bnc + 3] = f2t(rb[j].w);
            }
            __syncthreads();
        }
        buf ^= 1;
    }

    #pragma unroll
    for (int mi = 0; mi < 4; mi++) {
        int row = m0 + wm0 + mi * 16 + g;
        #pragma unroll
        for (int ni = 0; ni < 4; ni++) {
            int col = n0 + wn0 + ni * 8 + 2 * tig;
            if (col < N) {
                float2 v0 = make_float2(c[mi][ni][0], c[mi][ni][1]);
                float2 v1 = make_float2(c[mi][ni][2], c[mi][ni][3]);
                if (relu) {
                    v0.x = fmaxf(v0.x, 0.f); v0.y = fmaxf(v0.y, 0.f);
                    v1.x = fmaxf(v1.x, 0.f); v1.y = fmaxf(v1.y, 0.f);
                }
                if (obf) {
                    unsigned* Cu = (unsigned*)C;
                    Cu[((size_t)row * ldc + col) / 2]       = pack_bf2(v0.x, v0.y);
                    Cu[((size_t)(row + 8) * ldc + col) / 2] = pack_bf2(v1.x, v1.y);
                } else {
                    *(float2*)&C[(size_t)row * ldc + col] = v0;
                    *(float2*)&C[(size_t)(row + 8) * ldc + col] = v1;
                }
            }
        }
    }
}

// ================= bf16 GEMM — coalesced loaders + ldmatrix consumers =================
// As: 128 rows x 20 words (32 bf16 + pad). Bs: 32 k-rows x 68 words (128 bf16 + pad).
#define ABW 20
#define BBW 68
__global__ __launch_bounds__(256, 2) void gemm_nn_bf16(
    const float* __restrict__ A, int lda, const float* __restrict__ B, int ldb,
    float* __restrict__ C, int ldc, int K)
{
    __shared__ __align__(16) unsigned As[2][128 * ABW];
    __shared__ __align__(16) unsigned Bs[2][32 * BBW];

    const int t = threadIdx.x;
    const int lane = t & 31, warp = t >> 5;
    const int g = lane >> 2, tig = lane & 3;
    const int wm0 = (warp >> 2) * 64, wn0 = (warp & 3) * 32;
    const int m0 = blockIdx.y * 128, n0 = blockIdx.x * 128;

    // producers
    const int ar = t >> 2, ac = t & 3;      // A: rows ar, ar+64; 8 floats at col ac*8
    const int br = t >> 3, bc = t & 7;      // B: k-row br; 16 floats at col bc*16

    // ldmatrix lane addressing (word offsets)
    const int l15 = lane & 15, lh = lane >> 4;
    const int bkl = (lane & 7) + 8 * ((lane >> 3) & 1);
    const unsigned sA0 = (unsigned)__cvta_generic_to_shared(&As[0][0]);
    const unsigned sB0 = (unsigned)__cvta_generic_to_shared(&Bs[0][0]);

    float c[4][4][4] = {};

    // ---- preload stage 0 ----
    {
        #pragma unroll
        for (int p = 0; p < 2; p++) {
            const float* src = A + (size_t)(m0 + ar + 64 * p) * lda + ac * 8;
            float4 f0 = ((const float4*)src)[0], f1 = ((const float4*)src)[1];
            uint4 v = make_uint4(pack_bf2(f0.x, f0.y), pack_bf2(f0.z, f0.w),
                                 pack_bf2(f1.x, f1.y), pack_bf2(f1.z, f1.w));
            *(uint4*)&As[0][(ar + 64 * p) * ABW + ac * 4] = v;
        }
        const float* bsrc = B + (size_t)br * ldb + n0 + bc * 16;
        float4 f0 = ((const float4*)bsrc)[0], f1 = ((const float4*)bsrc)[1];
        float4 f2 = ((const float4*)bsrc)[2], f3 = ((const float4*)bsrc)[3];
        *(uint4*)&Bs[0][br * BBW + bc * 8] =
            make_uint4(pack_bf2(f0.x, f0.y), pack_bf2(f0.z, f0.w),
                       pack_bf2(f1.x, f1.y), pack_bf2(f1.z, f1.w));
        *(uint4*)&Bs[0][br * BBW + bc * 8 + 4] =
            make_uint4(pack_bf2(f2.x, f2.y), pack_bf2(f2.z, f2.w),
                       pack_bf2(f3.x, f3.y), pack_bf2(f3.z, f3.w));
    }
    __syncthreads();

    const int nk = K / 32;
    int buf = 0;
    for (int kt = 0; kt < nk; kt++) {
        unsigned sa[8], sbv[8];
        if (kt + 1 < nk) {
            int k0 = (kt + 1) * 32;
            #pragma unroll
            for (int p = 0; p < 2; p++) {
                const float* src = A + (size_t)(m0 + ar + 64 * p) * lda + k0 + ac * 8;
                float4 f0 = ((const float4*)src)[0], f1 = ((const float4*)src)[1];
                sa[4*p+0] = pack_bf2(f0.x, f0.y); sa[4*p+1] = pack_bf2(f0.z, f0.w);
                sa[4*p+2] = pack_bf2(f1.x, f1.y); sa[4*p+3] = pack_bf2(f1.z, f1.w);
            }
            const float* bsrc = B + (size_t)(k0 + br) * ldb + n0 + bc * 16;
            float4 f0 = ((const float4*)bsrc)[0], f1 = ((const float4*)bsrc)[1];
            float4 f2 = ((const float4*)bsrc)[2], f3 = ((const float4*)bsrc)[3];
            sbv[0] = pack_bf2(f0.x, f0.y); sbv[1] = pack_bf2(f0.z, f0.w);
            sbv[2] = pack_bf2(f1.x, f1.y); sbv[3] = pack_bf2(f1.z, f1.w);
            sbv[4] = pack_bf2(f2.x, f2.y); sbv[5] = pack_bf2(f2.z, f2.w);
            sbv[6] = pack_bf2(f3.x, f3.y); sbv[7] = pack_bf2(f3.z, f3.w);
        }

        // ---- compute stage: K=32 (two k16 halves) ----
        const unsigned sAb = sA0 + buf * (128 * ABW * 4);
        const unsigned sBb = sB0 + buf * (32 * BBW * 4);
        #pragma unroll
        for (int ksx = 0; ksx < 2; ksx++) {
            unsigned af[4][4];
            #pragma unroll
            for (int mi = 0; mi < 4; mi++)
                ldsm4(af[mi], sAb + (((wm0 + mi * 16 + l15) * ABW) + ksx * 8 + lh * 4) * 4);
            #pragma unroll
            for (int nb = 0; nb < 2; nb++) {
                unsigned br4[4];
                ldsm4t(br4, sBb + ((ksx * 16 + bkl) * BBW + (wn0 >> 1) + nb * 8 + 4 * lh) * 4);
                #pragma unroll
                for (int mi = 0; mi < 4; mi++) {
                    mma16(c[mi][2 * nb],     af[mi], br4);
                    mma16(c[mi][2 * nb + 1], af[mi], br4 + 2);
                }
            }
        }

        if (kt + 1 < nk) {
            int nb2 = buf ^ 1;
            *(uint4*)&As[nb2][ar * ABW + ac * 4]        = make_uint4(sa[0], sa[1], sa[2], sa[3]);
            *(uint4*)&As[nb2][(ar + 64) * ABW + ac * 4] = make_uint4(sa[4], sa[5], sa[6], sa[7]);
            *(uint4*)&Bs[nb2][br * BBW + bc * 8]     = make_uint4(sbv[0], sbv[1], sbv[2], sbv[3]);
            *(uint4*)&Bs[nb2][br * BBW + bc * 8 + 4] = make_uint4(sbv[4], sbv[5], sbv[6], sbv[7]);
            __syncthreads();
        }
        buf ^= 1;
    }

    // ---- epilogue: bf16 output ----
    #pragma unroll
    for (int mi = 0; mi < 4; mi++) {
        int row = m0 + wm0 + mi * 16 + g;
        #pragma unroll
        for (int ni = 0; ni < 4; ni++) {
            int col = n0 + wn0 + ni * 8 + 2 * tig;
            unsigned* Cu = (unsigned*)C;
            Cu[((size_t)row * ldc + col) / 2]       = pack_bf2(c[mi][ni][0], c[mi][ni][1]);
            Cu[((size_t)(row + 8) * ldc + col) / 2] = pack_bf2(c[mi][ni][2], c[mi][ni][3]);
        }
    }
}

// ================= bf16 pipelined flash attention with rel-shift (R5, proven) =================
#define QS 36        // word stride (72 bf16)
#define GS 264       // sG stride, bf16
#define PS 68        // P word stride (136 bf16)
#define OFF_QW 0
#define OFF_QR 18432
#define OFF_K  36864
#define OFF_V  73728
#define OFF_R  110592
#define OFF_G  147456
#define OFF_RED 215040
#define FA_SMEM 219136

__global__ __launch_bounds__(256, 1) void flash_attn(
    const __nv_bfloat16* __restrict__ Qb, const __nv_bfloat16* __restrict__ Kb,
    const __nv_bfloat16* __restrict__ Vb, const __nv_bfloat16* __restrict__ Rb,
    const float* __restrict__ rwb, const float* __restrict__ rrb,
    float* __restrict__ Om)
{
    extern __shared__ __align__(16) char smem[];
    unsigned*  uQw = (unsigned*)(smem + OFF_QW);
    unsigned*  uQr = (unsigned*)(smem + OFF_QR);
    unsigned*  uG  = (unsigned*)(smem + OFF_G);
    __nv_bfloat16* hG = (__nv_bfloat16*)(smem + OFF_G);
    float* redM = (float*)(smem + OFF_RED);
    float* redS = redM + 512;
    const unsigned sb = (unsigned)__cvta_generic_to_shared(smem);

    const int t = threadIdx.x;
    const int lane = t & 31, warp = t >> 5;
    const int g = lane >> 2, tig = lane & 3;
    const int wm0 = (warp >> 2) * 64;
    const int wn  = warp & 3;
    const int wn0 = wn * 32;
    const int wn0p = wn * 16;

    const int bh = blockIdx.z, b = bh >> 4, h = bh & 15;
    const int q0 = (gridDim.y - 1 - blockIdx.y) * 128;
    const int ntiles = q0 / 128 + 9;

    const __nv_bfloat16* gK = Kb + ((size_t)b * KLEN) * HD + h * DH;
    const __nv_bfloat16* gV = Vb + ((size_t)b * KLEN) * HD + h * DH;
    const __nv_bfloat16* gR = Rb + h * DH;

    {
        #pragma unroll
        for (int i = 0; i < 4; i++) {
            int id = t + 256 * i, row = id >> 3, ch = id & 7;
            cpa16(sb + OFF_K + row * 144 + ch * 16, gK + (size_t)row * HD + ch * 8);
            cpa16(sb + OFF_V + row * 144 + ch * 16, gV + (size_t)row * HD + ch * 8);
        }
        cpa_commit();
        int j0 = 0 - q0 + (QLEN - 128);
        #pragma unroll
        for (int i = 0; i < 8; i++) {
            int id = t + 256 * i, row = id >> 3, ch = id & 7;
            int j = j0 + row; if (j > KLEN - 1) j = KLEN - 1;
            cpa16(sb + OFF_R + row * 144 + ch * 16, gR + (size_t)j * HD + ch * 8);
        }
        cpa_commit();
    }

    {
        const __nv_bfloat16* qsrc = Qb + ((size_t)b * QLEN + q0) * HD + h * DH;
        int lr = t >> 1, lc0 = (t & 1) * 32;
        #pragma unroll
        for (int i = 0; i < 8; i++) {
            int c = lc0 + i * 4;
            uint2 u = *(const uint2*)&qsrc[(size_t)lr * HD + c];
            __nv_bfloat162 q01 = *(__nv_bfloat162*)&u.x;
            __nv_bfloat162 q23 = *(__nv_bfloat162*)&u.y;
            float4 bw = *(const float4*)&rwb[h * DH + c];
            float4 br = *(const float4*)&rrb[h * DH + c];
            float f0 = __bfloat162float(q01.x), f1 = __bfloat162float(q01.y);
            float f2 = __bfloat162float(q23.x), f3 = __bfloat162float(q23.y);
            uQw[lr * QS + c / 2]     = pack_bf2(f0 + bw.x, f1 + bw.y);
            uQw[lr * QS + c / 2 + 1] = pack_bf2(f2 + bw.z, f3 + bw.w);
            uQr[lr * QS + c / 2]     = pack_bf2(f0 + br.x, f1 + br.y);
            uQr[lr * QS + c / 2 + 1] = pack_bf2(f2 + br.z, f3 + br.w);
        }
    }

    float o[4][2][4] = {};
    float mrun[4][2], lrun[4][2];
    #pragma unroll
    for (int mi = 0; mi < 4; mi++)
        #pragma unroll
        for (int hh = 0; hh < 2; hh++) { mrun[mi][hh] = -INFINITY; lrun[mi][hh] = 0.f; }

    int buf = 0;
    for (int kt = 0; kt < ntiles; kt++) {
        const int k0 = kt * 128;
        cpa_waitall();
        __syncthreads();

        if (kt + 1 < ntiles) {
            const __nv_bfloat16* nK = gK + (size_t)(k0 + 128) * HD;
            const __nv_bfloat16* nV = gV + (size_t)(k0 + 128) * HD;
            unsigned kb = OFF_K + (buf ^ 1) * 18432, vb2 = OFF_V + (buf ^ 1) * 18432;
            #pragma unroll
            for (int i = 0; i < 4; i++) {
                int id = t + 256 * i, row = id >> 3, ch = id & 7;
                cpa16(sb + kb + row * 144 + ch * 16, nK + (size_t)row * HD + ch * 8);
                cpa16(sb + vb2 + row * 144 + ch * 16, nV + (size_t)row * HD + ch * 8);
            }
            cpa_commit();
        }

        float acc[4][4][4] = {};
        {
            const unsigned* uK = (const unsigned*)(smem + OFF_K + buf * 18432);
            #pragma unroll
            for (int ks = 0; ks < 4; ks++) {
                unsigned af[4][4], bf[4][2];
                #pragma unroll
                for (int mi = 0; mi < 4; mi++) {
                    int m = wm0 + mi * 16 + g;
                    af[mi][0] = uQw[m * QS + ks * 8 + tig];
                    af[mi][1] = uQw[(m + 8) * QS + ks * 8 + tig];
                    af[mi][2] = uQw[m * QS + ks * 8 + tig + 4];
                    af[mi][3] = uQw[(m + 8) * QS + ks * 8 + tig + 4];
                }
                #pragma unroll
                for (int ni = 0; ni < 4; ni++) {
                    int n = wn0 + ni * 8 + g;
                    bf[ni][0] = uK[n * QS + ks * 8 + tig];
                    bf[ni][1] = uK[n * QS + ks * 8 + tig + 4];
                }
                #pragma unroll
                for (int mi = 0; mi < 4; mi++)
                    #pragma unroll
                    for (int ni = 0; ni < 4; ni++)
                        mma16(acc[mi][ni], af[mi], bf[ni]);
            }
        }

        {
            const unsigned* uR = (const unsigned*)(smem + OFF_R);
            #pragma unroll
            for (int h2 = 0; h2 < 2; h2++) {
                float ga[4][4][4] = {};
                #pragma unroll
                for (int ks = 0; ks < 4; ks++) {
                    unsigned af[4][4], bf[4][2];
                    #pragma unroll
                    for (int mi = 0; mi < 4; mi++) {
                        int m = wm0 + mi * 16 + g;
                        af[mi][0] = uQr[m * QS + ks * 8 + tig];
                        af[mi][1] = uQr[(m + 8) * QS + ks * 8 + tig];
                        af[mi][2] = uQr[m * QS + ks * 8 + tig + 4];
                        af[mi][3] = uQr[(m + 8) * QS + ks * 8 + tig + 4];
                    }
                    #pragma unroll
                    for (int ni = 0; ni < 4; ni++) {
                        int n = h2 * 128 + wn0 + ni * 8 + g;
                        bf[ni][0] = uR[n * QS + ks * 8 + tig];
                        bf[ni][1] = uR[n * QS + ks * 8 + tig + 4];
                    }
                    #pragma unroll
                    for (int mi = 0; mi < 4; mi++)
                        #pragma unroll
                        for (int ni = 0; ni < 4; ni++)
                            mma16(ga[mi][ni], af[mi], bf[ni]);
                }
                #pragma unroll
                for (int mi = 0; mi < 4; mi++)
                    #pragma unroll
                    for (int ni = 0; ni < 4; ni++)
                        #pragma unroll
                        for (int hh = 0; hh < 2; hh++) {
                            int r = wm0 + mi * 16 + g + 8 * hh;
                            int col = h2 * 128 + wn0 + ni * 8 + 2 * tig;
                            uG[(r * GS + col) / 2] = pack_bf2(ga[mi][ni][2 * hh], ga[mi][ni][2 * hh + 1]);
                        }
            }
        }
        __syncthreads();

        if (kt + 1 < ntiles) {
            int j0n = (k0 + 128) - q0 + (QLEN - 128);
            #pragma unroll
            for (int i = 0; i < 8; i++) {
                int id = t + 256 * i, row = id >> 3, ch = id & 7;
                int j = j0n + row; if (j > KLEN - 1) j = KLEN - 1;
                cpa16(sb + OFF_R + row * 144 + ch * 16, gR + (size_t)j * HD + ch * 8);
            }
            cpa_commit();
        }

        #pragma unroll
        for (int mi = 0; mi < 4; mi++)
            #pragma unroll
            for (int ni = 0; ni < 4; ni++)
                #pragma unroll
                for (int hh = 0; hh < 2; hh++)
                    #pragma unroll
                    for (int e = 0; e < 2; e++) {
                        int r = wm0 + mi * 16 + g + 8 * hh;
                        int col = wn0 + ni * 8 + 2 * tig + e;
                        float s = acc[mi][ni][2 * hh + e]
                                + __bfloat162float(hG[r * GS + (col - r + 127)]);
                        acc[mi][ni][2 * hh + e] =
                            ((k0 + col) <= (q0 + r) + MLEN) ? s * 0.03125f : -1e30f;
                    }

        float mw[4][2];
        #pragma unroll
        for (int mi = 0; mi < 4; mi++)
            #pragma unroll
            for (int hh = 0; hh < 2; hh++) {
                float m8 = -INFINITY;
                #pragma unroll
                for (int ni = 0; ni < 4; ni++) {
                    m8 = fmaxf(m8, fmaxf(acc[mi][ni][2 * hh], acc[mi][ni][2 * hh + 1]));
                }
                m8 = fmaxf(m8, __shfl_xor_sync(0xffffffffu, m8, 1));
                m8 = fmaxf(m8, __shfl_xor_sync(0xffffffffu, m8, 2));
                mw[mi][hh] = m8;
                float sw = 0.f;
                #pragma unroll
                for (int ni = 0; ni < 4; ni++)
                    #pragma unroll
                    for (int e = 0; e < 2; e++) {
                        float p = __expf(acc[mi][ni][2 * hh + e] - m8);
                        acc[mi][ni][2 * hh + e] = p;
                        sw += p;
                    }
                sw += __shfl_xor_sync(0xffffffffu, sw, 1);
                sw += __shfl_xor_sync(0xffffffffu, sw, 2);
                if (tig == 0) {
                    int r = wm0 + mi * 16 + g + 8 * hh;
                    redM[wn * 128 + r] = m8;
                    redS[wn * 128 + r] = sw;
                }
            }
        __syncthreads();

        float fsc[4][2];
        #pragma unroll
        for (int mi = 0; mi < 4; mi++)
            #pragma unroll
            for (int hh = 0; hh < 2; hh++) {
                int r = wm0 + mi * 16 + g + 8 * hh;
                float m0v = redM[r], m1v = redM[128 + r], m2v = redM[256 + r], m3v = redM[384 + r];
                float mnew = fmaxf(mrun[mi][hh],
                              fmaxf(fmaxf(m0v, m1v), fmaxf(m2v, m3v)));
                float ladd = redS[r] * __expf(m0v - mnew) + redS[128 + r] * __expf(m1v - mnew)
                           + redS[256 + r] * __expf(m2v - mnew) + redS[384 + r] * __expf(m3v - mnew);
                float alpha = __expf(mrun[mi][hh] - mnew);
                lrun[mi][hh] = lrun[mi][hh] * alpha + ladd;
                mrun[mi][hh] = mnew;
                fsc[mi][hh] = __expf(mw[mi][hh] - mnew);
                #pragma unroll
                for (int ni2 = 0; ni2 < 2; ni2++) {
                    o[mi][ni2][2 * hh]     *= alpha;
                    o[mi][ni2][2 * hh + 1] *= alpha;
                }
            }
        #pragma unroll
        for (int mi = 0; mi < 4; mi++)
            #pragma unroll
            for (int ni = 0; ni < 4; ni++)
                #pragma unroll
                for (int hh = 0; hh < 2; hh++) {
                    int r = wm0 + mi * 16 + g + 8 * hh;
                    int col = wn0 + ni * 8 + 2 * tig;
                    uG[r * PS + col / 2] = pack_bf2(
                        acc[mi][ni][2 * hh] * fsc[mi][hh],
                        acc[mi][ni][2 * hh + 1] * fsc[mi][hh]);
                }
        __syncthreads();

        {
            const unsigned short* hV = (const unsigned short*)(smem + OFF_V + buf * 18432);
            #pragma unroll
            for (int ks = 0; ks < 8; ks++) {
                unsigned af[4][4], bf[2][2];
                #pragma unroll
                for (int mi = 0; mi < 4; mi++) {
                    int m = wm0 + mi * 16 + g;
                    af[mi][0] = uG[m * PS + ks * 8 + tig];
                    af[mi][1] = uG[(m + 8) * PS + ks * 8 + tig];
                    af[mi][2] = uG[m * PS + ks * 8 + tig + 4];
                    af[mi][3] = uG[(m + 8) * PS + ks * 8 + tig + 4];
                }
                #pragma unroll
                for (int ni2 = 0; ni2 < 2; ni2++) {
                    int n = wn0p + ni2 * 8 + g;
                    unsigned lo0 = hV[(ks * 16 + 2 * tig) * 72 + n];
                    unsigned hi0 = hV[(ks * 16 + 2 * tig + 1) * 72 + n];
                    unsigned lo1 = hV[(ks * 16 + 2 * tig + 8) * 72 + n];
                    unsigned hi1 = hV[(ks * 16 + 2 * tig + 9) * 72 + n];
                    bf[ni2][0] = lo0 | (hi0 << 16);
                    bf[ni2][1] = lo1 | (hi1 << 16);
                }
                #pragma unroll
                for (int mi = 0; mi < 4; mi++)
                    #pragma unroll
                    for (int ni2 = 0; ni2 < 2; ni2++)
                        mma16(o[mi][ni2], af[mi], bf[ni2]);
            }
        }
        buf ^= 1;
    }

    #pragma unroll
    for (int mi = 0; mi < 4; mi++)
        #pragma unroll
        for (int ni2 = 0; ni2 < 2; ni2++)
            #pragma unroll
            for (int hh = 0; hh < 2; hh++) {
                int r = wm0 + mi * 16 + g + 8 * hh;
                int d = wn0p + ni2 * 8 + 2 * tig;
                float inv = 1.0f / lrun[mi][hh];
                *(float2*)&Om[((size_t)b * QLEN + q0 + r) * HD + h * DH + d] =
                    make_float2(o[mi][ni2][2 * hh] * inv, o[mi][ni2][2 * hh + 1] * inv);
            }
}

// ---------------- out = LayerNorm(a + b), rows of EE ----------------
__global__ __launch_bounds__(256) void add_ln_kernel(
    const float* __restrict__ A, const float* __restrict__ Bv,
    const float* __restrict__ gamma, const float* __restrict__ beta,
    float* __restrict__ out)
{
    __shared__ float red[256];
    const size_t row = blockIdx.x;
    const int t = threadIdx.x;
    float4 va = ((const float4*)(A + row * EE))[t];
    float4 vb = ((const float4*)(Bv + row * EE))[t];
    float4 v = make_float4(va.x + vb.x, va.y + vb.y, va.z + vb.z, va.w + vb.w);

    red[t] = v.x + v.y + v.z + v.w; __syncthreads();
    for (int s = 128; s > 0; s >>= 1) { if (t < s) red[t] += red[t + s]; __syncthreads(); }
    const float mean = red[0] * (1.0f / EE); __syncthreads();

    float dx = v.x - mean, dy = v.y - mean, dz = v.z - mean, dw = v.w - mean;
    red[t] = dx * dx + dy * dy + dz * dz + dw * dw; __syncthreads();
    for (int s = 128; s > 0; s >>= 1) { if (t < s) red[t] += red[t + s]; __syncthreads(); }
    const float inv = rsqrtf(red[0] * (1.0f / EE) + 1e-3f);

    float4 gm = ((const float4*)gamma)[t];
    float4 bt = ((const float4*)beta)[t];
    float4 o;
    o.x = dx * inv * gm.x + bt.x; o.y = dy * inv * gm.y + bt.y;
    o.z = dz * inv * gm.z + bt.z; o.w = dw * inv * gm.w + bt.w;
    ((float4*)(out + row * EE))[t] = o;
}

// ---------------- launch ----------------
extern "C" void kernel_launch(void* const* d_in, const int* in_sizes, int n_in,
                              void* d_out, int out_size)
{
    const float* w      = (const float*)d_in[0];
    const float* r      = (const float*)d_in[1];
    const float* member = (const float*)d_in[2];
    const float* Wq  = (const float*)d_in[4];
    const float* Wk  = (const float*)d_in[5];
    const float* Wv  = (const float*)d_in[6];
    const float* Wr  = (const float*)d_in[7];
    const float* Wo  = (const float*)d_in[8];
    const float* rwb = (const float*)d_in[9];
    const float* rrb = (const float*)d_in[10];
    const float* ln1g = (const float*)d_in[11];
    const float* ln1b = (const float*)d_in[12];
    const float* W1  = (const float*)d_in[13];
    const float* W2  = (const float*)d_in[14];
    const float* ln2g = (const float*)d_in[15];
    const float* ln2b = (const float*)d_in[16];
    float* out = (float*)d_out;

    static float *p_cat = nullptr, *p_q, *p_k, *p_v, *p_r,
                 *p_att, *p_o, *p_x, *p_ffn, *p_y;
    if (!p_cat) {
        cudaGetSymbolAddress((void**)&p_cat, g_cat);
        cudaGetSymbolAddress((void**)&p_q,   g_q);
        cudaGetSymbolAddress((void**)&p_k,   g_k);
        cudaGetSymbolAddress((void**)&p_v,   g_v);
        cudaGetSymbolAddress((void**)&p_r,   g_r);
        cudaGetSymbolAddress((void**)&p_att, g_att);
        cudaGetSymbolAddress((void**)&p_o,   g_o);
        cudaGetSymbolAddress((void**)&p_x,   g_x);
        cudaGetSymbolAddress((void**)&p_ffn, g_ffn);
        cudaGetSymbolAddress((void**)&p_y,   g_y);
        cudaFuncSetAttribute(flash_attn, cudaFuncAttributeMaxDynamicSharedMemorySize, FA_SMEM);
    }

    // 1. cat
    copy_cat_kernel<<<(BB * KLEN * EE / 4) / 256, 256>>>(
        (const float4*)w, (const float4*)member, (float4*)p_cat);

    // 2. projections (bf16 MMA + ldmatrix, bf16 output)
    gemm_nn_bf16<<<dim3(HD / 128, (BB * QLEN) / 128), 256>>>(w,     EE, Wq, HD, p_q, HD, EE);
    gemm_nn_bf16<<<dim3(HD / 128, (BB * KLEN) / 128), 256>>>(p_cat, EE, Wk, HD, p_k, HD, EE);
    gemm_nn_bf16<<<dim3(HD / 128, (BB * KLEN) / 128), 256>>>(p_cat, EE, Wv, HD, p_v, HD, EE);
    gemm_nn_bf16<<<dim3(HD / 128, KLEN / 128),        256>>>(r,     EE, Wr, HD, p_r, HD, EE);

    // 3. fused attention
    flash_attn<<<dim3(1, QLEN / 128, BB * HH), 256, FA_SMEM>>>(
        (const __nv_bfloat16*)p_q, (const __nv_bfloat16*)p_k,
        (const __nv_bfloat16*)p_v, (const __nv_bfloat16*)p_r,
        rwb, rrb, p_att);

    // 4. output projection + LN1 (tf32)
    gemm_nn_tf32<<<dim3(EE / 128, (BB * QLEN) / 128), 256>>>(p_att, HD, Wo, EE, p_o, EE, EE, HD, 0, 0);
    add_ln_kernel<<<BB * QLEN, 256>>>(w, p_o, ln1g, ln1b, p_x);

    // 5. FFN + LN2 -> out (tf32)
    gemm_nn_tf32<<<dim3(FF / 128, (BB * QLEN) / 128), 256>>>(p_x,   EE, W1, FF, p_ffn, FF, FF, EE, 1, 0);
    gemm_nn_tf32<<<dim3(EE / 128, (BB * QLEN) / 128), 256>>>(p_ffn, FF, W2, EE, p_y,   EE, EE, FF, 0, 0);
    add_ln_kernel<<<BB * QLEN, 256>>>(p_y, p_x, ln2g, ln2b, out);
}

// round 11
// speedup vs baseline: 1.5902x; 1.1325x over previous
#include <cuda_runtime.h>
#include <cuda_bf16.h>
#include <cuda_fp16.h>
#include <math.h>

#define BB 2
#define QLEN 1024
#define MLEN 1024
#define KLEN 2048
#define EE 1024
#define HH 16
#define DH 64
#define HD 1024   // HH*DH
#define FF 4096

// ---------------- scratch ----------------
static __device__ float g_cat[(size_t)BB * KLEN * EE / 2];   // bf16
static __device__ float g_q  [(size_t)BB * QLEN * HD];   // bf16
static __device__ float g_k  [(size_t)BB * KLEN * HD];   // bf16
static __device__ float g_v  [(size_t)BB * KLEN * HD];   // bf16
static __device__ float g_r  [(size_t)KLEN * HD];        // bf16
static __device__ float g_att[(size_t)BB * QLEN * HD];
static __device__ float g_o  [(size_t)BB * QLEN * EE];
static __device__ float g_x  [(size_t)BB * QLEN * EE];
static __device__ float g_ffn[(size_t)BB * QLEN * FF];
static __device__ float g_y  [(size_t)BB * QLEN * EE];

// ---------------- helpers ----------------
__device__ __forceinline__ unsigned pack_bf2(float lo, float hi) {
    unsigned u; asm("cvt.rn.bf16x2.f32 %0, %1, %2;" : "=r"(u) : "f"(hi), "f"(lo)); return u;
}
template<int BF>
__device__ __forceinline__ unsigned pack2(float lo, float hi) {
    unsigned u;
    if (BF) asm("cvt.rn.bf16x2.f32 %0, %1, %2;" : "=r"(u) : "f"(hi), "f"(lo));
    else    asm("cvt.rn.f16x2.f32 %0, %1, %2;"  : "=r"(u) : "f"(hi), "f"(lo));
    return u;
}
__device__ __forceinline__ void mma16(float* c, const unsigned* a, const unsigned* b) {
    asm volatile("mma.sync.aligned.m16n8k16.row.col.f32.bf16.bf16.f32 "
        "{%0,%1,%2,%3}, {%4,%5,%6,%7}, {%8,%9}, {%0,%1,%2,%3};\n"
        : "+f"(c[0]), "+f"(c[1]), "+f"(c[2]), "+f"(c[3])
        : "r"(a[0]), "r"(a[1]), "r"(a[2]), "r"(a[3]), "r"(b[0]), "r"(b[1]));
}
template<int BF>
__device__ __forceinline__ void mmah(float* c, const unsigned* a, const unsigned* b) {
    if (BF)
        asm volatile("mma.sync.aligned.m16n8k16.row.col.f32.bf16.bf16.f32 "
            "{%0,%1,%2,%3}, {%4,%5,%6,%7}, {%8,%9}, {%0,%1,%2,%3};\n"
            : "+f"(c[0]), "+f"(c[1]), "+f"(c[2]), "+f"(c[3])
            : "r"(a[0]), "r"(a[1]), "r"(a[2]), "r"(a[3]), "r"(b[0]), "r"(b[1]));
    else
        asm volatile("mma.sync.aligned.m16n8k16.row.col.f32.f16.f16.f32 "
            "{%0,%1,%2,%3}, {%4,%5,%6,%7}, {%8,%9}, {%0,%1,%2,%3};\n"
            : "+f"(c[0]), "+f"(c[1]), "+f"(c[2]), "+f"(c[3])
            : "r"(a[0]), "r"(a[1]), "r"(a[2]), "r"(a[3]), "r"(b[0]), "r"(b[1]));
}
__device__ __forceinline__ void ldsm4(unsigned* r, unsigned saddr) {
    asm volatile("ldmatrix.sync.aligned.m8n8.x4.shared.b16 {%0,%1,%2,%3}, [%4];"
        : "=r"(r[0]), "=r"(r[1]), "=r"(r[2]), "=r"(r[3]) : "r"(saddr));
}
__device__ __forceinline__ void ldsm4t(unsigned* r, unsigned saddr) {
    asm volatile("ldmatrix.sync.aligned.m8n8.x4.trans.shared.b16 {%0,%1,%2,%3}, [%4];"
        : "=r"(r[0]), "=r"(r[1]), "=r"(r[2]), "=r"(r[3]) : "r"(saddr));
}
__device__ __forceinline__ void cpa16(unsigned saddr, const void* g) {
    asm volatile("cp.async.cg.shared.global [%0], [%1], 16;" :: "r"(saddr), "l"(g));
}
__device__ __forceinline__ void cpa_commit() { asm volatile("cp.async.commit_group;"); }
__device__ __forceinline__ void cpa_waitall() { asm volatile("cp.async.wait_group 0;"); }

// ---------------- cat = concat(member, w), bf16 output ----------------
__global__ __launch_bounds__(256) void copy_cat_kernel(
    const float4* __restrict__ w, const float4* __restrict__ member, uint2* __restrict__ cat)
{
    size_t i = (size_t)blockIdx.x * 256 + threadIdx.x;   // quad index
    int e4 = (int)(i % (EE / 4));
    size_t t2 = i / (EE / 4);
    int kl = (int)(t2 % KLEN);
    int b  = (int)(t2 / KLEN);
    float4 v;
    if (kl < MLEN) v = member[((size_t)b * MLEN + kl) * (EE / 4) + e4];
    else           v = w[((size_t)b * QLEN + (kl - MLEN)) * (EE / 4) + e4];
    cat[i] = make_uint2(pack_bf2(v.x, v.y), pack_bf2(v.z, v.w));
}

// ================= half-precision GEMM (ldmatrix consumers, R10-proven) =================
// BF: 1 = bf16 compute, 0 = fp16 compute. ABF: A operand already bf16 (requires BF=1).
// OBF: output bf16. RELU: fused relu. QMODE: A rows offset into cat layout (w rows).
// As: 128 rows x 20 words (32 halves + pad). Bs: 32 k-rows x 68 words (128 halves + pad).
#define ABW 20
#define BBW 68
template<int BF, int ABF, int OBF, int RELU, int QMODE>
__global__ __launch_bounds__(256, 2) void gemm_h(
    const void* __restrict__ Ap, int lda, const float* __restrict__ B, int ldb,
    float* __restrict__ C, int ldc, int K)
{
    __shared__ __align__(16) unsigned As[2][128 * ABW];
    __shared__ __align__(16) unsigned Bs[2][32 * BBW];

    const int t = threadIdx.x;
    const int lane = t & 31, warp = t >> 5;
    const int g = lane >> 2, tig = lane & 3;
    const int wm0 = (warp >> 2) * 64, wn0 = (warp & 3) * 32;
    const int m0 = blockIdx.y * 128, n0 = blockIdx.x * 128;
    const int moff = QMODE ? (((m0 >> 10) + 1) << 10) : 0;   // cat row offset for w rows

    const float* Af = (const float*)Ap;
    const __nv_bfloat16* Ah = (const __nv_bfloat16*)Ap;

    // producers
    const int ar = t >> 2, ac = t & 3;      // A: rows ar, ar+64; 8 values at col ac*8
    const int br = t >> 3, bc = t & 7;      // B: k-row br; 16 values at col bc*16

    // ldmatrix lane addressing
    const int l15 = lane & 15, lh = lane >> 4;
    const int bkl = (lane & 7) + 8 * ((lane >> 3) & 1);
    const unsigned sA0 = (unsigned)__cvta_generic_to_shared(&As[0][0]);
    const unsigned sB0 = (unsigned)__cvta_generic_to_shared(&Bs[0][0]);

    float c[4][4][4] = {};

    // ---- A tile loader (k0 = tile K offset) ----
    auto loadA = [&](int k0, unsigned* dst8) {
        #pragma unroll
        for (int p = 0; p < 2; p++) {
            size_t row = (size_t)(m0 + moff + ar + 64 * p);
            if (ABF) {
                uint4 v = *(const uint4*)&Ah[row * lda + k0 + ac * 8];
                dst8[4*p+0] = v.x; dst8[4*p+1] = v.y; dst8[4*p+2] = v.z; dst8[4*p+3] = v.w;
            } else {
                const float* src = Af + row * lda + k0 + ac * 8;
                float4 f0 = ((const float4*)src)[0], f1 = ((const float4*)src)[1];
                dst8[4*p+0] = pack2<BF>(f0.x, f0.y); dst8[4*p+1] = pack2<BF>(f0.z, f0.w);
                dst8[4*p+2] = pack2<BF>(f1.x, f1.y); dst8[4*p+3] = pack2<BF>(f1.z, f1.w);
            }
        }
    };
    auto loadB = [&](int k0, unsigned* dst8) {
        const float* bsrc = B + (size_t)(k0 + br) * ldb + n0 + bc * 16;
        float4 f0 = ((const float4*)bsrc)[0], f1 = ((const float4*)bsrc)[1];
        float4 f2 = ((const float4*)bsrc)[2], f3 = ((const float4*)bsrc)[3];
        dst8[0] = pack2<BF>(f0.x, f0.y); dst8[1] = pack2<BF>(f0.z, f0.w);
        dst8[2] = pack2<BF>(f1.x, f1.y); dst8[3] = pack2<BF>(f1.z, f1.w);
        dst8[4] = pack2<BF>(f2.x, f2.y); dst8[5] = pack2<BF>(f2.z, f2.w);
        dst8[6] = pack2<BF>(f3.x, f3.y); dst8[7] = pack2<BF>(f3.z, f3.w);
    };

    // ---- preload stage 0 ----
    {
        unsigned sa[8], sbv[8];
        loadA(0, sa); loadB(0, sbv);
        *(uint4*)&As[0][ar * ABW + ac * 4]        = make_uint4(sa[0], sa[1], sa[2], sa[3]);
        *(uint4*)&As[0][(ar + 64) * ABW + ac * 4] = make_uint4(sa[4], sa[5], sa[6], sa[7]);
        *(uint4*)&Bs[0][br * BBW + bc * 8]        = make_uint4(sbv[0], sbv[1], sbv[2], sbv[3]);
        *(uint4*)&Bs[0][br * BBW + bc * 8 + 4]    = make_uint4(sbv[4], sbv[5], sbv[6], sbv[7]);
    }
    __syncthreads();

    const int nk = K / 32;
    int buf = 0;
    for (int kt = 0; kt < nk; kt++) {
        unsigned sa[8], sbv[8];
        if (kt + 1 < nk) { loadA((kt + 1) * 32, sa); loadB((kt + 1) * 32, sbv); }

        // ---- compute stage: K=32 (two k16 halves) ----
        const unsigned sAb = sA0 + buf * (128 * ABW * 4);
        const unsigned sBb = sB0 + buf * (32 * BBW * 4);
        #pragma unroll
        for (int ksx = 0; ksx < 2; ksx++) {
            unsigned af[4][4];
            #pragma unroll
            for (int mi = 0; mi < 4; mi++)
                ldsm4(af[mi], sAb + (((wm0 + mi * 16 + l15) * ABW) + ksx * 8 + lh * 4) * 4);
            #pragma unroll
            for (int nb = 0; nb < 2; nb++) {
                unsigned br4[4];
                ldsm4t(br4, sBb + ((ksx * 16 + bkl) * BBW + (wn0 >> 1) + nb * 8 + 4 * lh) * 4);
                #pragma unroll
                for (int mi = 0; mi < 4; mi++) {
                    mmah<BF>(c[mi][2 * nb],     af[mi], br4);
                    mmah<BF>(c[mi][2 * nb + 1], af[mi], br4 + 2);
                }
            }
        }

        if (kt + 1 < nk) {
            int nb2 = buf ^ 1;
            *(uint4*)&As[nb2][ar * ABW + ac * 4]        = make_uint4(sa[0], sa[1], sa[2], sa[3]);
            *(uint4*)&As[nb2][(ar + 64) * ABW + ac * 4] = make_uint4(sa[4], sa[5], sa[6], sa[7]);
            *(uint4*)&Bs[nb2][br * BBW + bc * 8]        = make_uint4(sbv[0], sbv[1], sbv[2], sbv[3]);
            *(uint4*)&Bs[nb2][br * BBW + bc * 8 + 4]    = make_uint4(sbv[4], sbv[5], sbv[6], sbv[7]);
            __syncthreads();
        }
        buf ^= 1;
    }

    // ---- epilogue ----
    #pragma unroll
    for (int mi = 0; mi < 4; mi++) {
        int row = m0 + wm0 + mi * 16 + g;
        #pragma unroll
        for (int ni = 0; ni < 4; ni++) {
            int col = n0 + wn0 + ni * 8 + 2 * tig;
            float v0 = c[mi][ni][0], v1 = c[mi][ni][1];
            float v2 = c[mi][ni][2], v3 = c[mi][ni][3];
            if (RELU) {
                v0 = fmaxf(v0, 0.f); v1 = fmaxf(v1, 0.f);
                v2 = fmaxf(v2, 0.f); v3 = fmaxf(v3, 0.f);
            }
            if (OBF) {
                unsigned* Cu = (unsigned*)C;
                Cu[((size_t)row * ldc + col) / 2]       = pack_bf2(v0, v1);
                Cu[((size_t)(row + 8) * ldc + col) / 2] = pack_bf2(v2, v3);
            } else {
                *(float2*)&C[(size_t)row * ldc + col]       = make_float2(v0, v1);
                *(float2*)&C[(size_t)(row + 8) * ldc + col] = make_float2(v2, v3);
            }
        }
    }
}

// ================= bf16 pipelined flash attention with rel-shift (R5/R10, proven) =================
#define QS 36
#define GS 264
#define PS 68
#define OFF_QW 0
#define OFF_QR 18432
#define OFF_K  36864
#define OFF_V  73728
#define OFF_R  110592
#define OFF_G  147456
#define OFF_RED 215040
#define FA_SMEM 219136

__global__ __launch_bounds__(256, 1) void flash_attn(
    const __nv_bfloat16* __restrict__ Qb, const __nv_bfloat16* __restrict__ Kb,
    const __nv_bfloat16* __restrict__ Vb, const __nv_bfloat16* __restrict__ Rb,
    const float* __restrict__ rwb, const float* __restrict__ rrb,
    float* __restrict__ Om)
{
    extern __shared__ __align__(16) char smem[];
    unsigned*  uQw = (unsigned*)(smem + OFF_QW);
    unsigned*  uQr = (unsigned*)(smem + OFF_QR);
    unsigned*  uG  = (unsigned*)(smem + OFF_G);
    __nv_bfloat16* hG = (__nv_bfloat16*)(smem + OFF_G);
    float* redM = (float*)(smem + OFF_RED);
    float* redS = redM + 512;
    const unsigned sb = (unsigned)__cvta_generic_to_shared(smem);

    const int t = threadIdx.x;
    const int lane = t & 31, warp = t >> 5;
    const int g = lane >> 2, tig = lane & 3;
    const int wm0 = (warp >> 2) * 64;
    const int wn  = warp & 3;
    const int wn0 = wn * 32;
    const int wn0p = wn * 16;

    const int bh = blockIdx.z, b = bh >> 4, h = bh & 15;
    const int q0 = (gridDim.y - 1 - blockIdx.y) * 128;
    const int ntiles = q0 / 128 + 9;

    const __nv_bfloat16* gK = Kb + ((size_t)b * KLEN) * HD + h * DH;
    const __nv_bfloat16* gV = Vb + ((size_t)b * KLEN) * HD + h * DH;
    const __nv_bfloat16* gR = Rb + h * DH;

    {
        #pragma unroll
        for (int i = 0; i < 4; i++) {
            int id = t + 256 * i, row = id >> 3, ch = id & 7;
            cpa16(sb + OFF_K + row * 144 + ch * 16, gK + (size_t)row * HD + ch * 8);
            cpa16(sb + OFF_V + row * 144 + ch * 16, gV + (size_t)row * HD + ch * 8);
        }
        cpa_commit();
        int j0 = 0 - q0 + (QLEN - 128);
        #pragma unroll
        for (int i = 0; i < 8; i++) {
            int id = t + 256 * i, row = id >> 3, ch = id & 7;
            int j = j0 + row; if (j > KLEN - 1) j = KLEN - 1;
            cpa16(sb + OFF_R + row * 144 + ch * 16, gR + (size_t)j * HD + ch * 8);
        }
        cpa_commit();
    }

    {
        const __nv_bfloat16* qsrc = Qb + ((size_t)b * QLEN + q0) * HD + h * DH;
        int lr = t >> 1, lc0 = (t & 1) * 32;
        #pragma unroll
        for (int i = 0; i < 8; i++) {
            int c = lc0 + i * 4;
            uint2 u = *(const uint2*)&qsrc[(size_t)lr * HD + c];
            __nv_bfloat162 q01 = *(__nv_bfloat162*)&u.x;
            __nv_bfloat162 q23 = *(__nv_bfloat162*)&u.y;
            float4 bw = *(const float4*)&rwb[h * DH + c];
            float4 br = *(const float4*)&rrb[h * DH + c];
            float f0 = __bfloat162float(q01.x), f1 = __bfloat162float(q01.y);
            float f2 = __bfloat162float(q23.x), f3 = __bfloat162float(q23.y);
            uQw[lr * QS + c / 2]     = pack_bf2(f0 + bw.x, f1 + bw.y);
            uQw[lr * QS + c / 2 + 1] = pack_bf2(f2 + bw.z, f3 + bw.w);
            uQr[lr * QS + c / 2]     = pack_bf2(f0 + br.x, f1 + br.y);
            uQr[lr * QS + c / 2 + 1] = pack_bf2(f2 + br.z, f3 + br.w);
        }
    }

    float o[4][2][4] = {};
    float mrun[4][2], lrun[4][2];
    #pragma unroll
    for (int mi = 0; mi < 4; mi++)
        #pragma unroll
        for (int hh = 0; hh < 2; hh++) { mrun[mi][hh] = -INFINITY; lrun[mi][hh] = 0.f; }

    int buf = 0;
    for (int kt = 0; kt < ntiles; kt++) {
        const int k0 = kt * 128;
        cpa_waitall();
        __syncthreads();

        if (kt + 1 < ntiles) {
            const __nv_bfloat16* nK = gK + (size_t)(k0 + 128) * HD;
            const __nv_bfloat16* nV = gV + (size_t)(k0 + 128) * HD;
            unsigned kb = OFF_K + (buf ^ 1) * 18432, vb2 = OFF_V + (buf ^ 1) * 18432;
            #pragma unroll
            for (int i = 0; i < 4; i++) {
                int id = t + 256 * i, row = id >> 3, ch = id & 7;
                cpa16(sb + kb + row * 144 + ch * 16, nK + (size_t)row * HD + ch * 8);
                cpa16(sb + vb2 + row * 144 + ch * 16, nV + (size_t)row * HD + ch * 8);
            }
            cpa_commit();
        }

        float acc[4][4][4] = {};
        {
            const unsigned* uK = (const unsigned*)(smem + OFF_K + buf * 18432);
            #pragma unroll
            for (int ks = 0; ks < 4; ks++) {
                unsigned af[4][4], bf[4][2];
                #pragma unroll
                for (int mi = 0; mi < 4; mi++) {
                    int m = wm0 + mi * 16 + g;
                    af[mi][0] = uQw[m * QS + ks * 8 + tig];
                    af[mi][1] = uQw[(m + 8) * QS + ks * 8 + tig];
                    af[mi][2] = uQw[m * QS + ks * 8 + tig + 4];
                    af[mi][3] = uQw[(m + 8) * QS + ks * 8 + tig + 4];
                }
                #pragma unroll
                for (int ni = 0; ni < 4; ni++) {
                    int n = wn0 + ni * 8 + g;
                    bf[ni][0] = uK[n * QS + ks * 8 + tig];
                    bf[ni][1] = uK[n * QS + ks * 8 + tig + 4];
                }
                #pragma unroll
                for (int mi = 0; mi < 4; mi++)
                    #pragma unroll
                    for (int ni = 0; ni < 4; ni++)
                        mma16(acc[mi][ni], af[mi], bf[ni]);
            }
        }

        {
            const unsigned* uR = (const unsigned*)(smem + OFF_R);
            #pragma unroll
            for (int h2 = 0; h2 < 2; h2++) {
                float ga[4][4][4] = {};
                #pragma unroll
                for (int ks = 0; ks < 4; ks++) {
                    unsigned af[4][4], bf[4][2];
                    #pragma unroll
                    for (int mi = 0; mi < 4; mi++) {
                        int m = wm0 + mi * 16 + g;
                        af[mi][0] = uQr[m * QS + ks * 8 + tig];
                        af[mi][1] = uQr[(m + 8) * QS + ks * 8 + tig];
                        af[mi][2] = uQr[m * QS + ks * 8 + tig + 4];
                        af[mi][3] = uQr[(m + 8) * QS + ks * 8 + tig + 4];
                    }
                    #pragma unroll
                    for (int ni = 0; ni < 4; ni++) {
                        int n = h2 * 128 + wn0 + ni * 8 + g;
                        bf[ni][0] = uR[n * QS + ks * 8 + tig];
                        bf[ni][1] = uR[n * QS + ks * 8 + tig + 4];
                    }
                    #pragma unroll
                    for (int mi = 0; mi < 4; mi++)
                        #pragma unroll
                        for (int ni = 0; ni < 4; ni++)
                            mma16(ga[mi][ni], af[mi], bf[ni]);
                }
                #pragma unroll
                for (int mi = 0; mi < 4; mi++)
                    #pragma unroll
                    for (int ni = 0; ni < 4; ni++)
                        #pragma unroll
                        for (int hh = 0; hh < 2; hh++) {
                            int r = wm0 + mi * 16 + g + 8 * hh;
                            int col = h2 * 128 + wn0 + ni * 8 + 2 * tig;
                            uG[(r * GS + col) / 2] = pack_bf2(ga[mi][ni][2 * hh], ga[mi][ni][2 * hh + 1]);
                        }
            }
        }
        __syncthreads();

        if (kt + 1 < ntiles) {
            int j0n = (k0 + 128) - q0 + (QLEN - 128);
            #pragma unroll
            for (int i = 0; i < 8; i++) {
                int id = t + 256 * i, row = id >> 3, ch = id & 7;
                int j = j0n + row; if (j > KLEN - 1) j = KLEN - 1;
                cpa16(sb + OFF_R + row * 144 + ch * 16, gR + (size_t)j * HD + ch * 8);
            }
            cpa_commit();
        }

        #pragma unroll
        for (int mi = 0; mi < 4; mi++)
            #pragma unroll
            for (int ni = 0; ni < 4; ni++)
                #pragma unroll
                for (int hh = 0; hh < 2; hh++)
                    #pragma unroll
                    for (int e = 0; e < 2; e++) {
                        int r = wm0 + mi * 16 + g + 8 * hh;
                        int col = wn0 + ni * 8 + 2 * tig + e;
                        float s = acc[mi][ni][2 * hh + e]
                                + __bfloat162float(hG[r * GS + (col - r + 127)]);
                        acc[mi][ni][2 * hh + e] =
                            ((k0 + col) <= (q0 + r) + MLEN) ? s * 0.03125f : -1e30f;
                    }

        float mw[4][2];
        #pragma unroll
        for (int mi = 0; mi < 4; mi++)
            #pragma unroll
            for (int hh = 0; hh < 2; hh++) {
                float m8 = -INFINITY;
                #pragma unroll
                for (int ni = 0; ni < 4; ni++) {
                    m8 = fmaxf(m8, fmaxf(acc[mi][ni][2 * hh], acc[mi][ni][2 * hh + 1]));
                }
                m8 = fmaxf(m8, __shfl_xor_sync(0xffffffffu, m8, 1));
                m8 = fmaxf(m8, __shfl_xor_sync(0xffffffffu, m8, 2));
                mw[mi][hh] = m8;
                float sw = 0.f;
                #pragma unroll
                for (int ni = 0; ni < 4; ni++)
                    #pragma unroll
                    for (int e = 0; e < 2; e++) {
                        float p = __expf(acc[mi][ni][2 * hh + e] - m8);
                        acc[mi][ni][2 * hh + e] = p;
                        sw += p;
                    }
                sw += __shfl_xor_sync(0xffffffffu, sw, 1);
                sw += __shfl_xor_sync(0xffffffffu, sw, 2);
                if (tig == 0) {
                    int r = wm0 + mi * 16 + g + 8 * hh;
                    redM[wn * 128 + r] = m8;
                    redS[wn * 128 + r] = sw;
                }
            }
        __syncthreads();

        float fsc[4][2];
        #pragma unroll
        for (int mi = 0; mi < 4; mi++)
            #pragma unroll
            for (int hh = 0; hh < 2; hh++) {
                int r = wm0 + mi * 16 + g + 8 * hh;
                float m0v = redM[r], m1v = redM[128 + r], m2v = redM[256 + r], m3v = redM[384 + r];
                float mnew = fmaxf(mrun[mi][hh],
                              fmaxf(fmaxf(m0v, m1v), fmaxf(m2v, m3v)));
                float ladd = redS[r] * __expf(m0v - mnew) + redS[128 + r] * __expf(m1v - mnew)
                           + redS[256 + r] * __expf(m2v - mnew) + redS[384 + r] * __expf(m3v - mnew);
                float alpha = __expf(mrun[mi][hh] - mnew);
                lrun[mi][hh] = lrun[mi][hh] * alpha + ladd;
                mrun[mi][hh] = mnew;
                fsc[mi][hh] = __expf(mw[mi][hh] - mnew);
                #pragma unroll
                for (int ni2 = 0; ni2 < 2; ni2++) {
                    o[mi][ni2][2 * hh]     *= alpha;
                    o[mi][ni2][2 * hh + 1] *= alpha;
                }
            }
        #pragma unroll
        for (int mi = 0; mi < 4; mi++)
            #pragma unroll
            for (int ni = 0; ni < 4; ni++)
                #pragma unroll
                for (int hh = 0; hh < 2; hh++) {
                    int r = wm0 + mi * 16 + g + 8 * hh;
                    int col = wn0 + ni * 8 + 2 * tig;
                    uG[r * PS + col / 2] = pack_bf2(
                        acc[mi][ni][2 * hh] * fsc[mi][hh],
                        acc[mi][ni][2 * hh + 1] * fsc[mi][hh]);
                }
        __syncthreads();

        {
            const unsigned short* hV = (const unsigned short*)(smem + OFF_V + buf * 18432);
            #pragma unroll
            for (int ks = 0; ks < 8; ks++) {
                unsigned af[4][4], bf[2][2];
                #pragma unroll
                for (int mi = 0; mi < 4; mi++) {
                    int m = wm0 + mi * 16 + g;
                    af[mi][0] = uG[m * PS + ks * 8 + tig];
                    af[mi][1] = uG[(m + 8) * PS + ks * 8 + tig];
                    af[mi][2] = uG[m * PS + ks * 8 + tig + 4];
                    af[mi][3] = uG[(m + 8) * PS + ks * 8 + tig + 4];
                }
                #pragma unroll
                for (int ni2 = 0; ni2 < 2; ni2++) {
                    int n = wn0p + ni2 * 8 + g;
                    unsigned lo0 = hV[(ks * 16 + 2 * tig) * 72 + n];
                    unsigned hi0 = hV[(ks * 16 + 2 * tig + 1) * 72 + n];
                    unsigned lo1 = hV[(ks * 16 + 2 * tig + 8) * 72 + n];
                    unsigned hi1 = hV[(ks * 16 + 2 * tig + 9) * 72 + n];
                    bf[ni2][0] = lo0 | (hi0 << 16);
                    bf[ni2][1] = lo1 | (hi1 << 16);
                }
                #pragma unroll
                for (int mi = 0; mi < 4; mi++)
                    #pragma unroll
                    for (int ni2 = 0; ni2 < 2; ni2++)
                        mma16(o[mi][ni2], af[mi], bf[ni2]);
            }
        }
        buf ^= 1;
    }

    #pragma unroll
    for (int mi = 0; mi < 4; mi++)
        #pragma unroll
        for (int ni2 = 0; ni2 < 2; ni2++)
            #pragma unroll
            for (int hh = 0; hh < 2; hh++) {
                int r = wm0 + mi * 16 + g + 8 * hh;
                int d = wn0p + ni2 * 8 + 2 * tig;
                float inv = 1.0f / lrun[mi][hh];
                *(float2*)&Om[((size_t)b * QLEN + q0 + r) * HD + h * DH + d] =
                    make_float2(o[mi][ni2][2 * hh] * inv, o[mi][ni2][2 * hh + 1] * inv);
            }
}

// ---------------- out = LayerNorm(a + b), rows of EE ----------------
__global__ __launch_bounds__(256) void add_ln_kernel(
    const float* __restrict__ A, const float* __restrict__ Bv,
    const float* __restrict__ gamma, const float* __restrict__ beta,
    float* __restrict__ out)
{
    __shared__ float red[256];
    const size_t row = blockIdx.x;
    const int t = threadIdx.x;
    float4 va = ((const float4*)(A + row * EE))[t];
    float4 vb = ((const float4*)(Bv + row * EE))[t];
    float4 v = make_float4(va.x + vb.x, va.y + vb.y, va.z + vb.z, va.w + vb.w);

    red[t] = v.x + v.y + v.z + v.w; __syncthreads();
    for (int s = 128; s > 0; s >>= 1) { if (t < s) red[t] += red[t + s]; __syncthreads(); }
    const float mean = red[0] * (1.0f / EE); __syncthreads();

    float dx = v.x - mean, dy = v.y - mean, dz = v.z - mean, dw = v.w - mean;
    red[t] = dx * dx + dy * dy + dz * dz + dw * dw; __syncthreads();
    for (int s = 128; s > 0; s >>= 1) { if (t < s) red[t] += red[t + s]; __syncthreads(); }
    const float inv = rsqrtf(red[0] * (1.0f / EE) + 1e-3f);

    float4 gm = ((const float4*)gamma)[t];
    float4 bt = ((const float4*)beta)[t];
    float4 o;
    o.x = dx * inv * gm.x + bt.x; o.y = dy * inv * gm.y + bt.y;
    o.z = dz * inv * gm.z + bt.z; o.w = dw * inv * gm.w + bt.w;
    ((float4*)(out + row * EE))[t] = o;
}

// ---------------- launch ----------------
extern "C" void kernel_launch(void* const* d_in, const int* in_sizes, int n_in,
                              void* d_out, int out_size)
{
    const float* w      = (const float*)d_in[0];
    const float* r      = (const float*)d_in[1];
    const float* member = (const float*)d_in[2];
    const float* Wq  = (const float*)d_in[4];
    const float* Wk  = (const float*)d_in[5];
    const float* Wv  = (const float*)d_in[6];
    const float* Wr  = (const float*)d_in[7];
    const float* Wo  = (const float*)d_in[8];
    const float* rwb = (const float*)d_in[9];
    const float* rrb = (const float*)d_in[10];
    const float* ln1g = (const float*)d_in[11];
    const float* ln1b = (const float*)d_in[12];
    const float* W1  = (const float*)d_in[13];
    const float* W2  = (const float*)d_in[14];
    const float* ln2g = (const float*)d_in[15];
    const float* ln2b = (const float*)d_in[16];
    float* out = (float*)d_out;

    static float *p_cat = nullptr, *p_q, *p_k, *p_v, *p_r,
                 *p_att, *p_o, *p_x, *p_ffn, *p_y;
    if (!p_cat) {
        cudaGetSymbolAddress((void**)&p_cat, g_cat);
        cudaGetSymbolAddress((void**)&p_q,   g_q);
        cudaGetSymbolAddress((void**)&p_k,   g_k);
        cudaGetSymbolAddress((void**)&p_v,   g_v);
        cudaGetSymbolAddress((void**)&p_r,   g_r);
        cudaGetSymbolAddress((void**)&p_att, g_att);
        cudaGetSymbolAddress((void**)&p_o,   g_o);
        cudaGetSymbolAddress((void**)&p_x,   g_x);
        cudaGetSymbolAddress((void**)&p_ffn, g_ffn);
        cudaGetSymbolAddress((void**)&p_y,   g_y);
        cudaFuncSetAttribute(flash_attn, cudaFuncAttributeMaxDynamicSharedMemorySize, FA_SMEM);
    }

    // 1. cat (bf16 output)
    copy_cat_kernel<<<(BB * KLEN * EE / 4) / 256, 256>>>(
        (const float4*)w, (const float4*)member, (uint2*)p_cat);

    // 2. projections: bf16 compute, bf16 A (cat), bf16 out
    //    Wq reads the w rows inside cat via QMODE row offset.
    gemm_h<1,1,1,0,1><<<dim3(HD / 128, (BB * QLEN) / 128), 256>>>(p_cat, EE, Wq, HD, p_q, HD, EE);
    gemm_h<1,1,1,0,0><<<dim3(HD / 128, (BB * KLEN) / 128), 256>>>(p_cat, EE, Wk, HD, p_k, HD, EE);
    gemm_h<1,1,1,0,0><<<dim3(HD / 128, (BB * KLEN) / 128), 256>>>(p_cat, EE, Wv, HD, p_v, HD, EE);
    gemm_h<1,0,1,0,0><<<dim3(HD / 128, KLEN / 128),        256>>>(r,     EE, Wr, HD, p_r, HD, EE);

    // 3. fused attention
    flash_attn<<<dim3(1, QLEN / 128, BB * HH), 256, FA_SMEM>>>(
        (const __nv_bfloat16*)p_q, (const __nv_bfloat16*)p_k,
        (const __nv_bfloat16*)p_v, (const __nv_bfloat16*)p_r,
        rwb, rrb, p_att);

    // 4. output projection (fp16 compute, f32 out) + LN1
    gemm_h<0,0,0,0,0><<<dim3(EE / 128, (BB * QLEN) / 128), 256>>>(p_att, HD, Wo, EE, p_o, EE, HD);
    add_ln_kernel<<<BB * QLEN, 256>>>(w, p_o, ln1g, ln1b, p_x);

    // 5. FFN (fp16 compute) + LN2 -> out
    gemm_h<0,0,0,1,0><<<dim3(FF / 128, (BB * QLEN) / 128), 256>>>(p_x,   EE, W1, FF, p_ffn, FF, EE);
    gemm_h<0,0,0,0,0><<<dim3(EE / 128, (BB * QLEN) / 128), 256>>>(p_ffn, FF, W2, EE, p_y,   EE, FF);
    add_ln_kernel<<<BB * QLEN, 256>>>(p_y, p_x, ln2g, ln2b, out);
}

// round 12
// speedup vs baseline: 1.5951x; 1.0031x over previous
#include <cuda_runtime.h>
#include <cuda_bf16.h>
#include <cuda_fp16.h>
#include <math.h>

#define BB 2
#define QLEN 1024
#define MLEN 1024
#define KLEN 2048
#define EE 1024
#define HH 16
#define DH 64
#define HD 1024   // HH*DH
#define FF 4096

// ---------------- scratch ----------------
static __device__ float g_cat[(size_t)BB * KLEN * EE / 2];   // bf16
static __device__ float g_q  [(size_t)BB * QLEN * HD];       // bf16 (half used)
static __device__ float g_k  [(size_t)BB * KLEN * HD];       // bf16 (half used)
static __device__ float g_v  [(size_t)BB * KLEN * HD];       // bf16 (half used)
static __device__ float g_r  [(size_t)KLEN * HD];            // bf16 (half used)
static __device__ float g_att[(size_t)BB * QLEN * HD / 2];   // fp16
static __device__ float g_o  [(size_t)BB * QLEN * EE];
static __device__ float g_x  [(size_t)BB * QLEN * EE];
static __device__ float g_ffn[(size_t)BB * QLEN * FF / 2];   // fp16
static __device__ float g_y  [(size_t)BB * QLEN * EE];

// ---------------- helpers ----------------
__device__ __forceinline__ unsigned pack_bf2(float lo, float hi) {
    unsigned u; asm("cvt.rn.bf16x2.f32 %0, %1, %2;" : "=r"(u) : "f"(hi), "f"(lo)); return u;
}
template<int BF>
__device__ __forceinline__ unsigned pack2(float lo, float hi) {
    unsigned u;
    if (BF) asm("cvt.rn.bf16x2.f32 %0, %1, %2;" : "=r"(u) : "f"(hi), "f"(lo));
    else    asm("cvt.rn.f16x2.f32 %0, %1, %2;"  : "=r"(u) : "f"(hi), "f"(lo));
    return u;
}
__device__ __forceinline__ void mma16(float* c, const unsigned* a, const unsigned* b) {
    asm volatile("mma.sync.aligned.m16n8k16.row.col.f32.bf16.bf16.f32 "
        "{%0,%1,%2,%3}, {%4,%5,%6,%7}, {%8,%9}, {%0,%1,%2,%3};\n"
        : "+f"(c[0]), "+f"(c[1]), "+f"(c[2]), "+f"(c[3])
        : "r"(a[0]), "r"(a[1]), "r"(a[2]), "r"(a[3]), "r"(b[0]), "r"(b[1]));
}
template<int BF>
__device__ __forceinline__ void mmah(float* c, const unsigned* a, const unsigned* b) {
    if (BF)
        asm volatile("mma.sync.aligned.m16n8k16.row.col.f32.bf16.bf16.f32 "
            "{%0,%1,%2,%3}, {%4,%5,%6,%7}, {%8,%9}, {%0,%1,%2,%3};\n"
            : "+f"(c[0]), "+f"(c[1]), "+f"(c[2]), "+f"(c[3])
            : "r"(a[0]), "r"(a[1]), "r"(a[2]), "r"(a[3]), "r"(b[0]), "r"(b[1]));
    else
        asm volatile("mma.sync.aligned.m16n8k16.row.col.f32.f16.f16.f32 "
            "{%0,%1,%2,%3}, {%4,%5,%6,%7}, {%8,%9}, {%0,%1,%2,%3};\n"
            : "+f"(c[0]), "+f"(c[1]), "+f"(c[2]), "+f"(c[3])
            : "r"(a[0]), "r"(a[1]), "r"(a[2]), "r"(a[3]), "r"(b[0]), "r"(b[1]));
}
__device__ __forceinline__ void ldsm4(unsigned* r, unsigned saddr) {
    asm volatile("ldmatrix.sync.aligned.m8n8.x4.shared.b16 {%0,%1,%2,%3}, [%4];"
        : "=r"(r[0]), "=r"(r[1]), "=r"(r[2]), "=r"(r[3]) : "r"(saddr));
}
__device__ __forceinline__ void ldsm4t(unsigned* r, unsigned saddr) {
    asm volatile("ldmatrix.sync.aligned.m8n8.x4.trans.shared.b16 {%0,%1,%2,%3}, [%4];"
        : "=r"(r[0]), "=r"(r[1]), "=r"(r[2]), "=r"(r[3]) : "r"(saddr));
}
__device__ __forceinline__ void cpa16(unsigned saddr, const void* g) {
    asm volatile("cp.async.cg.shared.global [%0], [%1], 16;" :: "r"(saddr), "l"(g));
}
__device__ __forceinline__ void cpa_commit() { asm volatile("cp.async.commit_group;"); }
__device__ __forceinline__ void cpa_waitall() { asm volatile("cp.async.wait_group 0;"); }

// ---------------- cat = concat(member, w), bf16 output ----------------
__global__ __launch_bounds__(256) void copy_cat_kernel(
    const float4* __restrict__ w, const float4* __restrict__ member, uint2* __restrict__ cat)
{
    size_t i = (size_t)blockIdx.x * 256 + threadIdx.x;
    int e4 = (int)(i % (EE / 4));
    size_t t2 = i / (EE / 4);
    int kl = (int)(t2 % KLEN);
    int b  = (int)(t2 / KLEN);
    float4 v;
    if (kl < MLEN) v = member[((size_t)b * MLEN + kl) * (EE / 4) + e4];
    else           v = w[((size_t)b * QLEN + (kl - MLEN)) * (EE / 4) + e4];
    cat[i] = make_uint2(pack_bf2(v.x, v.y), pack_bf2(v.z, v.w));
}

// ================= half-precision GEMM (ldmatrix consumers) =================
// BF: 1=bf16 compute, 0=fp16. AH: A already 16-bit (matching BF type).
// OUT: 0=f32, 1=bf16, 2=fp16. RELU fused. QMODE: w-rows inside cat layout.
#define ABW 20
#define BBW 68
template<int BF, int AH, int OUT, int RELU, int QMODE>
__global__ __launch_bounds__(256, 2) void gemm_h(
    const void* __restrict__ Ap, int lda, const float* __restrict__ B, int ldb,
    float* __restrict__ C, int ldc, int K)
{
    __shared__ __align__(16) unsigned As[2][128 * ABW];
    __shared__ __align__(16) unsigned Bs[2][32 * BBW];

    const int t = threadIdx.x;
    const int lane = t & 31, warp = t >> 5;
    const int g = lane >> 2, tig = lane & 3;
    const int wm0 = (warp >> 2) * 64, wn0 = (warp & 3) * 32;
    const int m0 = blockIdx.y * 128, n0 = blockIdx.x * 128;
    const int moff = QMODE ? (((m0 >> 10) + 1) << 10) : 0;

    const float* Af = (const float*)Ap;
    const unsigned short* Ah = (const unsigned short*)Ap;

    const int ar = t >> 2, ac = t & 3;
    const int br = t >> 3, bc = t & 7;

    const int l15 = lane & 15, lh = lane >> 4;
    const int bkl = (lane & 7) + 8 * ((lane >> 3) & 1);
    const unsigned sA0 = (unsigned)__cvta_generic_to_shared(&As[0][0]);
    const unsigned sB0 = (unsigned)__cvta_generic_to_shared(&Bs[0][0]);

    float c[4][4][4] = {};

    auto loadA = [&](int k0, unsigned* dst8) {
        #pragma unroll
        for (int p = 0; p < 2; p++) {
            size_t row = (size_t)(m0 + moff + ar + 64 * p);
            if (AH) {
                uint4 v = *(const uint4*)&Ah[row * lda + k0 + ac * 8];
                dst8[4*p+0] = v.x; dst8[4*p+1] = v.y; dst8[4*p+2] = v.z; dst8[4*p+3] = v.w;
            } else {
                const float* src = Af + row * lda + k0 + ac * 8;
                float4 f0 = ((const float4*)src)[0], f1 = ((const float4*)src)[1];
                dst8[4*p+0] = pack2<BF>(f0.x, f0.y); dst8[4*p+1] = pack2<BF>(f0.z, f0.w);
                dst8[4*p+2] = pack2<BF>(f1.x, f1.y); dst8[4*p+3] = pack2<BF>(f1.z, f1.w);
            }
        }
    };
    auto loadB = [&](int k0, unsigned* dst8) {
        const float* bsrc = B + (size_t)(k0 + br) * ldb + n0 + bc * 16;
        float4 f0 = ((const float4*)bsrc)[0], f1 = ((const float4*)bsrc)[1];
        float4 f2 = ((const float4*)bsrc)[2], f3 = ((const float4*)bsrc)[3];
        dst8[0] = pack2<BF>(f0.x, f0.y); dst8[1] = pack2<BF>(f0.z, f0.w);
        dst8[2] = pack2<BF>(f1.x, f1.y); dst8[3] = pack2<BF>(f1.z, f1.w);
        dst8[4] = pack2<BF>(f2.x, f2.y); dst8[5] = pack2<BF>(f2.z, f2.w);
        dst8[6] = pack2<BF>(f3.x, f3.y); dst8[7] = pack2<BF>(f3.z, f3.w);
    };

    {
        unsigned sa[8], sbv[8];
        loadA(0, sa); loadB(0, sbv);
        *(uint4*)&As[0][ar * ABW + ac * 4]        = make_uint4(sa[0], sa[1], sa[2], sa[3]);
        *(uint4*)&As[0][(ar + 64) * ABW + ac * 4] = make_uint4(sa[4], sa[5], sa[6], sa[7]);
        *(uint4*)&Bs[0][br * BBW + bc * 8]        = make_uint4(sbv[0], sbv[1], sbv[2], sbv[3]);
        *(uint4*)&Bs[0][br * BBW + bc * 8 + 4]    = make_uint4(sbv[4], sbv[5], sbv[6], sbv[7]);
    }
    __syncthreads();

    const int nk = K / 32;
    int buf = 0;
    for (int kt = 0; kt < nk; kt++) {
        unsigned sa[8], sbv[8];
        if (kt + 1 < nk) { loadA((kt + 1) * 32, sa); loadB((kt + 1) * 32, sbv); }

        const unsigned sAb = sA0 + buf * (128 * ABW * 4);
        const unsigned sBb = sB0 + buf * (32 * BBW * 4);
        #pragma unroll
        for (int ksx = 0; ksx < 2; ksx++) {
            unsigned af[4][4];
            #pragma unroll
            for (int mi = 0; mi < 4; mi++)
                ldsm4(af[mi], sAb + (((wm0 + mi * 16 + l15) * ABW) + ksx * 8 + lh * 4) * 4);
            #pragma unroll
            for (int nb = 0; nb < 2; nb++) {
                unsigned br4[4];
                ldsm4t(br4, sBb + ((ksx * 16 + bkl) * BBW + (wn0 >> 1) + nb * 8 + 4 * lh) * 4);
                #pragma unroll
                for (int mi = 0; mi < 4; mi++) {
                    mmah<BF>(c[mi][2 * nb],     af[mi], br4);
                    mmah<BF>(c[mi][2 * nb + 1], af[mi], br4 + 2);
                }
            }
        }

        if (kt + 1 < nk) {
            int nb2 = buf ^ 1;
            *(uint4*)&As[nb2][ar * ABW + ac * 4]        = make_uint4(sa[0], sa[1], sa[2], sa[3]);
            *(uint4*)&As[nb2][(ar + 64) * ABW + ac * 4] = make_uint4(sa[4], sa[5], sa[6], sa[7]);
            *(uint4*)&Bs[nb2][br * BBW + bc * 8]        = make_uint4(sbv[0], sbv[1], sbv[2], sbv[3]);
            *(uint4*)&Bs[nb2][br * BBW + bc * 8 + 4]    = make_uint4(sbv[4], sbv[5], sbv[6], sbv[7]);
            __syncthreads();
        }
        buf ^= 1;
    }

    #pragma unroll
    for (int mi = 0; mi < 4; mi++) {
        int row = m0 + wm0 + mi * 16 + g;
        #pragma unroll
        for (int ni = 0; ni < 4; ni++) {
            int col = n0 + wn0 + ni * 8 + 2 * tig;
            float v0 = c[mi][ni][0], v1 = c[mi][ni][1];
            float v2 = c[mi][ni][2], v3 = c[mi][ni][3];
            if (RELU) {
                v0 = fmaxf(v0, 0.f); v1 = fmaxf(v1, 0.f);
                v2 = fmaxf(v2, 0.f); v3 = fmaxf(v3, 0.f);
            }
            if (OUT == 1) {
                unsigned* Cu = (unsigned*)C;
                Cu[((size_t)row * ldc + col) / 2]       = pack_bf2(v0, v1);
                Cu[((size_t)(row + 8) * ldc + col) / 2] = pack_bf2(v2, v3);
            } else if (OUT == 2) {
                unsigned* Cu = (unsigned*)C;
                Cu[((size_t)row * ldc + col) / 2]       = pack2<0>(v0, v1);
                Cu[((size_t)(row + 8) * ldc + col) / 2] = pack2<0>(v2, v3);
            } else {
                *(float2*)&C[(size_t)row * ldc + col]       = make_float2(v0, v1);
                *(float2*)&C[(size_t)(row + 8) * ldc + col] = make_float2(v2, v3);
            }
        }
    }
}

// ================= flash attention, rolling G band =================
// smem: QW 18432 | QR 18432 | K 2x18432 | V 2x18432 | R 2x18432 (halves) |
//       G 2x33792 (128x132 bf16 blocks; P overlays dead low block) | RED 4096
#define QS 36
#define OFF_QW 0
#define OFF_QR 18432
#define OFF_K  36864
#define OFF_V  73728
#define OFF_R  110592
#define OFF_G  147456
#define GBLK   33792
#define OFF_RED 215040
#define FA_SMEM 219136

__global__ __launch_bounds__(256, 1) void flash_attn(
    const __nv_bfloat16* __restrict__ Qb, const __nv_bfloat16* __restrict__ Kb,
    const __nv_bfloat16* __restrict__ Vb, const __nv_bfloat16* __restrict__ Rb,
    const float* __restrict__ rwb, const float* __restrict__ rrb,
    unsigned* __restrict__ Om)   // fp16 output (packed pairs)
{
    extern __shared__ __align__(16) char smem[];
    unsigned*  uQw = (unsigned*)(smem + OFF_QW);
    unsigned*  uQr = (unsigned*)(smem + OFF_QR);
    float* redM = (float*)(smem + OFF_RED);
    float* redS = redM + 512;
    const unsigned sb = (unsigned)__cvta_generic_to_shared(smem);

    const int t = threadIdx.x;
    const int lane = t & 31, warp = t >> 5;
    const int g = lane >> 2, tig = lane & 3;
    const int wm0 = (warp >> 2) * 64;
    const int wn  = warp & 3;
    const int wn0 = wn * 32;
    const int wn0p = wn * 16;

    const int bh = blockIdx.z, b = bh >> 4, h = bh & 15;
    const int q0 = (gridDim.y - 1 - blockIdx.y) * 128;
    const int ntiles = q0 / 128 + 9;

    const __nv_bfloat16* gK = Kb + ((size_t)b * KLEN) * HD + h * DH;
    const __nv_bfloat16* gV = Vb + ((size_t)b * KLEN) * HD + h * DH;
    const __nv_bfloat16* gR = Rb + h * DH;

    // prologue: K/V(0) + full 256-row R band for tile 0
    {
        #pragma unroll
        for (int i = 0; i < 4; i++) {
            int id = t + 256 * i, row = id >> 3, ch = id & 7;
            cpa16(sb + OFF_K + row * 144 + ch * 16, gK + (size_t)row * HD + ch * 8);
            cpa16(sb + OFF_V + row * 144 + ch * 16, gV + (size_t)row * HD + ch * 8);
        }
        cpa_commit();
        int j0 = 0 - q0 + (QLEN - 128);
        #pragma unroll
        for (int i = 0; i < 8; i++) {
            int id = t + 256 * i, row = id >> 3, ch = id & 7;
            int j = j0 + row; if (j > KLEN - 1) j = KLEN - 1;
            cpa16(sb + OFF_R + row * 144 + ch * 16, gR + (size_t)j * HD + ch * 8);
        }
        cpa_commit();
    }

    // Q + biases
    {
        const __nv_bfloat16* qsrc = Qb + ((size_t)b * QLEN + q0) * HD + h * DH;
        int lr = t >> 1, lc0 = (t & 1) * 32;
        #pragma unroll
        for (int i = 0; i < 8; i++) {
            int c = lc0 + i * 4;
            uint2 u = *(const uint2*)&qsrc[(size_t)lr * HD + c];
            __nv_bfloat162 q01 = *(__nv_bfloat162*)&u.x;
            __nv_bfloat162 q23 = *(__nv_bfloat162*)&u.y;
            float4 bw = *(const float4*)&rwb[h * DH + c];
            float4 br = *(const float4*)&rrb[h * DH + c];
            float f0 = __bfloat162float(q01.x), f1 = __bfloat162float(q01.y);
            float f2 = __bfloat162float(q23.x), f3 = __bfloat162float(q23.y);
            uQw[lr * QS + c / 2]     = pack_bf2(f0 + bw.x, f1 + bw.y);
            uQw[lr * QS + c / 2 + 1] = pack_bf2(f2 + bw.z, f3 + bw.w);
            uQr[lr * QS + c / 2]     = pack_bf2(f0 + br.x, f1 + br.y);
            uQr[lr * QS + c / 2 + 1] = pack_bf2(f2 + br.z, f3 + br.w);
        }
    }

    float o[4][2][4] = {};
    float mrun[4][2], lrun[4][2];
    #pragma unroll
    for (int mi = 0; mi < 4; mi++)
        #pragma unroll
        for (int hh = 0; hh < 2; hh++) { mrun[mi][hh] = -INFINITY; lrun[mi][hh] = 0.f; }

    // G block mma: compute 128x128 (Q+rrb)@Rrows^T into dstG (132-bf16 stride)
    auto gblock = [&](const unsigned* uRh, unsigned* uGd) {
        float ga[4][4][4] = {};
        #pragma unroll
        for (int ks = 0; ks < 4; ks++) {
            unsigned af[4][4], bf[4][2];
            #pragma unroll
            for (int mi = 0; mi < 4; mi++) {
                int m = wm0 + mi * 16 + g;
                af[mi][0] = uQr[m * QS + ks * 8 + tig];
                af[mi][1] = uQr[(m + 8) * QS + ks * 8 + tig];
                af[mi][2] = uQr[m * QS + ks * 8 + tig + 4];
                af[mi][3] = uQr[(m + 8) * QS + ks * 8 + tig + 4];
            }
            #pragma unroll
            for (int ni = 0; ni < 4; ni++) {
                int n = wn0 + ni * 8 + g;
                bf[ni][0] = uRh[n * QS + ks * 8 + tig];
                bf[ni][1] = uRh[n * QS + ks * 8 + tig + 4];
            }
            #pragma unroll
            for (int mi = 0; mi < 4; mi++)
                #pragma unroll
                for (int ni = 0; ni < 4; ni++)
                    mma16(ga[mi][ni], af[mi], bf[ni]);
        }
        #pragma unroll
        for (int mi = 0; mi < 4; mi++)
            #pragma unroll
            for (int ni = 0; ni < 4; ni++)
                #pragma unroll
                for (int hh = 0; hh < 2; hh++) {
                    int r = wm0 + mi * 16 + g + 8 * hh;
                    int col = wn0 + ni * 8 + 2 * tig;
                    uGd[r * 66 + col / 2] = pack_bf2(ga[mi][ni][2 * hh], ga[mi][ni][2 * hh + 1]);
                }
    };

    int buf = 0;
    for (int kt = 0; kt < ntiles; kt++) {
        const int k0 = kt * 128;
        cpa_waitall();
        __syncthreads();

        if (kt + 1 < ntiles) {
            const __nv_bfloat16* nK = gK + (size_t)(k0 + 128) * HD;
            const __nv_bfloat16* nV = gV + (size_t)(k0 + 128) * HD;
            unsigned kb = OFF_K + (buf ^ 1) * 18432, vb2 = OFF_V + (buf ^ 1) * 18432;
            #pragma unroll
            for (int i = 0; i < 4; i++) {
                int id = t + 256 * i, row = id >> 3, ch = id & 7;
                cpa16(sb + kb + row * 144 + ch * 16, nK + (size_t)row * HD + ch * 8);
                cpa16(sb + vb2 + row * 144 + ch * 16, nV + (size_t)row * HD + ch * 8);
            }
            cpa_commit();
        }

        // AC
        float acc[4][4][4] = {};
        {
            const unsigned* uK = (const unsigned*)(smem + OFF_K + buf * 18432);
            #pragma unroll
            for (int ks = 0; ks < 4; ks++) {
                unsigned af[4][4], bf[4][2];
                #pragma unroll
                for (int mi = 0; mi < 4; mi++) {
                    int m = wm0 + mi * 16 + g;
                    af[mi][0] = uQw[m * QS + ks * 8 + tig];
                    af[mi][1] = uQw[(m + 8) * QS + ks * 8 + tig];
                    af[mi][2] = uQw[m * QS + ks * 8 + tig + 4];
                    af[mi][3] = uQw[(m + 8) * QS + ks * 8 + tig + 4];
                }
                #pragma unroll
                for (int ni = 0; ni < 4; ni++) {
                    int n = wn0 + ni * 8 + g;
                    bf[ni][0] = uK[n * QS + ks * 8 + tig];
                    bf[ni][1] = uK[n * QS + ks * 8 + tig + 4];
                }
                #pragma unroll
                for (int mi = 0; mi < 4; mi++)
                    #pragma unroll
                    for (int ni = 0; ni < 4; ni++)
                        mma16(acc[mi][ni], af[mi], bf[ni]);
            }
        }

        // G: first tile also computes low block; every tile computes new high block
        if (kt == 0)
            gblock((const unsigned*)(smem + OFF_R), (unsigned*)(smem + OFF_G));
        gblock((const unsigned*)(smem + OFF_R + ((kt + 1) & 1) * 18432),
               (unsigned*)(smem + OFF_G + ((kt + 1) & 1) * GBLK));
        __syncthreads();   // G visible; R consumed

        // prefetch R high rows for next tile into the half just freed
        if (kt + 1 < ntiles) {
            int jb = (k0 + 128) - q0 + (QLEN - 128) + 128;
            unsigned rb = OFF_R + (kt & 1) * 18432;
            #pragma unroll
            for (int i = 0; i < 4; i++) {
                int id = t + 256 * i, row = id >> 3, ch = id & 7;
                int j = jb + row; if (j > KLEN - 1) j = KLEN - 1;
                cpa16(sb + rb + row * 144 + ch * 16, gR + (size_t)j * HD + ch * 8);
            }
            cpa_commit();
        }

        // gather shifted BD from the two G blocks + mask + scale
        {
            const __nv_bfloat16* hGL = (const __nv_bfloat16*)(smem + OFF_G + (kt & 1) * GBLK);
            const __nv_bfloat16* hGH = (const __nv_bfloat16*)(smem + OFF_G + ((kt + 1) & 1) * GBLK);
            #pragma unroll
            for (int mi = 0; mi < 4; mi++)
                #pragma unroll
                for (int ni = 0; ni < 4; ni++)
                    #pragma unroll
                    for (int hh = 0; hh < 2; hh++)
                        #pragma unroll
                        for (int e = 0; e < 2; e++) {
                            int r = wm0 + mi * 16 + g + 8 * hh;
                            int col = wn0 + ni * 8 + 2 * tig + e;
                            int c = col - r + 127;
                            float bd = __bfloat162float(
                                (c < 128) ? hGL[r * 132 + c] : hGH[r * 132 + (c - 128)]);
                            float s = acc[mi][ni][2 * hh + e] + bd;
                            acc[mi][ni][2 * hh + e] =
                                ((k0 + col) <= (q0 + r) + MLEN) ? s * 0.03125f : -1e30f;
                        }
        }

        // warp-level softmax stats
        float mw[4][2];
        #pragma unroll
        for (int mi = 0; mi < 4; mi++)
            #pragma unroll
            for (int hh = 0; hh < 2; hh++) {
                float m8 = -INFINITY;
                #pragma unroll
                for (int ni = 0; ni < 4; ni++)
                    m8 = fmaxf(m8, fmaxf(acc[mi][ni][2 * hh], acc[mi][ni][2 * hh + 1]));
                m8 = fmaxf(m8, __shfl_xor_sync(0xffffffffu, m8, 1));
                m8 = fmaxf(m8, __shfl_xor_sync(0xffffffffu, m8, 2));
                mw[mi][hh] = m8;
                float sw = 0.f;
                #pragma unroll
                for (int ni = 0; ni < 4; ni++)
                    #pragma unroll
                    for (int e = 0; e < 2; e++) {
                        float p = __expf(acc[mi][ni][2 * hh + e] - m8);
                        acc[mi][ni][2 * hh + e] = p;
                        sw += p;
                    }
                sw += __shfl_xor_sync(0xffffffffu, sw, 1);
                sw += __shfl_xor_sync(0xffffffffu, sw, 2);
                if (tig == 0) {
                    int r = wm0 + mi * 16 + g + 8 * hh;
                    redM[wn * 128 + r] = m8;
                    redS[wn * 128 + r] = sw;
                }
            }
        __syncthreads();

        // combine, rescale, write P (overlays dead low G block)
        unsigned* uP = (unsigned*)(smem + OFF_G + (kt & 1) * GBLK);
        float fsc[4][2];
        #pragma unroll
        for (int mi = 0; mi < 4; mi++)
            #pragma unroll
            for (int hh = 0; hh < 2; hh++) {
                int r = wm0 + mi * 16 + g + 8 * hh;
                float m0v = redM[r], m1v = redM[128 + r], m2v = redM[256 + r], m3v = redM[384 + r];
                float mnew = fmaxf(mrun[mi][hh], fmaxf(fmaxf(m0v, m1v), fmaxf(m2v, m3v)));
                float ladd = redS[r] * __expf(m0v - mnew) + redS[128 + r] * __expf(m1v - mnew)
                           + redS[256 + r] * __expf(m2v - mnew) + redS[384 + r] * __expf(m3v - mnew);
                float alpha = __expf(mrun[mi][hh] - mnew);
                lrun[mi][hh] = lrun[mi][hh] * alpha + ladd;
                mrun[mi][hh] = mnew;
                fsc[mi][hh] = __expf(mw[mi][hh] - mnew);
                #pragma unroll
                for (int ni2 = 0; ni2 < 2; ni2++) {
                    o[mi][ni2][2 * hh]     *= alpha;
                    o[mi][ni2][2 * hh + 1] *= alpha;
                }
            }
        #pragma unroll
        for (int mi = 0; mi < 4; mi++)
            #pragma unroll
            for (int ni = 0; ni < 4; ni++)
                #pragma unroll
                for (int hh = 0; hh < 2; hh++) {
                    int r = wm0 + mi * 16 + g + 8 * hh;
                    int col = wn0 + ni * 8 + 2 * tig;
                    uP[r * 66 + col / 2] = pack_bf2(
                        acc[mi][ni][2 * hh] * fsc[mi][hh],
                        acc[mi][ni][2 * hh + 1] * fsc[mi][hh]);
                }
        __syncthreads();

        // PV
        {
            const unsigned short* hV = (const unsigned short*)(smem + OFF_V + buf * 18432);
            #pragma unroll
            for (int ks = 0; ks < 8; ks++) {
                unsigned af[4][4], bf[2][2];
                #pragma unroll
                for (int mi = 0; mi < 4; mi++) {
                    int m = wm0 + mi * 16 + g;
                    af[mi][0] = uP[m * 66 + ks * 8 + tig];
                    af[mi][1] = uP[(m + 8) * 66 + ks * 8 + tig];
                    af[mi][2] = uP[m * 66 + ks * 8 + tig + 4];
                    af[mi][3] = uP[(m + 8) * 66 + ks * 8 + tig + 4];
                }
                #pragma unroll
                for (int ni2 = 0; ni2 < 2; ni2++) {
                    int n = wn0p + ni2 * 8 + g;
                    unsigned lo0 = hV[(ks * 16 + 2 * tig) * 72 + n];
                    unsigned hi0 = hV[(ks * 16 + 2 * tig + 1) * 72 + n];
                    unsigned lo1 = hV[(ks * 16 + 2 * tig + 8) * 72 + n];
                    unsigned hi1 = hV[(ks * 16 + 2 * tig + 9) * 72 + n];
                    bf[ni2][0] = lo0 | (hi0 << 16);
                    bf[ni2][1] = lo1 | (hi1 << 16);
                }
                #pragma unroll
                for (int mi = 0; mi < 4; mi++)
                    #pragma unroll
                    for (int ni2 = 0; ni2 < 2; ni2++)
                        mma16(o[mi][ni2], af[mi], bf[ni2]);
            }
        }
        buf ^= 1;
    }

    // epilogue: O /= l, write fp16
    #pragma unroll
    for (int mi = 0; mi < 4; mi++)
        #pragma unroll
        for (int ni2 = 0; ni2 < 2; ni2++)
            #pragma unroll
            for (int hh = 0; hh < 2; hh++) {
                int r = wm0 + mi * 16 + g + 8 * hh;
                int d = wn0p + ni2 * 8 + 2 * tig;
                float inv = 1.0f / lrun[mi][hh];
                Om[(((size_t)b * QLEN + q0 + r) * HD + h * DH + d) / 2] =
                    pack2<0>(o[mi][ni2][2 * hh] * inv, o[mi][ni2][2 * hh + 1] * inv);
            }
}

// ---------------- out = LayerNorm(a + b), rows of EE ----------------
__global__ __launch_bounds__(256) void add_ln_kernel(
    const float* __restrict__ A, const float* __restrict__ Bv,
    const float* __restrict__ gamma, const float* __restrict__ beta,
    float* __restrict__ out)
{
    __shared__ float red[256];
    const size_t row = blockIdx.x;
    const int t = threadIdx.x;
    float4 va = ((const float4*)(A + row * EE))[t];
    float4 vb = ((const float4*)(Bv + row * EE))[t];
    float4 v = make_float4(va.x + vb.x, va.y + vb.y, va.z + vb.z, va.w + vb.w);

    red[t] = v.x + v.y + v.z + v.w; __syncthreads();
    for (int s = 128; s > 0; s >>= 1) { if (t < s) red[t] += red[t + s]; __syncthreads(); }
    const float mean = red[0] * (1.0f / EE); __syncthreads();

    float dx = v.x - mean, dy = v.y - mean, dz = v.z - mean, dw = v.w - mean;
    red[t] = dx * dx + dy * dy + dz * dz + dw * dw; __syncthreads();
    for (int s = 128; s > 0; s >>= 1) { if (t < s) red[t] += red[t + s]; __syncthreads(); }
    const float inv = rsqrtf(red[0] * (1.0f / EE) + 1e-3f);

    float4 gm = ((const float4*)gamma)[t];
    float4 bt = ((const float4*)beta)[t];
    float4 o;
    o.x = dx * inv * gm.x + bt.x; o.y = dy * inv * gm.y + bt.y;
    o.z = dz * inv * gm.z + bt.z; o.w = dw * inv * gm.w + bt.w;
    ((float4*)(out + row * EE))[t] = o;
}

// ---------------- launch ----------------
extern "C" void kernel_launch(void* const* d_in, const int* in_sizes, int n_in,
                              void* d_out, int out_size)
{
    const float* w      = (const float*)d_in[0];
    const float* r      = (const float*)d_in[1];
    const float* member = (const float*)d_in[2];
    const float* Wq  = (const float*)d_in[4];
    const float* Wk  = (const float*)d_in[5];
    const float* Wv  = (const float*)d_in[6];
    const float* Wr  = (const float*)d_in[7];
    const float* Wo  = (const float*)d_in[8];
    const float* rwb = (const float*)d_in[9];
    const float* rrb = (const float*)d_in[10];
    const float* ln1g = (const float*)d_in[11];
    const float* ln1b = (const float*)d_in[12];
    const float* W1  = (const float*)d_in[13];
    const float* W2  = (const float*)d_in[14];
    const float* ln2g = (const float*)d_in[15];
    const float* ln2b = (const float*)d_in[16];
    float* out = (float*)d_out;

    static float *p_cat = nullptr, *p_q, *p_k, *p_v, *p_r,
                 *p_att, *p_o, *p_x, *p_ffn, *p_y;
    if (!p_cat) {
        cudaGetSymbolAddress((void**)&p_cat, g_cat);
        cudaGetSymbolAddress((void**)&p_q,   g_q);
        cudaGetSymbolAddress((void**)&p_k,   g_k);
        cudaGetSymbolAddress((void**)&p_v,   g_v);
        cudaGetSymbolAddress((void**)&p_r,   g_r);
        cudaGetSymbolAddress((void**)&p_att, g_att);
        cudaGetSymbolAddress((void**)&p_o,   g_o);
        cudaGetSymbolAddress((void**)&p_x,   g_x);
        cudaGetSymbolAddress((void**)&p_ffn, g_ffn);
        cudaGetSymbolAddress((void**)&p_y,   g_y);
        cudaFuncSetAttribute(flash_attn, cudaFuncAttributeMaxDynamicSharedMemorySize, FA_SMEM);
    }

    // 1. cat (bf16)
    copy_cat_kernel<<<(BB * KLEN * EE / 4) / 256, 256>>>(
        (const float4*)w, (const float4*)member, (uint2*)p_cat);

    // 2. projections: bf16 compute, bf16 out
    gemm_h<1,1,1,0,1><<<dim3(HD / 128, (BB * QLEN) / 128), 256>>>(p_cat, EE, Wq, HD, p_q, HD, EE);
    gemm_h<1,1,1,0,0><<<dim3(HD / 128, (BB * KLEN) / 128), 256>>>(p_cat, EE, Wk, HD, p_k, HD, EE);
    gemm_h<1,1,1,0,0><<<dim3(HD / 128, (BB * KLEN) / 128), 256>>>(p_cat, EE, Wv, HD, p_v, HD, EE);
    gemm_h<1,0,1,0,0><<<dim3(HD / 128, KLEN / 128),        256>>>(r,     EE, Wr, HD, p_r, HD, EE);

    // 3. fused attention (fp16 O out)
    flash_attn<<<dim3(1, QLEN / 128, BB * HH), 256, FA_SMEM>>>(
        (const __nv_bfloat16*)p_q, (const __nv_bfloat16*)p_k,
        (const __nv_bfloat16*)p_v, (const __nv_bfloat16*)p_r,
        rwb, rrb, (unsigned*)p_att);

    // 4. output projection (fp16 compute, fp16 A, f32 out) + LN1
    gemm_h<0,1,0,0,0><<<dim3(EE / 128, (BB * QLEN) / 128), 256>>>(p_att, HD, Wo, EE, p_o, EE, HD);
    add_ln_kernel<<<BB * QLEN, 256>>>(w, p_o, ln1g, ln1b, p_x);

    // 5. FFN (fp16 compute, fp16 intermediate) + LN2 -> out
    gemm_h<0,0,2,1,0><<<dim3(FF / 128, (BB * QLEN) / 128), 256>>>(p_x,   EE, W1, FF, p_ffn, FF, EE);
    gemm_h<0,1,0,0,0><<<dim3(EE / 128, (BB * QLEN) / 128), 256>>>(p_ffn, FF, W2, EE, p_y,   EE, FF);
    add_ln_kernel<<<BB * QLEN, 256>>>(p_y, p_x, ln2g, ln2b, out);
}

// round 14
// speedup vs baseline: 1.6509x; 1.0349x over previous
#include <cuda_runtime.h>
#include <cuda_bf16.h>
#include <cuda_fp16.h>
#include <math.h>

#define BB 2
#define QLEN 1024
#define MLEN 1024
#define KLEN 2048
#define EE 1024
#define HH 16
#define DH 64
#define HD 1024   // HH*DH
#define FF 4096

// ---------------- scratch ----------------
static __device__ float g_cat[(size_t)BB * KLEN * EE / 2];   // bf16
static __device__ float g_q  [(size_t)BB * QLEN * HD];       // bf16 (half used)
static __device__ float g_k  [(size_t)BB * KLEN * HD];       // bf16 (half used)
static __device__ float g_v  [(size_t)BB * KLEN * HD];       // bf16 (half used)
static __device__ float g_r  [(size_t)KLEN * HD];            // bf16 (half used)
static __device__ float g_att[(size_t)BB * QLEN * HD / 2];   // fp16
static __device__ float g_o  [(size_t)BB * QLEN * EE];
static __device__ float g_x  [(size_t)BB * QLEN * EE];
static __device__ float g_ffn[(size_t)BB * QLEN * FF / 2];   // fp16
static __device__ float g_y  [(size_t)BB * QLEN * EE];

// ---------------- helpers ----------------
__device__ __forceinline__ unsigned pack_bf2(float lo, float hi) {
    unsigned u; asm("cvt.rn.bf16x2.f32 %0, %1, %2;" : "=r"(u) : "f"(hi), "f"(lo)); return u;
}
template<int BF>
__device__ __forceinline__ unsigned pack2(float lo, float hi) {
    unsigned u;
    if (BF) asm("cvt.rn.bf16x2.f32 %0, %1, %2;" : "=r"(u) : "f"(hi), "f"(lo));
    else    asm("cvt.rn.f16x2.f32 %0, %1, %2;"  : "=r"(u) : "f"(hi), "f"(lo));
    return u;
}
__device__ __forceinline__ void mma16(float* c, const unsigned* a, const unsigned* b) {
    asm volatile("mma.sync.aligned.m16n8k16.row.col.f32.bf16.bf16.f32 "
        "{%0,%1,%2,%3}, {%4,%5,%6,%7}, {%8,%9}, {%0,%1,%2,%3};\n"
        : "+f"(c[0]), "+f"(c[1]), "+f"(c[2]), "+f"(c[3])
        : "r"(a[0]), "r"(a[1]), "r"(a[2]), "r"(a[3]), "r"(b[0]), "r"(b[1]));
}
template<int BF>
__device__ __forceinline__ void mmah(float* c, const unsigned* a, const unsigned* b) {
    if (BF)
        asm volatile("mma.sync.aligned.m16n8k16.row.col.f32.bf16.bf16.f32 "
            "{%0,%1,%2,%3}, {%4,%5,%6,%7}, {%8,%9}, {%0,%1,%2,%3};\n"
            : "+f"(c[0]), "+f"(c[1]), "+f"(c[2]), "+f"(c[3])
            : "r"(a[0]), "r"(a[1]), "r"(a[2]), "r"(a[3]), "r"(b[0]), "r"(b[1]));
    else
        asm volatile("mma.sync.aligned.m16n8k16.row.col.f32.f16.f16.f32 "
            "{%0,%1,%2,%3}, {%4,%5,%6,%7}, {%8,%9}, {%0,%1,%2,%3};\n"
            : "+f"(c[0]), "+f"(c[1]), "+f"(c[2]), "+f"(c[3])
            : "r"(a[0]), "r"(a[1]), "r"(a[2]), "r"(a[3]), "r"(b[0]), "r"(b[1]));
}
__device__ __forceinline__ void ldsm4(unsigned* r, unsigned saddr) {
    asm volatile("ldmatrix.sync.aligned.m8n8.x4.shared.b16 {%0,%1,%2,%3}, [%4];"
        : "=r"(r[0]), "=r"(r[1]), "=r"(r[2]), "=r"(r[3]) : "r"(saddr));
}
__device__ __forceinline__ void ldsm4t(unsigned* r, unsigned saddr) {
    asm volatile("ldmatrix.sync.aligned.m8n8.x4.trans.shared.b16 {%0,%1,%2,%3}, [%4];"
        : "=r"(r[0]), "=r"(r[1]), "=r"(r[2]), "=r"(r[3]) : "r"(saddr));
}
__device__ __forceinline__ void cpa16(unsigned saddr, const void* g) {
    asm volatile("cp.async.cg.shared.global [%0], [%1], 16;" :: "r"(saddr), "l"(g));
}
__device__ __forceinline__ void cpa_commit() { asm volatile("cp.async.commit_group;"); }
__device__ __forceinline__ void cpa_waitall() { asm volatile("cp.async.wait_group 0;"); }

// ---------------- cat = concat(member, w), bf16 output ----------------
__global__ __launch_bounds__(256) void copy_cat_kernel(
    const float4* __restrict__ w, const float4* __restrict__ member, uint2* __restrict__ cat)
{
    size_t i = (size_t)blockIdx.x * 256 + threadIdx.x;
    int e4 = (int)(i % (EE / 4));
    size_t t2 = i / (EE / 4);
    int kl = (int)(t2 % KLEN);
    int b  = (int)(t2 / KLEN);
    float4 v;
    if (kl < MLEN) v = member[((size_t)b * MLEN + kl) * (EE / 4) + e4];
    else           v = w[((size_t)b * QLEN + (kl - MLEN)) * (EE / 4) + e4];
    cat[i] = make_uint2(pack_bf2(v.x, v.y), pack_bf2(v.z, v.w));
}

// ================= half-precision GEMM (ldmatrix consumers, proven) =================
#define ABW 20
#define BBW 68
template<int BF, int AH, int OUT, int RELU, int QMODE>
__global__ __launch_bounds__(256, 2) void gemm_h(
    const void* __restrict__ Ap, int lda, const float* __restrict__ B, int ldb,
    float* __restrict__ C, int ldc, int K)
{
    __shared__ __align__(16) unsigned As[2][128 * ABW];
    __shared__ __align__(16) unsigned Bs[2][32 * BBW];

    const int t = threadIdx.x;
    const int lane = t & 31, warp = t >> 5;
    const int g = lane >> 2, tig = lane & 3;
    const int wm0 = (warp >> 2) * 64, wn0 = (warp & 3) * 32;
    const int m0 = blockIdx.y * 128, n0 = blockIdx.x * 128;
    const int moff = QMODE ? (((m0 >> 10) + 1) << 10) : 0;

    const float* Af = (const float*)Ap;
    const unsigned short* Ah = (const unsigned short*)Ap;

    const int ar = t >> 2, ac = t & 3;
    const int br = t >> 3, bc = t & 7;

    const int l15 = lane & 15, lh = lane >> 4;
    const int bkl = (lane & 7) + 8 * ((lane >> 3) & 1);
    const unsigned sA0 = (unsigned)__cvta_generic_to_shared(&As[0][0]);
    const unsigned sB0 = (unsigned)__cvta_generic_to_shared(&Bs[0][0]);

    float c[4][4][4] = {};

    auto loadA = [&](int k0, unsigned* dst8) {
        #pragma unroll
        for (int p = 0; p < 2; p++) {
            size_t row = (size_t)(m0 + moff + ar + 64 * p);
            if (AH) {
                uint4 v = *(const uint4*)&Ah[row * lda + k0 + ac * 8];
                dst8[4*p+0] = v.x; dst8[4*p+1] = v.y; dst8[4*p+2] = v.z; dst8[4*p+3] = v.w;
            } else {
                const float* src = Af + row * lda + k0 + ac * 8;
                float4 f0 = ((const float4*)src)[0], f1 = ((const float4*)src)[1];
                dst8[4*p+0] = pack2<BF>(f0.x, f0.y); dst8[4*p+1] = pack2<BF>(f0.z, f0.w);
                dst8[4*p+2] = pack2<BF>(f1.x, f1.y); dst8[4*p+3] = pack2<BF>(f1.z, f1.w);
            }
        }
    };
    auto loadB = [&](int k0, unsigned* dst8) {
        const float* bsrc = B + (size_t)(k0 + br) * ldb + n0 + bc * 16;
        float4 f0 = ((const float4*)bsrc)[0], f1 = ((const float4*)bsrc)[1];
        float4 f2 = ((const float4*)bsrc)[2], f3 = ((const float4*)bsrc)[3];
        dst8[0] = pack2<BF>(f0.x, f0.y); dst8[1] = pack2<BF>(f0.z, f0.w);
        dst8[2] = pack2<BF>(f1.x, f1.y); dst8[3] = pack2<BF>(f1.z, f1.w);
        dst8[4] = pack2<BF>(f2.x, f2.y); dst8[5] = pack2<BF>(f2.z, f2.w);
        dst8[6] = pack2<BF>(f3.x, f3.y); dst8[7] = pack2<BF>(f3.z, f3.w);
    };

    {
        unsigned sa[8], sbv[8];
        loadA(0, sa); loadB(0, sbv);
        *(uint4*)&As[0][ar * ABW + ac * 4]        = make_uint4(sa[0], sa[1], sa[2], sa[3]);
        *(uint4*)&As[0][(ar + 64) * ABW + ac * 4] = make_uint4(sa[4], sa[5], sa[6], sa[7]);
        *(uint4*)&Bs[0][br * BBW + bc * 8]        = make_uint4(sbv[0], sbv[1], sbv[2], sbv[3]);
        *(uint4*)&Bs[0][br * BBW + bc * 8 + 4]    = make_uint4(sbv[4], sbv[5], sbv[6], sbv[7]);
    }
    __syncthreads();

    const int nk = K / 32;
    int buf = 0;
    for (int kt = 0; kt < nk; kt++) {
        unsigned sa[8], sbv[8];
        if (kt + 1 < nk) { loadA((kt + 1) * 32, sa); loadB((kt + 1) * 32, sbv); }

        const unsigned sAb = sA0 + buf * (128 * ABW * 4);
        const unsigned sBb = sB0 + buf * (32 * BBW * 4);
        #pragma unroll
        for (int ksx = 0; ksx < 2; ksx++) {
            unsigned af[4][4];
            #pragma unroll
            for (int mi = 0; mi < 4; mi++)
                ldsm4(af[mi], sAb + (((wm0 + mi * 16 + l15) * ABW) + ksx * 8 + lh * 4) * 4);
            #pragma unroll
            for (int nb = 0; nb < 2; nb++) {
                unsigned br4[4];
                ldsm4t(br4, sBb + ((ksx * 16 + bkl) * BBW + (wn0 >> 1) + nb * 8 + 4 * lh) * 4);
                #pragma unroll
                for (int mi = 0; mi < 4; mi++) {
                    mmah<BF>(c[mi][2 * nb],     af[mi], br4);
                    mmah<BF>(c[mi][2 * nb + 1], af[mi], br4 + 2);
                }
            }
        }

        if (kt + 1 < nk) {
            int nb2 = buf ^ 1;
            *(uint4*)&As[nb2][ar * ABW + ac * 4]        = make_uint4(sa[0], sa[1], sa[2], sa[3]);
            *(uint4*)&As[nb2][(ar + 64) * ABW + ac * 4] = make_uint4(sa[4], sa[5], sa[6], sa[7]);
            *(uint4*)&Bs[nb2][br * BBW + bc * 8]        = make_uint4(sbv[0], sbv[1], sbv[2], sbv[3]);
            *(uint4*)&Bs[nb2][br * BBW + bc * 8 + 4]    = make_uint4(sbv[4], sbv[5], sbv[6], sbv[7]);
            __syncthreads();
        }
        buf ^= 1;
    }

    #pragma unroll
    for (int mi = 0; mi < 4; mi++) {
        int row = m0 + wm0 + mi * 16 + g;
        #pragma unroll
        for (int ni = 0; ni < 4; ni++) {
            int col = n0 + wn0 + ni * 8 + 2 * tig;
            float v0 = c[mi][ni][0], v1 = c[mi][ni][1];
            float v2 = c[mi][ni][2], v3 = c[mi][ni][3];
            if (RELU) {
                v0 = fmaxf(v0, 0.f); v1 = fmaxf(v1, 0.f);
                v2 = fmaxf(v2, 0.f); v3 = fmaxf(v3, 0.f);
            }
            if (OUT == 1) {
                unsigned* Cu = (unsigned*)C;
                Cu[((size_t)row * ldc + col) / 2]       = pack_bf2(v0, v1);
                Cu[((size_t)(row + 8) * ldc + col) / 2] = pack_bf2(v2, v3);
            } else if (OUT == 2) {
                unsigned* Cu = (unsigned*)C;
                Cu[((size_t)row * ldc + col) / 2]       = pack2<0>(v0, v1);
                Cu[((size_t)(row + 8) * ldc + col) / 2] = pack2<0>(v2, v3);
            } else {
                *(float2*)&C[(size_t)row * ldc + col]       = make_float2(v0, v1);
                *(float2*)&C[(size_t)(row + 8) * ldc + col] = make_float2(v2, v3);
            }
        }
    }
}

// ================= flash attention, rolling G band + ldmatrix consumers =================
// G/P row stride: 68 words (136 bf16) = 272 bytes (16B-aligned for ldmatrix)
#define QS 36
#define GSW 68
#define OFF_QW 0
#define OFF_QR 18432
#define OFF_K  36864
#define OFF_V  73728
#define OFF_R  110592
#define OFF_G  147456
#define GBLK   34816
#define OFF_RED 217088
#define FA_SMEM 221184

__global__ __launch_bounds__(256, 1) void flash_attn(
    const __nv_bfloat16* __restrict__ Qb, const __nv_bfloat16* __restrict__ Kb,
    const __nv_bfloat16* __restrict__ Vb, const __nv_bfloat16* __restrict__ Rb,
    const float* __restrict__ rwb, const float* __restrict__ rrb,
    unsigned* __restrict__ Om)
{
    extern __shared__ __align__(16) char smem[];
    unsigned*  uQw = (unsigned*)(smem + OFF_QW);
    unsigned*  uQr = (unsigned*)(smem + OFF_QR);
    float* redM = (float*)(smem + OFF_RED);
    float* redS = redM + 512;
    const unsigned sb = (unsigned)__cvta_generic_to_shared(smem);

    const int t = threadIdx.x;
    const int lane = t & 31, warp = t >> 5;
    const int g = lane >> 2, tig = lane & 3;
    const int wm0 = (warp >> 2) * 64;
    const int wn  = warp & 3;
    const int wn0 = wn * 32;
    const int wn0p = wn * 16;
    const int l15 = lane & 15, lh = lane >> 4;
    const int bkl = (lane & 7) + 8 * ((lane >> 3) & 1);

    const int bh = blockIdx.z, b = bh >> 4, h = bh & 15;
    const int q0 = (gridDim.y - 1 - blockIdx.y) * 128;
    const int ntiles = q0 / 128 + 9;

    const __nv_bfloat16* gK = Kb + ((size_t)b * KLEN) * HD + h * DH;
    const __nv_bfloat16* gV = Vb + ((size_t)b * KLEN) * HD + h * DH;
    const __nv_bfloat16* gR = Rb + h * DH;

    // prologue: K/V(0) + full 256-row R band
    {
        #pragma unroll
        for (int i = 0; i < 4; i++) {
            int id = t + 256 * i, row = id >> 3, ch = id & 7;
            cpa16(sb + OFF_K + row * 144 + ch * 16, gK + (size_t)row * HD + ch * 8);
            cpa16(sb + OFF_V + row * 144 + ch * 16, gV + (size_t)row * HD + ch * 8);
        }
        cpa_commit();
        int j0 = 0 - q0 + (QLEN - 128);
        #pragma unroll
        for (int i = 0; i < 8; i++) {
            int id = t + 256 * i, row = id >> 3, ch = id & 7;
            int j = j0 + row; if (j > KLEN - 1) j = KLEN - 1;
            cpa16(sb + OFF_R + row * 144 + ch * 16, gR + (size_t)j * HD + ch * 8);
        }
        cpa_commit();
    }

    // Q + biases
    {
        const __nv_bfloat16* qsrc = Qb + ((size_t)b * QLEN + q0) * HD + h * DH;
        int lr = t >> 1, lc0 = (t & 1) * 32;
        #pragma unroll
        for (int i = 0; i < 8; i++) {
            int c = lc0 + i * 4;
            uint2 u = *(const uint2*)&qsrc[(size_t)lr * HD + c];
            __nv_bfloat162 q01 = *(__nv_bfloat162*)&u.x;
            __nv_bfloat162 q23 = *(__nv_bfloat162*)&u.y;
            float4 bw = *(const float4*)&rwb[h * DH + c];
            float4 br = *(const float4*)&rrb[h * DH + c];
            float f0 = __bfloat162float(q01.x), f1 = __bfloat162float(q01.y);
            float f2 = __bfloat162float(q23.x), f3 = __bfloat162float(q23.y);
            uQw[lr * QS + c / 2]     = pack_bf2(f0 + bw.x, f1 + bw.y);
            uQw[lr * QS + c / 2 + 1] = pack_bf2(f2 + bw.z, f3 + bw.w);
            uQr[lr * QS + c / 2]     = pack_bf2(f0 + br.x, f1 + br.y);
            uQr[lr * QS + c / 2 + 1] = pack_bf2(f2 + br.z, f3 + br.w);
        }
    }

    float o[4][2][4] = {};
    float mrun[4][2], lrun[4][2];
    #pragma unroll
    for (int mi = 0; mi < 4; mi++)
        #pragma unroll
        for (int hh = 0; hh < 2; hh++) { mrun[mi][hh] = -INFINITY; lrun[mi][hh] = 0.f; }

    const unsigned sQWb = sb + OFF_QW, sQRb = sb + OFF_QR;

    // QK^T-style 128x128 block (A from saddrA, B rows from saddrB), acc +=
    auto qkblock = [&](unsigned saddrA, unsigned saddrB, float (*acc)[4][4]) {
        #pragma unroll
        for (int ks = 0; ks < 4; ks++) {
            unsigned af[4][4];
            #pragma unroll
            for (int mi = 0; mi < 4; mi++)
                ldsm4(af[mi], saddrA + ((wm0 + mi * 16 + l15) * QS + ks * 8 + lh * 4) * 4);
            unsigned b0[4], b1[4];
            ldsm4(b0, saddrB + ((wn0 + l15) * QS + ks * 8 + lh * 4) * 4);
            ldsm4(b1, saddrB + ((wn0 + 16 + l15) * QS + ks * 8 + lh * 4) * 4);
            unsigned bf[4][2] = {
                {b0[0], b0[2]}, {b0[1], b0[3]}, {b1[0], b1[2]}, {b1[1], b1[3]}};
            #pragma unroll
            for (int mi = 0; mi < 4; mi++)
                #pragma unroll
                for (int ni = 0; ni < 4; ni++)
                    mma16(acc[mi][ni], af[mi], bf[ni]);
        }
    };

    int buf = 0;
    for (int kt = 0; kt < ntiles; kt++) {
        const int k0 = kt * 128;
        cpa_waitall();
        __syncthreads();

        if (kt + 1 < ntiles) {
            const __nv_bfloat16* nK = gK + (size_t)(k0 + 128) * HD;
            const __nv_bfloat16* nV = gV + (size_t)(k0 + 128) * HD;
            unsigned kb = OFF_K + (buf ^ 1) * 18432, vb2 = OFF_V + (buf ^ 1) * 18432;
            #pragma unroll
            for (int i = 0; i < 4; i++) {
                int id = t + 256 * i, row = id >> 3, ch = id & 7;
                cpa16(sb + kb + row * 144 + ch * 16, nK + (size_t)row * HD + ch * 8);
                cpa16(sb + vb2 + row * 144 + ch * 16, nV + (size_t)row * HD + ch * 8);
            }
            cpa_commit();
        }

        // AC
        float acc[4][4][4] = {};
        qkblock(sQWb, sb + OFF_K + buf * 18432, acc);

        // G blocks (rolling band)
        auto gblock = [&](unsigned saddrR, unsigned* uGd) {
            float ga[4][4][4] = {};
            qkblock(sQRb, saddrR, ga);
            #pragma unroll
            for (int mi = 0; mi < 4; mi++)
                #pragma unroll
                for (int ni = 0; ni < 4; ni++)
                    #pragma unroll
                    for (int hh = 0; hh < 2; hh++) {
                        int r = wm0 + mi * 16 + g + 8 * hh;
                        int col = wn0 + ni * 8 + 2 * tig;
                        uGd[r * GSW + col / 2] = pack_bf2(ga[mi][ni][2 * hh], ga[mi][ni][2 * hh + 1]);
                    }
        };
        if (kt == 0)
            gblock(sb + OFF_R, (unsigned*)(smem + OFF_G));
        gblock(sb + OFF_R + ((kt + 1) & 1) * 18432,
               (unsigned*)(smem + OFF_G + ((kt + 1) & 1) * GBLK));
        __syncthreads();

        if (kt + 1 < ntiles) {
            int jb = (k0 + 128) - q0 + (QLEN - 128) + 128;
            unsigned rb = OFF_R + (kt & 1) * 18432;
            #pragma unroll
            for (int i = 0; i < 4; i++) {
                int id = t + 256 * i, row = id >> 3, ch = id & 7;
                int j = jb + row; if (j > KLEN - 1) j = KLEN - 1;
                cpa16(sb + rb + row * 144 + ch * 16, gR + (size_t)j * HD + ch * 8);
            }
            cpa_commit();
        }

        // gather shifted BD + mask + scale
        {
            const __nv_bfloat16* hGL = (const __nv_bfloat16*)(smem + OFF_G + (kt & 1) * GBLK);
            const __nv_bfloat16* hGH = (const __nv_bfloat16*)(smem + OFF_G + ((kt + 1) & 1) * GBLK);
            #pragma unroll
            for (int mi = 0; mi < 4; mi++)
                #pragma unroll
                for (int ni = 0; ni < 4; ni++)
                    #pragma unroll
                    for (int hh = 0; hh < 2; hh++)
                        #pragma unroll
                        for (int e = 0; e < 2; e++) {
                            int r = wm0 + mi * 16 + g + 8 * hh;
                            int col = wn0 + ni * 8 + 2 * tig + e;
                            int c = col - r + 127;
                            float bd = __bfloat162float(
                                (c < 128) ? hGL[r * 136 + c] : hGH[r * 136 + (c - 128)]);
                            float s = acc[mi][ni][2 * hh + e] + bd;
                            acc[mi][ni][2 * hh + e] =
                                ((k0 + col) <= (q0 + r) + MLEN) ? s * 0.03125f : -1e30f;
                        }
        }

        // warp-level softmax stats
        float mw[4][2];
        #pragma unroll
        for (int mi = 0; mi < 4; mi++)
            #pragma unroll
            for (int hh = 0; hh < 2; hh++) {
                float m8 = -INFINITY;
                #pragma unroll
                for (int ni = 0; ni < 4; ni++)
                    m8 = fmaxf(m8, fmaxf(acc[mi][ni][2 * hh], acc[mi][ni][2 * hh + 1]));
                m8 = fmaxf(m8, __shfl_xor_sync(0xffffffffu, m8, 1));
                m8 = fmaxf(m8, __shfl_xor_sync(0xffffffffu, m8, 2));
                mw[mi][hh] = m8;
                float sw = 0.f;
                #pragma unroll
                for (int ni = 0; ni < 4; ni++)
                    #pragma unroll
                    for (int e = 0; e < 2; e++) {
                        float p = __expf(acc[mi][ni][2 * hh + e] - m8);
                        acc[mi][ni][2 * hh + e] = p;
                        sw += p;
                    }
                sw += __shfl_xor_sync(0xffffffffu, sw, 1);
                sw += __shfl_xor_sync(0xffffffffu, sw, 2);
                if (tig == 0) {
                    int r = wm0 + mi * 16 + g + 8 * hh;
                    redM[wn * 128 + r] = m8;
                    redS[wn * 128 + r] = sw;
                }
            }
        __syncthreads();

        // combine, rescale, write P (overlays dead low G block)
        unsigned* uP = (unsigned*)(smem + OFF_G + (kt & 1) * GBLK);
        const unsigned sP = sb + OFF_G + (kt & 1) * GBLK;
        float fsc[4][2];
        #pragma unroll
        for (int mi = 0; mi < 4; mi++)
            #pragma unroll
            for (int hh = 0; hh < 2; hh++) {
                int r = wm0 + mi * 16 + g + 8 * hh;
                float m0v = redM[r], m1v = redM[128 + r], m2v = redM[256 + r], m3v = redM[384 + r];
                float mnew = fmaxf(mrun[mi][hh], fmaxf(fmaxf(m0v, m1v), fmaxf(m2v, m3v)));
                float ladd = redS[r] * __expf(m0v - mnew) + redS[128 + r] * __expf(m1v - mnew)
                           + redS[256 + r] * __expf(m2v - mnew) + redS[384 + r] * __expf(m3v - mnew);
                float alpha = __expf(mrun[mi][hh] - mnew);
                lrun[mi][hh] = lrun[mi][hh] * alpha + ladd;
                mrun[mi][hh] = mnew;
                fsc[mi][hh] = __expf(mw[mi][hh] - mnew);
                #pragma unroll
                for (int ni2 = 0; ni2 < 2; ni2++) {
                    o[mi][ni2][2 * hh]     *= alpha;
                    o[mi][ni2][2 * hh + 1] *= alpha;
                }
            }
        #pragma unroll
        for (int mi = 0; mi < 4; mi++)
            #pragma unroll
            for (int ni = 0; ni < 4; ni++)
                #pragma unroll
                for (int hh = 0; hh < 2; hh++) {
                    int r = wm0 + mi * 16 + g + 8 * hh;
                    int col = wn0 + ni * 8 + 2 * tig;
                    uP[r * GSW + col / 2] = pack_bf2(
                        acc[mi][ni][2 * hh] * fsc[mi][hh],
                        acc[mi][ni][2 * hh + 1] * fsc[mi][hh]);
                }
        __syncthreads();

        // PV: a-frags via ldsm4 on P (stride GSW), b-frags via ldsm4t on V (stride QS)
        {
            const unsigned sV = sb + OFF_V + buf * 18432;
            #pragma unroll
            for (int ks = 0; ks < 8; ks++) {
                unsigned af[4][4];
                #pragma unroll
                for (int mi = 0; mi < 4; mi++)
                    ldsm4(af[mi], sP + ((wm0 + mi * 16 + l15) * GSW + ks * 8 + lh * 4) * 4);
                unsigned bv[4];
                ldsm4t(bv, sV + ((ks * 16 + bkl) * QS + (wn0p >> 1) + 4 * lh) * 4);
                #pragma unroll
                for (int mi = 0; mi < 4; mi++) {
                    mma16(o[mi][0], af[mi], bv);
                    mma16(o[mi][1], af[mi], bv + 2);
                }
            }
        }
        buf ^= 1;
    }

    // epilogue: O /= l, write fp16
    #pragma unroll
    for (int mi = 0; mi < 4; mi++)
        #pragma unroll
        for (int ni2 = 0; ni2 < 2; ni2++)
            #pragma unroll
            for (int hh = 0; hh < 2; hh++) {
                int r = wm0 + mi * 16 + g + 8 * hh;
                int d = wn0p + ni2 * 8 + 2 * tig;
                float inv = 1.0f / lrun[mi][hh];
                Om[(((size_t)b * QLEN + q0 + r) * HD + h * DH + d) / 2] =
                    pack2<0>(o[mi][ni2][2 * hh] * inv, o[mi][ni2][2 * hh + 1] * inv);
            }
}

// ---------------- out = LayerNorm(a + b), rows of EE ----------------
__global__ __launch_bounds__(256) void add_ln_kernel(
    const float* __restrict__ A, const float* __restrict__ Bv,
    const float* __restrict__ gamma, const float* __restrict__ beta,
    float* __restrict__ out)
{
    __shared__ float red[256];
    const size_t row = blockIdx.x;
    const int t = threadIdx.x;
    float4 va = ((const float4*)(A + row * EE))[t];
    float4 vb = ((const float4*)(Bv + row * EE))[t];
    float4 v = make_float4(va.x + vb.x, va.y + vb.y, va.z + vb.z, va.w + vb.w);

    red[t] = v.x + v.y + v.z + v.w; __syncthreads();
    for (int s = 128; s > 0; s >>= 1) { if (t < s) red[t] += red[t + s]; __syncthreads(); }
    const float mean = red[0] * (1.0f / EE); __syncthreads();

    float dx = v.x - mean, dy = v.y - mean, dz = v.z - mean, dw = v.w - mean;
    red[t] = dx * dx + dy * dy + dz * dz + dw * dw; __syncthreads();
    for (int s = 128; s > 0; s >>= 1) { if (t < s) red[t] += red[t + s]; __syncthreads(); }
    const float inv = rsqrtf(red[0] * (1.0f / EE) + 1e-3f);

    float4 gm = ((const float4*)gamma)[t];
    float4 bt = ((const float4*)beta)[t];
    float4 o;
    o.x = dx * inv * gm.x + bt.x; o.y = dy * inv * gm.y + bt.y;
    o.z = dz * inv * gm.z + bt.z; o.w = dw * inv * gm.w + bt.w;
    ((float4*)(out + row * EE))[t] = o;
}

// ---------------- launch ----------------
extern "C" void kernel_launch(void* const* d_in, const int* in_sizes, int n_in,
                              void* d_out, int out_size)
{
    const float* w      = (const float*)d_in[0];
    const float* r      = (const float*)d_in[1];
    const float* member = (const float*)d_in[2];
    const float* Wq  = (const float*)d_in[4];
    const float* Wk  = (const float*)d_in[5];
    const float* Wv  = (const float*)d_in[6];
    const float* Wr  = (const float*)d_in[7];
    const float* Wo  = (const float*)d_in[8];
    const float* rwb = (const float*)d_in[9];
    const float* rrb = (const float*)d_in[10];
    const float* ln1g = (const float*)d_in[11];
    const float* ln1b = (const float*)d_in[12];
    const float* W1  = (const float*)d_in[13];
    const float* W2  = (const float*)d_in[14];
    const float* ln2g = (const float*)d_in[15];
    const float* ln2b = (const float*)d_in[16];
    float* out = (float*)d_out;

    static float *p_cat = nullptr, *p_q, *p_k, *p_v, *p_r,
                 *p_att, *p_o, *p_x, *p_ffn, *p_y;
    if (!p_cat) {
        cudaGetSymbolAddress((void**)&p_cat, g_cat);
        cudaGetSymbolAddress((void**)&p_q,   g_q);
        cudaGetSymbolAddress((void**)&p_k,   g_k);
        cudaGetSymbolAddress((void**)&p_v,   g_v);
        cudaGetSymbolAddress((void**)&p_r,   g_r);
        cudaGetSymbolAddress((void**)&p_att, g_att);
        cudaGetSymbolAddress((void**)&p_o,   g_o);
        cudaGetSymbolAddress((void**)&p_x,   g_x);
        cudaGetSymbolAddress((void**)&p_ffn, g_ffn);
        cudaGetSymbolAddress((void**)&p_y,   g_y);
        cudaFuncSetAttribute(flash_attn, cudaFuncAttributeMaxDynamicSharedMemorySize, FA_SMEM);
    }

    // 1. cat (bf16)
    copy_cat_kernel<<<(BB * KLEN * EE / 4) / 256, 256>>>(
        (const float4*)w, (const float4*)member, (uint2*)p_cat);

    // 2. projections: bf16 compute, bf16 out
    gemm_h<1,1,1,0,1><<<dim3(HD / 128, (BB * QLEN) / 128), 256>>>(p_cat, EE, Wq, HD, p_q, HD, EE);
    gemm_h<1,1,1,0,0><<<dim3(HD / 128, (BB * KLEN) / 128), 256>>>(p_cat, EE, Wk, HD, p_k, HD, EE);
    gemm_h<1,1,1,0,0><<<dim3(HD / 128, (BB * KLEN) / 128), 256>>>(p_cat, EE, Wv, HD, p_v, HD, EE);
    gemm_h<1,0,1,0,0><<<dim3(HD / 128, KLEN / 128),        256>>>(r,     EE, Wr, HD, p_r, HD, EE);

    // 3. fused attention (fp16 O out)
    flash_attn<<<dim3(1, QLEN / 128, BB * HH), 256, FA_SMEM>>>(
        (const __nv_bfloat16*)p_q, (const __nv_bfloat16*)p_k,
        (const __nv_bfloat16*)p_v, (const __nv_bfloat16*)p_r,
        rwb, rrb, (unsigned*)p_att);

    // 4. output projection (fp16 compute, fp16 A, f32 out) + LN1
    gemm_h<0,1,0,0,0><<<dim3(EE / 128, (BB * QLEN) / 128), 256>>>(p_att, HD, Wo, EE, p_o, EE, HD);
    add_ln_kernel<<<BB * QLEN, 256>>>(w, p_o, ln1g, ln1b, p_x);

    // 5. FFN (fp16 compute, fp16 intermediate) + LN2 -> out
    gemm_h<0,0,2,1,0><<<dim3(FF / 128, (BB * QLEN) / 128), 256>>>(p_x,   EE, W1, FF, p_ffn, FF, EE);
    gemm_h<0,1,0,0,0><<<dim3(EE / 128, (BB * QLEN) / 128), 256>>>(p_ffn, FF, W2, EE, p_y,   EE, FF);
    add_ln_kernel<<<BB * QLEN, 256>>>(p_y, p_x, ln2g, ln2b, out);
}

// round 15
// speedup vs baseline: 1.6970x; 1.0279x over previous
#include <cuda_runtime.h>
#include <cuda_bf16.h>
#include <cuda_fp16.h>
#include <math.h>

#define BB 2
#define QLEN 1024
#define MLEN 1024
#define KLEN 2048
#define EE 1024
#define HH 16
#define DH 64
#define HD 1024   // HH*DH
#define FF 4096

// ---------------- scratch ----------------
static __device__ float g_cat[(size_t)BB * KLEN * EE / 2];   // bf16
static __device__ float g_q  [(size_t)BB * QLEN * HD];       // bf16 (half used)
static __device__ float g_k  [(size_t)BB * KLEN * HD];       // bf16 (half used)
static __device__ float g_v  [(size_t)BB * KLEN * HD];       // bf16 (half used)
static __device__ float g_r  [(size_t)KLEN * HD];            // bf16 (half used)
static __device__ float g_att[(size_t)BB * QLEN * HD / 2];   // fp16
static __device__ float g_o  [(size_t)BB * QLEN * EE];
static __device__ float g_x  [(size_t)BB * QLEN * EE];
static __device__ float g_ffn[(size_t)BB * QLEN * FF / 2];   // fp16
static __device__ float g_y  [(size_t)BB * QLEN * EE];

// ---------------- helpers ----------------
__device__ __forceinline__ unsigned pack_bf2(float lo, float hi) {
    unsigned u; asm("cvt.rn.bf16x2.f32 %0, %1, %2;" : "=r"(u) : "f"(hi), "f"(lo)); return u;
}
template<int BF>
__device__ __forceinline__ unsigned pack2(float lo, float hi) {
    unsigned u;
    if (BF) asm("cvt.rn.bf16x2.f32 %0, %1, %2;" : "=r"(u) : "f"(hi), "f"(lo));
    else    asm("cvt.rn.f16x2.f32 %0, %1, %2;"  : "=r"(u) : "f"(hi), "f"(lo));
    return u;
}
__device__ __forceinline__ void mma16(float* c, const unsigned* a, const unsigned* b) {
    asm volatile("mma.sync.aligned.m16n8k16.row.col.f32.bf16.bf16.f32 "
        "{%0,%1,%2,%3}, {%4,%5,%6,%7}, {%8,%9}, {%0,%1,%2,%3};\n"
        : "+f"(c[0]), "+f"(c[1]), "+f"(c[2]), "+f"(c[3])
        : "r"(a[0]), "r"(a[1]), "r"(a[2]), "r"(a[3]), "r"(b[0]), "r"(b[1]));
}
template<int BF>
__device__ __forceinline__ void mmah(float* c, const unsigned* a, const unsigned* b) {
    if (BF)
        asm volatile("mma.sync.aligned.m16n8k16.row.col.f32.bf16.bf16.f32 "
            "{%0,%1,%2,%3}, {%4,%5,%6,%7}, {%8,%9}, {%0,%1,%2,%3};\n"
            : "+f"(c[0]), "+f"(c[1]), "+f"(c[2]), "+f"(c[3])
            : "r"(a[0]), "r"(a[1]), "r"(a[2]), "r"(a[3]), "r"(b[0]), "r"(b[1]));
    else
        asm volatile("mma.sync.aligned.m16n8k16.row.col.f32.f16.f16.f32 "
            "{%0,%1,%2,%3}, {%4,%5,%6,%7}, {%8,%9}, {%0,%1,%2,%3};\n"
            : "+f"(c[0]), "+f"(c[1]), "+f"(c[2]), "+f"(c[3])
            : "r"(a[0]), "r"(a[1]), "r"(a[2]), "r"(a[3]), "r"(b[0]), "r"(b[1]));
}
__device__ __forceinline__ void ldsm4(unsigned* r, unsigned saddr) {
    asm volatile("ldmatrix.sync.aligned.m8n8.x4.shared.b16 {%0,%1,%2,%3}, [%4];"
        : "=r"(r[0]), "=r"(r[1]), "=r"(r[2]), "=r"(r[3]) : "r"(saddr));
}
__device__ __forceinline__ void ldsm4t(unsigned* r, unsigned saddr) {
    asm volatile("ldmatrix.sync.aligned.m8n8.x4.trans.shared.b16 {%0,%1,%2,%3}, [%4];"
        : "=r"(r[0]), "=r"(r[1]), "=r"(r[2]), "=r"(r[3]) : "r"(saddr));
}
__device__ __forceinline__ void cpa16(unsigned saddr, const void* g) {
    asm volatile("cp.async.cg.shared.global [%0], [%1], 16;" :: "r"(saddr), "l"(g));
}
__device__ __forceinline__ void cpa_commit() { asm volatile("cp.async.commit_group;"); }
__device__ __forceinline__ void cpa_waitall() { asm volatile("cp.async.wait_group 0;"); }

// ---------------- cat = concat(member, w), bf16 output ----------------
__global__ __launch_bounds__(256) void copy_cat_kernel(
    const float4* __restrict__ w, const float4* __restrict__ member, uint2* __restrict__ cat)
{
    size_t i = (size_t)blockIdx.x * 256 + threadIdx.x;
    int e4 = (int)(i % (EE / 4));
    size_t t2 = i / (EE / 4);
    int kl = (int)(t2 % KLEN);
    int b  = (int)(t2 / KLEN);
    float4 v;
    if (kl < MLEN) v = member[((size_t)b * MLEN + kl) * (EE / 4) + e4];
    else           v = w[((size_t)b * QLEN + (kl - MLEN)) * (EE / 4) + e4];
    cat[i] = make_uint2(pack_bf2(v.x, v.y), pack_bf2(v.z, v.w));
}

// ================= half-precision GEMM (ldmatrix consumers, proven) =================
#define ABW 20
#define BBW 68
template<int BF, int AH, int OUT, int RELU, int QMODE>
__global__ __launch_bounds__(256, 2) void gemm_h(
    const void* __restrict__ Ap, int lda, const float* __restrict__ B, int ldb,
    float* __restrict__ C, int ldc, int K)
{
    __shared__ __align__(16) unsigned As[2][128 * ABW];
    __shared__ __align__(16) unsigned Bs[2][32 * BBW];

    const int t = threadIdx.x;
    const int lane = t & 31, warp = t >> 5;
    const int g = lane >> 2, tig = lane & 3;
    const int wm0 = (warp >> 2) * 64, wn0 = (warp & 3) * 32;
    const int m0 = blockIdx.y * 128, n0 = blockIdx.x * 128;
    const int moff = QMODE ? (((m0 >> 10) + 1) << 10) : 0;

    const float* Af = (const float*)Ap;
    const unsigned short* Ah = (const unsigned short*)Ap;

    const int ar = t >> 2, ac = t & 3;
    const int br = t >> 3, bc = t & 7;

    const int l15 = lane & 15, lh = lane >> 4;
    const int bkl = (lane & 7) + 8 * ((lane >> 3) & 1);
    const unsigned sA0 = (unsigned)__cvta_generic_to_shared(&As[0][0]);
    const unsigned sB0 = (unsigned)__cvta_generic_to_shared(&Bs[0][0]);

    float c[4][4][4] = {};

    auto loadA = [&](int k0, unsigned* dst8) {
        #pragma unroll
        for (int p = 0; p < 2; p++) {
            size_t row = (size_t)(m0 + moff + ar + 64 * p);
            if (AH) {
                uint4 v = *(const uint4*)&Ah[row * lda + k0 + ac * 8];
                dst8[4*p+0] = v.x; dst8[4*p+1] = v.y; dst8[4*p+2] = v.z; dst8[4*p+3] = v.w;
            } else {
                const float* src = Af + row * lda + k0 + ac * 8;
                float4 f0 = ((const float4*)src)[0], f1 = ((const float4*)src)[1];
                dst8[4*p+0] = pack2<BF>(f0.x, f0.y); dst8[4*p+1] = pack2<BF>(f0.z, f0.w);
                dst8[4*p+2] = pack2<BF>(f1.x, f1.y); dst8[4*p+3] = pack2<BF>(f1.z, f1.w);
            }
        }
    };
    auto loadB = [&](int k0, unsigned* dst8) {
        const float* bsrc = B + (size_t)(k0 + br) * ldb + n0 + bc * 16;
        float4 f0 = ((const float4*)bsrc)[0], f1 = ((const float4*)bsrc)[1];
        float4 f2 = ((const float4*)bsrc)[2], f3 = ((const float4*)bsrc)[3];
        dst8[0] = pack2<BF>(f0.x, f0.y); dst8[1] = pack2<BF>(f0.z, f0.w);
        dst8[2] = pack2<BF>(f1.x, f1.y); dst8[3] = pack2<BF>(f1.z, f1.w);
        dst8[4] = pack2<BF>(f2.x, f2.y); dst8[5] = pack2<BF>(f2.z, f2.w);
        dst8[6] = pack2<BF>(f3.x, f3.y); dst8[7] = pack2<BF>(f3.z, f3.w);
    };

    {
        unsigned sa[8], sbv[8];
        loadA(0, sa); loadB(0, sbv);
        *(uint4*)&As[0][ar * ABW + ac * 4]        = make_uint4(sa[0], sa[1], sa[2], sa[3]);
        *(uint4*)&As[0][(ar + 64) * ABW + ac * 4] = make_uint4(sa[4], sa[5], sa[6], sa[7]);
        *(uint4*)&Bs[0][br * BBW + bc * 8]        = make_uint4(sbv[0], sbv[1], sbv[2], sbv[3]);
        *(uint4*)&Bs[0][br * BBW + bc * 8 + 4]    = make_uint4(sbv[4], sbv[5], sbv[6], sbv[7]);
    }
    __syncthreads();

    const int nk = K / 32;
    int buf = 0;
    for (int kt = 0; kt < nk; kt++) {
        unsigned sa[8], sbv[8];
        if (kt + 1 < nk) { loadA((kt + 1) * 32, sa); loadB((kt + 1) * 32, sbv); }

        const unsigned sAb = sA0 + buf * (128 * ABW * 4);
        const unsigned sBb = sB0 + buf * (32 * BBW * 4);
        #pragma unroll
        for (int ksx = 0; ksx < 2; ksx++) {
            unsigned af[4][4];
            #pragma unroll
            for (int mi = 0; mi < 4; mi++)
                ldsm4(af[mi], sAb + (((wm0 + mi * 16 + l15) * ABW) + ksx * 8 + lh * 4) * 4);
            #pragma unroll
            for (int nb = 0; nb < 2; nb++) {
                unsigned br4[4];
                ldsm4t(br4, sBb + ((ksx * 16 + bkl) * BBW + (wn0 >> 1) + nb * 8 + 4 * lh) * 4);
                #pragma unroll
                for (int mi = 0; mi < 4; mi++) {
                    mmah<BF>(c[mi][2 * nb],     af[mi], br4);
                    mmah<BF>(c[mi][2 * nb + 1], af[mi], br4 + 2);
                }
            }
        }

        if (kt + 1 < nk) {
            int nb2 = buf ^ 1;
            *(uint4*)&As[nb2][ar * ABW + ac * 4]        = make_uint4(sa[0], sa[1], sa[2], sa[3]);
            *(uint4*)&As[nb2][(ar + 64) * ABW + ac * 4] = make_uint4(sa[4], sa[5], sa[6], sa[7]);
            *(uint4*)&Bs[nb2][br * BBW + bc * 8]        = make_uint4(sbv[0], sbv[1], sbv[2], sbv[3]);
            *(uint4*)&Bs[nb2][br * BBW + bc * 8 + 4]    = make_uint4(sbv[4], sbv[5], sbv[6], sbv[7]);
            __syncthreads();
        }
        buf ^= 1;
    }

    #pragma unroll
    for (int mi = 0; mi < 4; mi++) {
        int row = m0 + wm0 + mi * 16 + g;
        #pragma unroll
        for (int ni = 0; ni < 4; ni++) {
            int col = n0 + wn0 + ni * 8 + 2 * tig;
            float v0 = c[mi][ni][0], v1 = c[mi][ni][1];
            float v2 = c[mi][ni][2], v3 = c[mi][ni][3];
            if (RELU) {
                v0 = fmaxf(v0, 0.f); v1 = fmaxf(v1, 0.f);
                v2 = fmaxf(v2, 0.f); v3 = fmaxf(v3, 0.f);
            }
            if (OUT == 1) {
                unsigned* Cu = (unsigned*)C;
                Cu[((size_t)row * ldc + col) / 2]       = pack_bf2(v0, v1);
                Cu[((size_t)(row + 8) * ldc + col) / 2] = pack_bf2(v2, v3);
            } else if (OUT == 2) {
                unsigned* Cu = (unsigned*)C;
                Cu[((size_t)row * ldc + col) / 2]       = pack2<0>(v0, v1);
                Cu[((size_t)(row + 8) * ldc + col) / 2] = pack2<0>(v2, v3);
            } else {
                *(float2*)&C[(size_t)row * ldc + col]       = make_float2(v0, v1);
                *(float2*)&C[(size_t)(row + 8) * ldc + col] = make_float2(v2, v3);
            }
        }
    }
}

// ================= flash attention: warp-row ownership (16 q-rows / warp) =================
#define QS 36
#define GSW 68
#define OFF_QW 0
#define OFF_QR 18432
#define OFF_K  36864
#define OFF_V  73728
#define OFF_R  110592
#define OFF_G  147456
#define GBLK   34816
#define OFF_RED 217088
#define FA_SMEM 221184

__global__ __launch_bounds__(256, 1) void flash_attn(
    const __nv_bfloat16* __restrict__ Qb, const __nv_bfloat16* __restrict__ Kb,
    const __nv_bfloat16* __restrict__ Vb, const __nv_bfloat16* __restrict__ Rb,
    const float* __restrict__ rwb, const float* __restrict__ rrb,
    unsigned* __restrict__ Om)
{
    extern __shared__ __align__(16) char smem[];
    unsigned*  uQw = (unsigned*)(smem + OFF_QW);
    unsigned*  uQr = (unsigned*)(smem + OFF_QR);
    const unsigned sb = (unsigned)__cvta_generic_to_shared(smem);

    const int t = threadIdx.x;
    const int lane = t & 31, warp = t >> 5;
    const int g = lane >> 2, tig = lane & 3;
    const int wm0 = warp * 16;                    // warp owns q-rows [wm0, wm0+16)
    const int l15 = lane & 15, lh = lane >> 4;
    const int bkl = (lane & 7) + 8 * ((lane >> 3) & 1);

    const int bh = blockIdx.z, b = bh >> 4, h = bh & 15;
    const int q0 = (gridDim.y - 1 - blockIdx.y) * 128;
    const int ntiles = q0 / 128 + 9;

    const __nv_bfloat16* gK = Kb + ((size_t)b * KLEN) * HD + h * DH;
    const __nv_bfloat16* gV = Vb + ((size_t)b * KLEN) * HD + h * DH;
    const __nv_bfloat16* gR = Rb + h * DH;

    // prologue: K/V(0) + full 256-row R band
    {
        #pragma unroll
        for (int i = 0; i < 4; i++) {
            int id = t + 256 * i, row = id >> 3, ch = id & 7;
            cpa16(sb + OFF_K + row * 144 + ch * 16, gK + (size_t)row * HD + ch * 8);
            cpa16(sb + OFF_V + row * 144 + ch * 16, gV + (size_t)row * HD + ch * 8);
        }
        cpa_commit();
        int j0 = 0 - q0 + (QLEN - 128);
        #pragma unroll
        for (int i = 0; i < 8; i++) {
            int id = t + 256 * i, row = id >> 3, ch = id & 7;
            int j = j0 + row; if (j > KLEN - 1) j = KLEN - 1;
            cpa16(sb + OFF_R + row * 144 + ch * 16, gR + (size_t)j * HD + ch * 8);
        }
        cpa_commit();
    }

    // Q + biases
    {
        const __nv_bfloat16* qsrc = Qb + ((size_t)b * QLEN + q0) * HD + h * DH;
        int lr = t >> 1, lc0 = (t & 1) * 32;
        #pragma unroll
        for (int i = 0; i < 8; i++) {
            int c = lc0 + i * 4;
            uint2 u = *(const uint2*)&qsrc[(size_t)lr * HD + c];
            __nv_bfloat162 q01 = *(__nv_bfloat162*)&u.x;
            __nv_bfloat162 q23 = *(__nv_bfloat162*)&u.y;
            float4 bw = *(const float4*)&rwb[h * DH + c];
            float4 br = *(const float4*)&rrb[h * DH + c];
            float f0 = __bfloat162float(q01.x), f1 = __bfloat162float(q01.y);
            float f2 = __bfloat162float(q23.x), f3 = __bfloat162float(q23.y);
            uQw[lr * QS + c / 2]     = pack_bf2(f0 + bw.x, f1 + bw.y);
            uQw[lr * QS + c / 2 + 1] = pack_bf2(f2 + bw.z, f3 + bw.w);
            uQr[lr * QS + c / 2]     = pack_bf2(f0 + br.x, f1 + br.y);
            uQr[lr * QS + c / 2 + 1] = pack_bf2(f2 + br.z, f3 + br.w);
        }
    }

    float o[8][4] = {};
    float mrun[2] = {-INFINITY, -INFINITY}, lrun[2] = {0.f, 0.f};

    const unsigned sQWb = sb + OFF_QW, sQRb = sb + OFF_QR;

    // 16x128 score block: A rows [wm0,wm0+16) from saddrA, B = all 128 rows of saddrB
    auto qkblock = [&](unsigned saddrA, unsigned saddrB, float (*acc)[4]) {
        #pragma unroll
        for (int ks = 0; ks < 4; ks++) {
            unsigned af[4];
            ldsm4(af, saddrA + ((wm0 + l15) * QS + ks * 8 + lh * 4) * 4);
            #pragma unroll
            for (int nb = 0; nb < 8; nb++) {
                unsigned b4[4];
                ldsm4(b4, saddrB + ((nb * 16 + l15) * QS + ks * 8 + lh * 4) * 4);
                unsigned bf0[2] = {b4[0], b4[2]}, bf1[2] = {b4[1], b4[3]};
                mma16(acc[2 * nb],     af, bf0);
                mma16(acc[2 * nb + 1], af, bf1);
            }
        }
    };

    int buf = 0;
    for (int kt = 0; kt < ntiles; kt++) {
        const int k0 = kt * 128;
        cpa_waitall();
        __syncthreads();

        if (kt + 1 < ntiles) {
            const __nv_bfloat16* nK = gK + (size_t)(k0 + 128) * HD;
            const __nv_bfloat16* nV = gV + (size_t)(k0 + 128) * HD;
            unsigned kb = OFF_K + (buf ^ 1) * 18432, vb2 = OFF_V + (buf ^ 1) * 18432;
            #pragma unroll
            for (int i = 0; i < 4; i++) {
                int id = t + 256 * i, row = id >> 3, ch = id & 7;
                cpa16(sb + kb + row * 144 + ch * 16, nK + (size_t)row * HD + ch * 8);
                cpa16(sb + vb2 + row * 144 + ch * 16, nV + (size_t)row * HD + ch * 8);
            }
            cpa_commit();
        }

        // AC
        float acc[16][4] = {};
        qkblock(sQWb, sb + OFF_K + buf * 18432, acc);

        // G blocks (rolling band, warp-private rows)
        auto gblock = [&](unsigned saddrR, unsigned* uGd) {
            float ga[16][4] = {};
            qkblock(sQRb, saddrR, ga);
            #pragma unroll
            for (int ni = 0; ni < 16; ni++)
                #pragma unroll
                for (int hh = 0; hh < 2; hh++) {
                    int r = wm0 + g + 8 * hh;
                    int col = ni * 8 + 2 * tig;
                    uGd[r * GSW + col / 2] = pack_bf2(ga[ni][2 * hh], ga[ni][2 * hh + 1]);
                }
        };
        if (kt == 0)
            gblock(sb + OFF_R, (unsigned*)(smem + OFF_G));
        gblock(sb + OFF_R + ((kt + 1) & 1) * 18432,
               (unsigned*)(smem + OFF_G + ((kt + 1) & 1) * GBLK));
        __syncthreads();   // all warps done reading R before refill; also publishes G

        if (kt + 1 < ntiles) {
            int jb = (k0 + 128) - q0 + (QLEN - 128) + 128;
            unsigned rb = OFF_R + (kt & 1) * 18432;
            #pragma unroll
            for (int i = 0; i < 4; i++) {
                int id = t + 256 * i, row = id >> 3, ch = id & 7;
                int j = jb + row; if (j > KLEN - 1) j = KLEN - 1;
                cpa16(sb + rb + row * 144 + ch * 16, gR + (size_t)j * HD + ch * 8);
            }
            cpa_commit();
        }

        // gather shifted BD + mask + scale
        {
            const __nv_bfloat16* hGL = (const __nv_bfloat16*)(smem + OFF_G + (kt & 1) * GBLK);
            const __nv_bfloat16* hGH = (const __nv_bfloat16*)(smem + OFF_G + ((kt + 1) & 1) * GBLK);
            #pragma unroll
            for (int ni = 0; ni < 16; ni++)
                #pragma unroll
                for (int hh = 0; hh < 2; hh++)
                    #pragma unroll
                    for (int e = 0; e < 2; e++) {
                        int r = wm0 + g + 8 * hh;
                        int col = ni * 8 + 2 * tig + e;
                        int c = col - r + 127;
                        float bd = __bfloat162float(
                            (c < 128) ? hGL[r * 136 + c] : hGH[r * 136 + (c - 128)]);
                        float s = acc[ni][2 * hh + e] + bd;
                        acc[ni][2 * hh + e] =
                            ((k0 + col) <= (q0 + r) + MLEN) ? s * 0.03125f : -1e30f;
                    }
        }

        // warp-local softmax (row fully owned by this warp)
        float fsc[2];
        #pragma unroll
        for (int hh = 0; hh < 2; hh++) {
            float m8 = -INFINITY;
            #pragma unroll
            for (int ni = 0; ni < 16; ni++)
                m8 = fmaxf(m8, fmaxf(acc[ni][2 * hh], acc[ni][2 * hh + 1]));
            m8 = fmaxf(m8, __shfl_xor_sync(0xffffffffu, m8, 1));
            m8 = fmaxf(m8, __shfl_xor_sync(0xffffffffu, m8, 2));
            float sw = 0.f;
            #pragma unroll
            for (int ni = 0; ni < 16; ni++)
                #pragma unroll
                for (int e = 0; e < 2; e++) {
                    float p = __expf(acc[ni][2 * hh + e] - m8);
                    acc[ni][2 * hh + e] = p;
                    sw += p;
                }
            sw += __shfl_xor_sync(0xffffffffu, sw, 1);
            sw += __shfl_xor_sync(0xffffffffu, sw, 2);
            float mnew = fmaxf(mrun[hh], m8);
            float alpha = __expf(mrun[hh] - mnew);
            lrun[hh] = lrun[hh] * alpha + sw * __expf(m8 - mnew);
            mrun[hh] = mnew;
            fsc[hh] = __expf(m8 - mnew);
            #pragma unroll
            for (int ni2 = 0; ni2 < 8; ni2++) {
                o[ni2][2 * hh]     *= alpha;
                o[ni2][2 * hh + 1] *= alpha;
            }
        }

        // write P (warp-private rows; overlays dead low G block)
        unsigned* uP = (unsigned*)(smem + OFF_G + (kt & 1) * GBLK);
        const unsigned sP = sb + OFF_G + (kt & 1) * GBLK;
        #pragma unroll
        for (int ni = 0; ni < 16; ni++)
            #pragma unroll
            for (int hh = 0; hh < 2; hh++) {
                int r = wm0 + g + 8 * hh;
                int col = ni * 8 + 2 * tig;
                uP[r * GSW + col / 2] = pack_bf2(
                    acc[ni][2 * hh] * fsc[hh], acc[ni][2 * hh + 1] * fsc[hh]);
            }
        __syncwarp();

        // PV: af from own P rows, bv from V (all warps read all V rows)
        {
            const unsigned sV = sb + OFF_V + buf * 18432;
            #pragma unroll
            for (int ks = 0; ks < 8; ks++) {
                unsigned af[4];
                ldsm4(af, sP + ((wm0 + l15) * GSW + ks * 8 + lh * 4) * 4);
                #pragma unroll
                for (int nb = 0; nb < 4; nb++) {
                    unsigned bv[4];
                    ldsm4t(bv, sV + ((ks * 16 + bkl) * QS + nb * 8 + 4 * lh) * 4);
                    mma16(o[2 * nb],     af, bv);
                    mma16(o[2 * nb + 1], af, bv + 2);
                }
            }
        }
        buf ^= 1;
    }

    // epilogue: O /= l, write fp16
    #pragma unroll
    for (int ni2 = 0; ni2 < 8; ni2++)
        #pragma unroll
        for (int hh = 0; hh < 2; hh++) {
            int r = wm0 + g + 8 * hh;
            int d = ni2 * 8 + 2 * tig;
            float inv = 1.0f / lrun[hh];
            Om[(((size_t)b * QLEN + q0 + r) * HD + h * DH + d) / 2] =
                pack2<0>(o[ni2][2 * hh] * inv, o[ni2][2 * hh + 1] * inv);
        }
}

// ---------------- out = LayerNorm(a + b), rows of EE ----------------
__global__ __launch_bounds__(256) void add_ln_kernel(
    const float* __restrict__ A, const float* __restrict__ Bv,
    const float* __restrict__ gamma, const float* __restrict__ beta,
    float* __restrict__ out)
{
    __shared__ float red[256];
    const size_t row = blockIdx.x;
    const int t = threadIdx.x;
    float4 va = ((const float4*)(A + row * EE))[t];
    float4 vb = ((const float4*)(Bv + row * EE))[t];
    float4 v = make_float4(va.x + vb.x, va.y + vb.y, va.z + vb.z, va.w + vb.w);

    red[t] = v.x + v.y + v.z + v.w; __syncthreads();
    for (int s = 128; s > 0; s >>= 1) { if (t < s) red[t] += red[t + s]; __syncthreads(); }
    const float mean = red[0] * (1.0f / EE); __syncthreads();

    float dx = v.x - mean, dy = v.y - mean, dz = v.z - mean, dw = v.w - mean;
    red[t] = dx * dx + dy * dy + dz * dz + dw * dw; __syncthreads();
    for (int s = 128; s > 0; s >>= 1) { if (t < s) red[t] += red[t + s]; __syncthreads(); }
    const float inv = rsqrtf(red[0] * (1.0f / EE) + 1e-3f);

    float4 gm = ((const float4*)gamma)[t];
    float4 bt = ((const float4*)beta)[t];
    float4 o;
    o.x = dx * inv * gm.x + bt.x; o.y = dy * inv * gm.y + bt.y;
    o.z = dz * inv * gm.z + bt.z; o.w = dw * inv * gm.w + bt.w;
    ((float4*)(out + row * EE))[t] = o;
}

// ---------------- launch ----------------
extern "C" void kernel_launch(void* const* d_in, const int* in_sizes, int n_in,
                              void* d_out, int out_size)
{
    const float* w      = (const float*)d_in[0];
    const float* r      = (const float*)d_in[1];
    const float* member = (const float*)d_in[2];
    const float* Wq  = (const float*)d_in[4];
    const float* Wk  = (const float*)d_in[5];
    const float* Wv  = (const float*)d_in[6];
    const float* Wr  = (const float*)d_in[7];
    const float* Wo  = (const float*)d_in[8];
    const float* rwb = (const float*)d_in[9];
    const float* rrb = (const float*)d_in[10];
    const float* ln1g = (const float*)d_in[11];
    const float* ln1b = (const float*)d_in[12];
    const float* W1  = (const float*)d_in[13];
    const float* W2  = (const float*)d_in[14];
    const float* ln2g = (const float*)d_in[15];
    const float* ln2b = (const float*)d_in[16];
    float* out = (float*)d_out;

    static float *p_cat = nullptr, *p_q, *p_k, *p_v, *p_r,
                 *p_att, *p_o, *p_x, *p_ffn, *p_y;
    if (!p_cat) {
        cudaGetSymbolAddress((void**)&p_cat, g_cat);
        cudaGetSymbolAddress((void**)&p_q,   g_q);
        cudaGetSymbolAddress((void**)&p_k,   g_k);
        cudaGetSymbolAddress((void**)&p_v,   g_v);
        cudaGetSymbolAddress((void**)&p_r,   g_r);
        cudaGetSymbolAddress((void**)&p_att, g_att);
        cudaGetSymbolAddress((void**)&p_o,   g_o);
        cudaGetSymbolAddress((void**)&p_x,   g_x);
        cudaGetSymbolAddress((void**)&p_ffn, g_ffn);
        cudaGetSymbolAddress((void**)&p_y,   g_y);
        cudaFuncSetAttribute(flash_attn, cudaFuncAttributeMaxDynamicSharedMemorySize, FA_SMEM);
    }

    // 1. cat (bf16)
    copy_cat_kernel<<<(BB * KLEN * EE / 4) / 256, 256>>>(
        (const float4*)w, (const float4*)member, (uint2*)p_cat);

    // 2. projections: bf16 compute, bf16 out
    gemm_h<1,1,1,0,1><<<dim3(HD / 128, (BB * QLEN) / 128), 256>>>(p_cat, EE, Wq, HD, p_q, HD, EE);
    gemm_h<1,1,1,0,0><<<dim3(HD / 128, (BB * KLEN) / 128), 256>>>(p_cat, EE, Wk, HD, p_k, HD, EE);
    gemm_h<1,1,1,0,0><<<dim3(HD / 128, (BB * KLEN) / 128), 256>>>(p_cat, EE, Wv, HD, p_v, HD, EE);
    gemm_h<1,0,1,0,0><<<dim3(HD / 128, KLEN / 128),        256>>>(r,     EE, Wr, HD, p_r, HD, EE);

    // 3. fused attention (fp16 O out)
    flash_attn<<<dim3(1, QLEN / 128, BB * HH), 256, FA_SMEM>>>(
        (const __nv_bfloat16*)p_q, (const __nv_bfloat16*)p_k,
        (const __nv_bfloat16*)p_v, (const __nv_bfloat16*)p_r,
        rwb, rrb, (unsigned*)p_att);

    // 4. output projection (fp16 compute, fp16 A, f32 out) + LN1
    gemm_h<0,1,0,0,0><<<dim3(EE / 128, (BB * QLEN) / 128), 256>>>(p_att, HD, Wo, EE, p_o, EE, HD);
    add_ln_kernel<<<BB * QLEN, 256>>>(w, p_o, ln1g, ln1b, p_x);

    // 5. FFN (fp16 compute, fp16 intermediate) + LN2 -> out
    gemm_h<0,0,2,1,0><<<dim3(FF / 128, (BB * QLEN) / 128), 256>>>(p_x,   EE, W1, FF, p_ffn, FF, EE);
    gemm_h<0,1,0,0,0><<<dim3(EE / 128, (BB * QLEN) / 128), 256>>>(p_ffn, FF, W2, EE, p_y,   EE, FF);
    add_ln_kernel<<<BB * QLEN, 256>>>(p_y, p_x, ln2g, ln2b, out);
}

// round 16
// speedup vs baseline: 2.4524x; 1.4452x over previous
#include <cuda_runtime.h>
#include <cuda_bf16.h>
#include <cuda_fp16.h>
#include <math.h>

#define BB 2
#define QLEN 1024
#define MLEN 1024
#define KLEN 2048
#define EE 1024
#define HH 16
#define DH 64
#define HD 1024   // HH*DH
#define FF 4096

// ---------------- scratch ----------------
static __device__ float g_cat[(size_t)BB * KLEN * EE / 2];   // bf16
static __device__ float g_q  [(size_t)BB * QLEN * HD];       // bf16 (half used)
static __device__ float g_k  [(size_t)BB * KLEN * HD];       // bf16 (half used)
static __device__ float g_v  [(size_t)BB * KLEN * HD];       // bf16 (half used)
static __device__ float g_r  [(size_t)KLEN * HD];            // bf16 (half used)
static __device__ float g_att[(size_t)BB * QLEN * HD / 2];   // fp16
static __device__ float g_o  [(size_t)BB * QLEN * EE];
static __device__ float g_x  [(size_t)BB * QLEN * EE];
static __device__ float g_x16[(size_t)BB * QLEN * EE / 2];   // fp16 copy of x
static __device__ float g_ffn[(size_t)BB * QLEN * FF / 2];   // fp16
static __device__ float g_y  [(size_t)BB * QLEN * EE];
// converted weights / r
static __device__ float g_wq16[(size_t)EE * HD / 2];   // bf16
static __device__ float g_wk16[(size_t)EE * HD / 2];   // bf16
static __device__ float g_wv16[(size_t)EE * HD / 2];   // bf16
static __device__ float g_wr16[(size_t)EE * HD / 2];   // bf16
static __device__ float g_r16 [(size_t)KLEN * EE / 2]; // bf16
static __device__ float g_wo16[(size_t)HD * EE / 2];   // fp16
static __device__ float g_w116[(size_t)EE * FF / 2];   // fp16
static __device__ float g_w216[(size_t)FF * EE / 2];   // fp16

// ---------------- helpers ----------------
__device__ __forceinline__ unsigned pack_bf2(float lo, float hi) {
    unsigned u; asm("cvt.rn.bf16x2.f32 %0, %1, %2;" : "=r"(u) : "f"(hi), "f"(lo)); return u;
}
template<int BF>
__device__ __forceinline__ unsigned pack2(float lo, float hi) {
    unsigned u;
    if (BF) asm("cvt.rn.bf16x2.f32 %0, %1, %2;" : "=r"(u) : "f"(hi), "f"(lo));
    else    asm("cvt.rn.f16x2.f32 %0, %1, %2;"  : "=r"(u) : "f"(hi), "f"(lo));
    return u;
}
__device__ __forceinline__ void mma16(float* c, const unsigned* a, const unsigned* b) {
    asm volatile("mma.sync.aligned.m16n8k16.row.col.f32.bf16.bf16.f32 "
        "{%0,%1,%2,%3}, {%4,%5,%6,%7}, {%8,%9}, {%0,%1,%2,%3};\n"
        : "+f"(c[0]), "+f"(c[1]), "+f"(c[2]), "+f"(c[3])
        : "r"(a[0]), "r"(a[1]), "r"(a[2]), "r"(a[3]), "r"(b[0]), "r"(b[1]));
}
template<int BF>
__device__ __forceinline__ void mmah(float* c, const unsigned* a, const unsigned* b) {
    if (BF)
        asm volatile("mma.sync.aligned.m16n8k16.row.col.f32.bf16.bf16.f32 "
            "{%0,%1,%2,%3}, {%4,%5,%6,%7}, {%8,%9}, {%0,%1,%2,%3};\n"
            : "+f"(c[0]), "+f"(c[1]), "+f"(c[2]), "+f"(c[3])
            : "r"(a[0]), "r"(a[1]), "r"(a[2]), "r"(a[3]), "r"(b[0]), "r"(b[1]));
    else
        asm volatile("mma.sync.aligned.m16n8k16.row.col.f32.f16.f16.f32 "
            "{%0,%1,%2,%3}, {%4,%5,%6,%7}, {%8,%9}, {%0,%1,%2,%3};\n"
            : "+f"(c[0]), "+f"(c[1]), "+f"(c[2]), "+f"(c[3])
            : "r"(a[0]), "r"(a[1]), "r"(a[2]), "r"(a[3]), "r"(b[0]), "r"(b[1]));
}
__device__ __forceinline__ void ldsm4(unsigned* r, unsigned saddr) {
    asm volatile("ldmatrix.sync.aligned.m8n8.x4.shared.b16 {%0,%1,%2,%3}, [%4];"
        : "=r"(r[0]), "=r"(r[1]), "=r"(r[2]), "=r"(r[3]) : "r"(saddr));
}
__device__ __forceinline__ void ldsm4t(unsigned* r, unsigned saddr) {
    asm volatile("ldmatrix.sync.aligned.m8n8.x4.trans.shared.b16 {%0,%1,%2,%3}, [%4];"
        : "=r"(r[0]), "=r"(r[1]), "=r"(r[2]), "=r"(r[3]) : "r"(saddr));
}
__device__ __forceinline__ void cpa16(unsigned saddr, const void* g) {
    asm volatile("cp.async.cg.shared.global [%0], [%1], 16;" :: "r"(saddr), "l"(g));
}
__device__ __forceinline__ void cpa_commit() { asm volatile("cp.async.commit_group;"); }
__device__ __forceinline__ void cpa_wait1() { asm volatile("cp.async.wait_group 1;"); }
__device__ __forceinline__ void cpa_waitall() { asm volatile("cp.async.wait_group 0;"); }

// ---------------- convert weights + r to 16-bit ----------------
#define SEG_W  262144      // 1M f32 / 4
#define SEG_R  524288      // 2M f32 / 4
#define SEG_W1 1048576     // 4M f32 / 4
#define CV_TOTAL (4 * SEG_W + SEG_R + SEG_W + 2 * SEG_W1)   // 3931136 quads
__global__ __launch_bounds__(256) void convert_kernel(
    const float4* Wq, const float4* Wk, const float4* Wv, const float4* Wr,
    const float4* r, const float4* Wo, const float4* W1, const float4* W2,
    uint2* wq, uint2* wk, uint2* wv, uint2* wr,
    uint2* r16, uint2* wo, uint2* w1, uint2* w2)
{
    size_t i = (size_t)blockIdx.x * 256 + threadIdx.x;
    const float4* src; uint2* dst; size_t j; int bf;
    if      (i < 1 * SEG_W)          { src = Wq; dst = wq; j = i;               bf = 1; }
    else if (i < 2 * SEG_W)          { src = Wk; dst = wk; j = i - 1 * SEG_W;   bf = 1; }
    else if (i < 3 * SEG_W)          { src = Wv; dst = wv; j = i - 2 * SEG_W;   bf = 1; }
    else if (i < 4 * SEG_W)          { src = Wr; dst = wr; j = i - 3 * SEG_W;   bf = 1; }
    else if (i < 4 * SEG_W + SEG_R)  { src = r;  dst = r16; j = i - 4 * SEG_W;  bf = 1; }
    else if (i < 5 * SEG_W + SEG_R)  { src = Wo; dst = wo; j = i - 4 * SEG_W - SEG_R; bf = 0; }
    else if (i < 5 * SEG_W + SEG_R + SEG_W1)
        { src = W1; dst = w1; j = i - 5 * SEG_W - SEG_R; bf = 0; }
    else { src = W2; dst = w2; j = i - 5 * SEG_W - SEG_R - SEG_W1; bf = 0; }
    float4 f = src[j];
    if (bf) dst[j] = make_uint2(pack_bf2(f.x, f.y), pack_bf2(f.z, f.w));
    else    dst[j] = make_uint2(pack2<0>(f.x, f.y), pack2<0>(f.z, f.w));
}

// ---------------- cat = concat(member, w), bf16 output ----------------
__global__ __launch_bounds__(256) void copy_cat_kernel(
    const float4* __restrict__ w, const float4* __restrict__ member, uint2* __restrict__ cat)
{
    size_t i = (size_t)blockIdx.x * 256 + threadIdx.x;
    int e4 = (int)(i % (EE / 4));
    size_t t2 = i / (EE / 4);
    int kl = (int)(t2 % KLEN);
    int b  = (int)(t2 / KLEN);
    float4 v;
    if (kl < MLEN) v = member[((size_t)b * MLEN + kl) * (EE / 4) + e4];
    else           v = w[((size_t)b * QLEN + (kl - MLEN)) * (EE / 4) + e4];
    cat[i] = make_uint2(pack_bf2(v.x, v.y), pack_bf2(v.z, v.w));
}

// ================= all-half GEMM, 3-stage cp.async pipeline =================
// A: [M, lda] half, B: [K, ldb] half. Consumers = proven ldmatrix layout.
#define ABW 20
#define BBW 68
#define GH2_STG (128 * ABW + 32 * BBW)    // 4736 words per stage
#define GH2_SMEM (3 * GH2_STG * 4)        // 56832 bytes
template<int BF, int OUT, int RELU, int QMODE>
__global__ __launch_bounds__(256, 2) void gemm_h2(
    const unsigned short* __restrict__ A, int lda,
    const unsigned short* __restrict__ B, int ldb,
    float* __restrict__ C, int ldc, int K)
{
    extern __shared__ __align__(16) unsigned dsm[];
    const unsigned sb = (unsigned)__cvta_generic_to_shared(dsm);

    const int t = threadIdx.x;
    const int lane = t & 31, warp = t >> 5;
    const int g = lane >> 2, tig = lane & 3;
    const int wm0 = (warp >> 2) * 64, wn0 = (warp & 3) * 32;
    const int m0 = blockIdx.y * 128, n0 = blockIdx.x * 128;
    const int moff = QMODE ? (((m0 >> 10) + 1) << 10) : 0;

    const int l15 = lane & 15, lh = lane >> 4;
    const int bkl = (lane & 7) + 8 * ((lane >> 3) & 1);

    // loader: 2 A chunks + 2 B chunks of 16B per thread per stage
    auto issue = [&](int kt3, int k0) {
        unsigned base = sb + kt3 * (GH2_STG * 4);
        #pragma unroll
        for (int i = 0; i < 2; i++) {
            int id = t + 256 * i;                 // A chunk: row = id>>2, ac = id&3
            int row = id >> 2, ac = id & 3;
            cpa16(base + (row * ABW + ac * 4) * 4,
                  A + (size_t)(m0 + moff + row) * lda + k0 + ac * 8);
        }
        #pragma unroll
        for (int i = 0; i < 2; i++) {
            int id = t + 256 * i;                 // B chunk: row = id>>4, bc = id&15
            int row = id >> 4, bc = id & 15;
            cpa16(base + (2560 + row * BBW + bc * 4) * 4,
                  B + (size_t)(k0 + row) * ldb + n0 + bc * 8);
        }
    };

    const int nk = K / 32;
    issue(0, 0); cpa_commit();
    issue(1, 32); cpa_commit();

    float c[4][4][4] = {};

    for (int kt = 0; kt < nk; kt++) {
        cpa_wait1();
        __syncthreads();
        if (kt + 2 < nk) issue((kt + 2) % 3, (kt + 2) * 32);
        cpa_commit();

        const unsigned sAb = sb + (kt % 3) * (GH2_STG * 4);
        const unsigned sBb = sAb + 2560 * 4;
        #pragma unroll
        for (int ksx = 0; ksx < 2; ksx++) {
            unsigned af[4][4];
            #pragma unroll
            for (int mi = 0; mi < 4; mi++)
                ldsm4(af[mi], sAb + (((wm0 + mi * 16 + l15) * ABW) + ksx * 8 + lh * 4) * 4);
            #pragma unroll
            for (int nb = 0; nb < 2; nb++) {
                unsigned br4[4];
                ldsm4t(br4, sBb + ((ksx * 16 + bkl) * BBW + (wn0 >> 1) + nb * 8 + 4 * lh) * 4);
                #pragma unroll
                for (int mi = 0; mi < 4; mi++) {
                    mmah<BF>(c[mi][2 * nb],     af[mi], br4);
                    mmah<BF>(c[mi][2 * nb + 1], af[mi], br4 + 2);
                }
            }
        }
    }

    #pragma unroll
    for (int mi = 0; mi < 4; mi++) {
        int row = m0 + wm0 + mi * 16 + g;
        #pragma unroll
        for (int ni = 0; ni < 4; ni++) {
            int col = n0 + wn0 + ni * 8 + 2 * tig;
            float v0 = c[mi][ni][0], v1 = c[mi][ni][1];
            float v2 = c[mi][ni][2], v3 = c[mi][ni][3];
            if (RELU) {
                v0 = fmaxf(v0, 0.f); v1 = fmaxf(v1, 0.f);
                v2 = fmaxf(v2, 0.f); v3 = fmaxf(v3, 0.f);
            }
            if (OUT == 1) {
                unsigned* Cu = (unsigned*)C;
                Cu[((size_t)row * ldc + col) / 2]       = pack_bf2(v0, v1);
                Cu[((size_t)(row + 8) * ldc + col) / 2] = pack_bf2(v2, v3);
            } else if (OUT == 2) {
                unsigned* Cu = (unsigned*)C;
                Cu[((size_t)row * ldc + col) / 2]       = pack2<0>(v0, v1);
                Cu[((size_t)(row + 8) * ldc + col) / 2] = pack2<0>(v2, v3);
            } else {
                *(float2*)&C[(size_t)row * ldc + col]       = make_float2(v0, v1);
                *(float2*)&C[(size_t)(row + 8) * ldc + col] = make_float2(v2, v3);
            }
        }
    }
}

// ================= flash attention: warp-row ownership (R15, proven) =================
#define QS 36
#define GSW 68
#define OFF_QW 0
#define OFF_QR 18432
#define OFF_K  36864
#define OFF_V  73728
#define OFF_R  110592
#define OFF_G  147456
#define GBLK   34816
#define FA_SMEM 221184

__global__ __launch_bounds__(256, 1) void flash_attn(
    const __nv_bfloat16* __restrict__ Qb, const __nv_bfloat16* __restrict__ Kb,
    const __nv_bfloat16* __restrict__ Vb, const __nv_bfloat16* __restrict__ Rb,
    const float* __restrict__ rwb, const float* __restrict__ rrb,
    unsigned* __restrict__ Om)
{
    extern __shared__ __align__(16) char smem[];
    unsigned*  uQw = (unsigned*)(smem + OFF_QW);
    unsigned*  uQr = (unsigned*)(smem + OFF_QR);
    const unsigned sb = (unsigned)__cvta_generic_to_shared(smem);

    const int t = threadIdx.x;
    const int lane = t & 31, warp = t >> 5;
    const int g = lane >> 2, tig = lane & 3;
    const int wm0 = warp * 16;
    const int l15 = lane & 15, lh = lane >> 4;
    const int bkl = (lane & 7) + 8 * ((lane >> 3) & 1);

    const int bh = blockIdx.z, b = bh >> 4, h = bh & 15;
    const int q0 = (gridDim.y - 1 - blockIdx.y) * 128;
    const int ntiles = q0 / 128 + 9;

    const __nv_bfloat16* gK = Kb + ((size_t)b * KLEN) * HD + h * DH;
    const __nv_bfloat16* gV = Vb + ((size_t)b * KLEN) * HD + h * DH;
    const __nv_bfloat16* gR = Rb + h * DH;

    {
        #pragma unroll
        for (int i = 0; i < 4; i++) {
            int id = t + 256 * i, row = id >> 3, ch = id & 7;
            cpa16(sb + OFF_K + row * 144 + ch * 16, gK + (size_t)row * HD + ch * 8);
            cpa16(sb + OFF_V + row * 144 + ch * 16, gV + (size_t)row * HD + ch * 8);
        }
        cpa_commit();
        int j0 = 0 - q0 + (QLEN - 128);
        #pragma unroll
        for (int i = 0; i < 8; i++) {
            int id = t + 256 * i, row = id >> 3, ch = id & 7;
            int j = j0 + row; if (j > KLEN - 1) j = KLEN - 1;
            cpa16(sb + OFF_R + row * 144 + ch * 16, gR + (size_t)j * HD + ch * 8);
        }
        cpa_commit();
    }

    {
        const __nv_bfloat16* qsrc = Qb + ((size_t)b * QLEN + q0) * HD + h * DH;
        int lr = t >> 1, lc0 = (t & 1) * 32;
        #pragma unroll
        for (int i = 0; i < 8; i++) {
            int c = lc0 + i * 4;
            uint2 u = *(const uint2*)&qsrc[(size_t)lr * HD + c];
            __nv_bfloat162 q01 = *(__nv_bfloat162*)&u.x;
            __nv_bfloat162 q23 = *(__nv_bfloat162*)&u.y;
            float4 bw = *(const float4*)&rwb[h * DH + c];
            float4 br = *(const float4*)&rrb[h * DH + c];
            float f0 = __bfloat162float(q01.x), f1 = __bfloat162float(q01.y);
            float f2 = __bfloat162float(q23.x), f3 = __bfloat162float(q23.y);
            uQw[lr * QS + c / 2]     = pack_bf2(f0 + bw.x, f1 + bw.y);
            uQw[lr * QS + c / 2 + 1] = pack_bf2(f2 + bw.z, f3 + bw.w);
            uQr[lr * QS + c / 2]     = pack_bf2(f0 + br.x, f1 + br.y);
            uQr[lr * QS + c / 2 + 1] = pack_bf2(f2 + br.z, f3 + br.w);
        }
    }

    float o[8][4] = {};
    float mrun[2] = {-INFINITY, -INFINITY}, lrun[2] = {0.f, 0.f};

    const unsigned sQWb = sb + OFF_QW, sQRb = sb + OFF_QR;

    auto qkblock = [&](unsigned saddrA, unsigned saddrB, float (*acc)[4]) {
        #pragma unroll
        for (int ks = 0; ks < 4; ks++) {
            unsigned af[4];
            ldsm4(af, saddrA + ((wm0 + l15) * QS + ks * 8 + lh * 4) * 4);
            #pragma unroll
            for (int nb = 0; nb < 8; nb++) {
                unsigned b4[4];
                ldsm4(b4, saddrB + ((nb * 16 + l15) * QS + ks * 8 + lh * 4) * 4);
                unsigned bf0[2] = {b4[0], b4[2]}, bf1[2] = {b4[1], b4[3]};
                mma16(acc[2 * nb],     af, bf0);
                mma16(acc[2 * nb + 1], af, bf1);
            }
        }
    };

    int buf = 0;
    for (int kt = 0; kt < ntiles; kt++) {
        const int k0 = kt * 128;
        cpa_waitall();
        __syncthreads();

        if (kt + 1 < ntiles) {
            const __nv_bfloat16* nK = gK + (size_t)(k0 + 128) * HD;
            const __nv_bfloat16* nV = gV + (size_t)(k0 + 128) * HD;
            unsigned kb = OFF_K + (buf ^ 1) * 18432, vb2 = OFF_V + (buf ^ 1) * 18432;
            #pragma unroll
            for (int i = 0; i < 4; i++) {
                int id = t + 256 * i, row = id >> 3, ch = id & 7;
                cpa16(sb + kb + row * 144 + ch * 16, nK + (size_t)row * HD + ch * 8);
                cpa16(sb + vb2 + row * 144 + ch * 16, nV + (size_t)row * HD + ch * 8);
            }
            cpa_commit();
        }

        float acc[16][4] = {};
        qkblock(sQWb, sb + OFF_K + buf * 18432, acc);

        auto gblock = [&](unsigned saddrR, unsigned* uGd) {
            float ga[16][4] = {};
            qkblock(sQRb, saddrR, ga);
            #pragma unroll
            for (int ni = 0; ni < 16; ni++)
                #pragma unroll
                for (int hh = 0; hh < 2; hh++) {
                    int r = wm0 + g + 8 * hh;
                    int col = ni * 8 + 2 * tig;
                    uGd[r * GSW + col / 2] = pack_bf2(ga[ni][2 * hh], ga[ni][2 * hh + 1]);
                }
        };
        if (kt == 0)
            gblock(sb + OFF_R, (unsigned*)(smem + OFF_G));
        gblock(sb + OFF_R + ((kt + 1) & 1) * 18432,
               (unsigned*)(smem + OFF_G + ((kt + 1) & 1) * GBLK));
        __syncthreads();

        if (kt + 1 < ntiles) {
            int jb = (k0 + 128) - q0 + (QLEN - 128) + 128;
            unsigned rb = OFF_R + (kt & 1) * 18432;
            #pragma unroll
            for (int i = 0; i < 4; i++) {
                int id = t + 256 * i, row = id >> 3, ch = id & 7;
                int j = jb + row; if (j > KLEN - 1) j = KLEN - 1;
                cpa16(sb + rb + row * 144 + ch * 16, gR + (size_t)j * HD + ch * 8);
            }
            cpa_commit();
        }

        {
            const __nv_bfloat16* hGL = (const __nv_bfloat16*)(smem + OFF_G + (kt & 1) * GBLK);
            const __nv_bfloat16* hGH = (const __nv_bfloat16*)(smem + OFF_G + ((kt + 1) & 1) * GBLK);
            #pragma unroll
            for (int ni = 0; ni < 16; ni++)
                #pragma unroll
                for (int hh = 0; hh < 2; hh++)
                    #pragma unroll
                    for (int e = 0; e < 2; e++) {
                        int r = wm0 + g + 8 * hh;
                        int col = ni * 8 + 2 * tig + e;
                        int c = col - r + 127;
                        float bd = __bfloat162float(
                            (c < 128) ? hGL[r * 136 + c] : hGH[r * 136 + (c - 128)]);
                        float s = acc[ni][2 * hh + e] + bd;
                        acc[ni][2 * hh + e] =
                            ((k0 + col) <= (q0 + r) + MLEN) ? s * 0.03125f : -1e30f;
                    }
        }

        float fsc[2];
        #pragma unroll
        for (int hh = 0; hh < 2; hh++) {
            float m8 = -INFINITY;
            #pragma unroll
            for (int ni = 0; ni < 16; ni++)
                m8 = fmaxf(m8, fmaxf(acc[ni][2 * hh], acc[ni][2 * hh + 1]));
            m8 = fmaxf(m8, __shfl_xor_sync(0xffffffffu, m8, 1));
            m8 = fmaxf(m8, __shfl_xor_sync(0xffffffffu, m8, 2));
            float sw = 0.f;
            #pragma unroll
            for (int ni = 0; ni < 16; ni++)
                #pragma unroll
                for (int e = 0; e < 2; e++) {
                    float p = __expf(acc[ni][2 * hh + e] - m8);
                    acc[ni][2 * hh + e] = p;
                    sw += p;
                }
            sw += __shfl_xor_sync(0xffffffffu, sw, 1);
            sw += __shfl_xor_sync(0xffffffffu, sw, 2);
            float mnew = fmaxf(mrun[hh], m8);
            float alpha = __expf(mrun[hh] - mnew);
            lrun[hh] = lrun[hh] * alpha + sw * __expf(m8 - mnew);
            mrun[hh] = mnew;
            fsc[hh] = __expf(m8 - mnew);
            #pragma unroll
            for (int ni2 = 0; ni2 < 8; ni2++) {
                o[ni2][2 * hh]     *= alpha;
                o[ni2][2 * hh + 1] *= alpha;
            }
        }

        unsigned* uP = (unsigned*)(smem + OFF_G + (kt & 1) * GBLK);
        const unsigned sP = sb + OFF_G + (kt & 1) * GBLK;
        #pragma unroll
        for (int ni = 0; ni < 16; ni++)
            #pragma unroll
            for (int hh = 0; hh < 2; hh++) {
                int r = wm0 + g + 8 * hh;
                int col = ni * 8 + 2 * tig;
                uP[r * GSW + col / 2] = pack_bf2(
                    acc[ni][2 * hh] * fsc[hh], acc[ni][2 * hh + 1] * fsc[hh]);
            }
        __syncwarp();

        {
            const unsigned sV = sb + OFF_V + buf * 18432;
            #pragma unroll
            for (int ks = 0; ks < 8; ks++) {
                unsigned af[4];
                ldsm4(af, sP + ((wm0 + l15) * GSW + ks * 8 + lh * 4) * 4);
                #pragma unroll
                for (int nb = 0; nb < 4; nb++) {
                    unsigned bv[4];
                    ldsm4t(bv, sV + ((ks * 16 + bkl) * QS + nb * 8 + 4 * lh) * 4);
                    mma16(o[2 * nb],     af, bv);
                    mma16(o[2 * nb + 1], af, bv + 2);
                }
            }
        }
        buf ^= 1;
    }

    #pragma unroll
    for (int ni2 = 0; ni2 < 8; ni2++)
        #pragma unroll
        for (int hh = 0; hh < 2; hh++) {
            int r = wm0 + g + 8 * hh;
            int d = ni2 * 8 + 2 * tig;
            float inv = 1.0f / lrun[hh];
            Om[(((size_t)b * QLEN + q0 + r) * HD + h * DH + d) / 2] =
                pack2<0>(o[ni2][2 * hh] * inv, o[ni2][2 * hh + 1] * inv);
        }
}

// ---------------- out = LayerNorm(a + b); optional fp16 copy ----------------
__global__ __launch_bounds__(256) void add_ln_kernel(
    const float* __restrict__ A, const float* __restrict__ Bv,
    const float* __restrict__ gamma, const float* __restrict__ beta,
    float* __restrict__ out, unsigned* __restrict__ out16)
{
    __shared__ float red[256];
    const size_t row = blockIdx.x;
    const int t = threadIdx.x;
    float4 va = ((const float4*)(A + row * EE))[t];
    float4 vb = ((const float4*)(Bv + row * EE))[t];
    float4 v = make_float4(va.x + vb.x, va.y + vb.y, va.z + vb.z, va.w + vb.w);

    red[t] = v.x + v.y + v.z + v.w; __syncthreads();
    for (int s = 128; s > 0; s >>= 1) { if (t < s) red[t] += red[t + s]; __syncthreads(); }
    const float mean = red[0] * (1.0f / EE); __syncthreads();

    float dx = v.x - mean, dy = v.y - mean, dz = v.z - mean, dw = v.w - mean;
    red[t] = dx * dx + dy * dy + dz * dz + dw * dw; __syncthreads();
    for (int s = 128; s > 0; s >>= 1) { if (t < s) red[t] += red[t + s]; __syncthreads(); }
    const float inv = rsqrtf(red[0] * (1.0f / EE) + 1e-3f);

    float4 gm = ((const float4*)gamma)[t];
    float4 bt = ((const float4*)beta)[t];
    float4 o;
    o.x = dx * inv * gm.x + bt.x; o.y = dy * inv * gm.y + bt.y;
    o.z = dz * inv * gm.z + bt.z; o.w = dw * inv * gm.w + bt.w;
    ((float4*)(out + row * EE))[t] = o;
    if (out16)
        ((uint2*)(out16 + row * EE / 2))[t] =
            make_uint2(pack2<0>(o.x, o.y), pack2<0>(o.z, o.w));
}

// ---------------- launch ----------------
extern "C" void kernel_launch(void* const* d_in, const int* in_sizes, int n_in,
                              void* d_out, int out_size)
{
    const float* w      = (const float*)d_in[0];
    const float* r      = (const float*)d_in[1];
    const float* member = (const float*)d_in[2];
    const float* Wq  = (const float*)d_in[4];
    const float* Wk  = (const float*)d_in[5];
    const float* Wv  = (const float*)d_in[6];
    const float* Wr  = (const float*)d_in[7];
    const float* Wo  = (const float*)d_in[8];
    const float* rwb = (const float*)d_in[9];
    const float* rrb = (const float*)d_in[10];
    const float* ln1g = (const float*)d_in[11];
    const float* ln1b = (const float*)d_in[12];
    const float* W1  = (const float*)d_in[13];
    const float* W2  = (const float*)d_in[14];
    const float* ln2g = (const float*)d_in[15];
    const float* ln2b = (const float*)d_in[16];
    float* out = (float*)d_out;

    static float *p_cat = nullptr, *p_q, *p_k, *p_v, *p_r,
                 *p_att, *p_o, *p_x, *p_x16, *p_ffn, *p_y,
                 *p_wq, *p_wk, *p_wv, *p_wr, *p_r16, *p_wo, *p_w1, *p_w2;
    if (!p_cat) {
        cudaGetSymbolAddress((void**)&p_cat, g_cat);
        cudaGetSymbolAddress((void**)&p_q,   g_q);
        cudaGetSymbolAddress((void**)&p_k,   g_k);
        cudaGetSymbolAddress((void**)&p_v,   g_v);
        cudaGetSymbolAddress((void**)&p_r,   g_r);
        cudaGetSymbolAddress((void**)&p_att, g_att);
        cudaGetSymbolAddress((void**)&p_o,   g_o);
        cudaGetSymbolAddress((void**)&p_x,   g_x);
        cudaGetSymbolAddress((void**)&p_x16, g_x16);
        cudaGetSymbolAddress((void**)&p_ffn, g_ffn);
        cudaGetSymbolAddress((void**)&p_y,   g_y);
        cudaGetSymbolAddress((void**)&p_wq,  g_wq16);
        cudaGetSymbolAddress((void**)&p_wk,  g_wk16);
        cudaGetSymbolAddress((void**)&p_wv,  g_wv16);
        cudaGetSymbolAddress((void**)&p_wr,  g_wr16);
        cudaGetSymbolAddress((void**)&p_r16, g_r16);
        cudaGetSymbolAddress((void**)&p_wo,  g_wo16);
        cudaGetSymbolAddress((void**)&p_w1,  g_w116);
        cudaGetSymbolAddress((void**)&p_w2,  g_w216);
        cudaFuncSetAttribute(flash_attn, cudaFuncAttributeMaxDynamicSharedMemorySize, FA_SMEM);
        cudaFuncSetAttribute(gemm_h2<1,1,0,0>, cudaFuncAttributeMaxDynamicSharedMemorySize, GH2_SMEM);
        cudaFuncSetAttribute(gemm_h2<1,1,0,1>, cudaFuncAttributeMaxDynamicSharedMemorySize, GH2_SMEM);
        cudaFuncSetAttribute(gemm_h2<0,0,0,0>, cudaFuncAttributeMaxDynamicSharedMemorySize, GH2_SMEM);
        cudaFuncSetAttribute(gemm_h2<0,2,1,0>, cudaFuncAttributeMaxDynamicSharedMemorySize, GH2_SMEM);
    }

    // 0. convert weights + r to 16-bit
    convert_kernel<<<CV_TOTAL / 256, 256>>>(
        (const float4*)Wq, (const float4*)Wk, (const float4*)Wv, (const float4*)Wr,
        (const float4*)r, (const float4*)Wo, (const float4*)W1, (const float4*)W2,
        (uint2*)p_wq, (uint2*)p_wk, (uint2*)p_wv, (uint2*)p_wr,
        (uint2*)p_r16, (uint2*)p_wo, (uint2*)p_w1, (uint2*)p_w2);

    // 1. cat (bf16)
    copy_cat_kernel<<<(BB * KLEN * EE / 4) / 256, 256>>>(
        (const float4*)w, (const float4*)member, (uint2*)p_cat);

    // 2. projections: bf16, all-half pipeline
    gemm_h2<1,1,0,1><<<dim3(HD / 128, (BB * QLEN) / 128), 256, GH2_SMEM>>>(
        (const unsigned short*)p_cat, EE, (const unsigned short*)p_wq, HD, p_q, HD, EE);
    gemm_h2<1,1,0,0><<<dim3(HD / 128, (BB * KLEN) / 128), 256, GH2_SMEM>>>(
        (const unsigned short*)p_cat, EE, (const unsigned short*)p_wk, HD, p_k, HD, EE);
    gemm_h2<1,1,0,0><<<dim3(HD / 128, (BB * KLEN) / 128), 256, GH2_SMEM>>>(
        (const unsigned short*)p_cat, EE, (const unsigned short*)p_wv, HD, p_v, HD, EE);
    gemm_h2<1,1,0,0><<<dim3(HD / 128, KLEN / 128), 256, GH2_SMEM>>>(
        (const unsigned short*)p_r16, EE, (const unsigned short*)p_wr, HD, p_r, HD, EE);

    // 3. fused attention (fp16 O out)
    flash_attn<<<dim3(1, QLEN / 128, BB * HH), 256, FA_SMEM>>>(
        (const __nv_bfloat16*)p_q, (const __nv_bfloat16*)p_k,
        (const __nv_bfloat16*)p_v, (const __nv_bfloat16*)p_r,
        rwb, rrb, (unsigned*)p_att);

    // 4. output projection (fp16) + LN1 (f32 + fp16 copy)
    gemm_h2<0,0,0,0><<<dim3(EE / 128, (BB * QLEN) / 128), 256, GH2_SMEM>>>(
        (const unsigned short*)p_att, HD, (const unsigned short*)p_wo, EE, p_o, EE, HD);
    add_ln_kernel<<<BB * QLEN, 256>>>(w, p_o, ln1g, ln1b, p_x, (unsigned*)p_x16);

    // 5. FFN (fp16) + LN2 -> out
    gemm_h2<0,2,1,0><<<dim3(FF / 128, (BB * QLEN) / 128), 256, GH2_SMEM>>>(
        (const unsigned short*)p_x16, EE, (const unsigned short*)p_w1, FF, p_ffn, FF, EE);
    gemm_h2<0,0,0,0><<<dim3(EE / 128, (BB * QLEN) / 128), 256, GH2_SMEM>>>(
        (const unsigned short*)p_ffn, FF, (const unsigned short*)p_w2, EE, p_y, EE, FF);
    add_ln_kernel<<<BB * QLEN, 256>>>(p_y, p_x, ln2g, ln2b, out, nullptr);
}

// round 17
// speedup vs baseline: 2.7344x; 1.1150x over previous
#include <cuda_runtime.h>
#include <cuda_bf16.h>
#include <cuda_fp16.h>
#include <math.h>

#define BB 2
#define QLEN 1024
#define MLEN 1024
#define KLEN 2048
#define EE 1024
#define HH 16
#define DH 64
#define HD 1024   // HH*DH
#define FF 4096

// ---------------- scratch ----------------
static __device__ float g_cat[(size_t)BB * KLEN * EE / 2];   // bf16
static __device__ float g_q  [(size_t)BB * QLEN * HD];       // bf16 (half used)
static __device__ float g_k  [(size_t)BB * KLEN * HD];       // bf16 (half used)
static __device__ float g_v  [(size_t)BB * KLEN * HD];       // bf16 (half used)
static __device__ float g_r  [(size_t)KLEN * HD];            // bf16 (half used)
static __device__ float g_att[(size_t)BB * QLEN * HD / 2];   // fp16
static __device__ float g_o  [(size_t)BB * QLEN * EE];
static __device__ float g_x  [(size_t)BB * QLEN * EE];
static __device__ float g_x16[(size_t)BB * QLEN * EE / 2];   // fp16 copy of x
static __device__ float g_ffn[(size_t)BB * QLEN * FF / 2];   // fp16
static __device__ float g_y  [(size_t)BB * QLEN * EE];
// converted weights / r
static __device__ float g_wq16[(size_t)EE * HD / 2];   // bf16
static __device__ float g_wk16[(size_t)EE * HD / 2];   // bf16
static __device__ float g_wv16[(size_t)EE * HD / 2];   // bf16
static __device__ float g_wr16[(size_t)EE * HD / 2];   // bf16
static __device__ float g_r16 [(size_t)KLEN * EE / 2]; // bf16
static __device__ float g_wo16[(size_t)HD * EE / 2];   // fp16
static __device__ float g_w116[(size_t)EE * FF / 2];   // fp16
static __device__ float g_w216[(size_t)FF * EE / 2];   // fp16

// ---------------- helpers ----------------
__device__ __forceinline__ unsigned pack_bf2(float lo, float hi) {
    unsigned u; asm("cvt.rn.bf16x2.f32 %0, %1, %2;" : "=r"(u) : "f"(hi), "f"(lo)); return u;
}
template<int BF>
__device__ __forceinline__ unsigned pack2(float lo, float hi) {
    unsigned u;
    if (BF) asm("cvt.rn.bf16x2.f32 %0, %1, %2;" : "=r"(u) : "f"(hi), "f"(lo));
    else    asm("cvt.rn.f16x2.f32 %0, %1, %2;"  : "=r"(u) : "f"(hi), "f"(lo));
    return u;
}
__device__ __forceinline__ float ex2(float x) {
    float y; asm("ex2.approx.ftz.f32 %0, %1;" : "=f"(y) : "f"(x)); return y;
}
__device__ __forceinline__ void mma16(float* c, const unsigned* a, const unsigned* b) {
    asm volatile("mma.sync.aligned.m16n8k16.row.col.f32.bf16.bf16.f32 "
        "{%0,%1,%2,%3}, {%4,%5,%6,%7}, {%8,%9}, {%0,%1,%2,%3};\n"
        : "+f"(c[0]), "+f"(c[1]), "+f"(c[2]), "+f"(c[3])
        : "r"(a[0]), "r"(a[1]), "r"(a[2]), "r"(a[3]), "r"(b[0]), "r"(b[1]));
}
template<int BF>
__device__ __forceinline__ void mmah(float* c, const unsigned* a, const unsigned* b) {
    if (BF)
        asm volatile("mma.sync.aligned.m16n8k16.row.col.f32.bf16.bf16.f32 "
            "{%0,%1,%2,%3}, {%4,%5,%6,%7}, {%8,%9}, {%0,%1,%2,%3};\n"
            : "+f"(c[0]), "+f"(c[1]), "+f"(c[2]), "+f"(c[3])
            : "r"(a[0]), "r"(a[1]), "r"(a[2]), "r"(a[3]), "r"(b[0]), "r"(b[1]));
    else
        asm volatile("mma.sync.aligned.m16n8k16.row.col.f32.f16.f16.f32 "
            "{%0,%1,%2,%3}, {%4,%5,%6,%7}, {%8,%9}, {%0,%1,%2,%3};\n"
            : "+f"(c[0]), "+f"(c[1]), "+f"(c[2]), "+f"(c[3])
            : "r"(a[0]), "r"(a[1]), "r"(a[2]), "r"(a[3]), "r"(b[0]), "r"(b[1]));
}
__device__ __forceinline__ void ldsm4(unsigned* r, unsigned saddr) {
    asm volatile("ldmatrix.sync.aligned.m8n8.x4.shared.b16 {%0,%1,%2,%3}, [%4];"
        : "=r"(r[0]), "=r"(r[1]), "=r"(r[2]), "=r"(r[3]) : "r"(saddr));
}
__device__ __forceinline__ void ldsm4t(unsigned* r, unsigned saddr) {
    asm volatile("ldmatrix.sync.aligned.m8n8.x4.trans.shared.b16 {%0,%1,%2,%3}, [%4];"
        : "=r"(r[0]), "=r"(r[1]), "=r"(r[2]), "=r"(r[3]) : "r"(saddr));
}
__device__ __forceinline__ void cpa16(unsigned saddr, const void* g) {
    asm volatile("cp.async.cg.shared.global [%0], [%1], 16;" :: "r"(saddr), "l"(g));
}
__device__ __forceinline__ void cpa_commit() { asm volatile("cp.async.commit_group;"); }
__device__ __forceinline__ void cpa_wait1() { asm volatile("cp.async.wait_group 1;"); }
__device__ __forceinline__ void cpa_waitall() { asm volatile("cp.async.wait_group 0;"); }

// ---------------- convert weights + r to 16-bit ----------------
#define SEG_W  262144
#define SEG_R  524288
#define SEG_W1 1048576
#define CV_TOTAL (4 * SEG_W + SEG_R + SEG_W + 2 * SEG_W1)
__global__ __launch_bounds__(256) void convert_kernel(
    const float4* Wq, const float4* Wk, const float4* Wv, const float4* Wr,
    const float4* r, const float4* Wo, const float4* W1, const float4* W2,
    uint2* wq, uint2* wk, uint2* wv, uint2* wr,
    uint2* r16, uint2* wo, uint2* w1, uint2* w2)
{
    size_t i = (size_t)blockIdx.x * 256 + threadIdx.x;
    const float4* src; uint2* dst; size_t j; int bf;
    if      (i < 1 * SEG_W)          { src = Wq; dst = wq; j = i;               bf = 1; }
    else if (i < 2 * SEG_W)          { src = Wk; dst = wk; j = i - 1 * SEG_W;   bf = 1; }
    else if (i < 3 * SEG_W)          { src = Wv; dst = wv; j = i - 2 * SEG_W;   bf = 1; }
    else if (i < 4 * SEG_W)          { src = Wr; dst = wr; j = i - 3 * SEG_W;   bf = 1; }
    else if (i < 4 * SEG_W + SEG_R)  { src = r;  dst = r16; j = i - 4 * SEG_W;  bf = 1; }
    else if (i < 5 * SEG_W + SEG_R)  { src = Wo; dst = wo; j = i - 4 * SEG_W - SEG_R; bf = 0; }
    else if (i < 5 * SEG_W + SEG_R + SEG_W1)
        { src = W1; dst = w1; j = i - 5 * SEG_W - SEG_R; bf = 0; }
    else { src = W2; dst = w2; j = i - 5 * SEG_W - SEG_R - SEG_W1; bf = 0; }
    float4 f = src[j];
    if (bf) dst[j] = make_uint2(pack_bf2(f.x, f.y), pack_bf2(f.z, f.w));
    else    dst[j] = make_uint2(pack2<0>(f.x, f.y), pack2<0>(f.z, f.w));
}

// ---------------- cat = concat(member, w), bf16 output ----------------
__global__ __launch_bounds__(256) void copy_cat_kernel(
    const float4* __restrict__ w, const float4* __restrict__ member, uint2* __restrict__ cat)
{
    size_t i = (size_t)blockIdx.x * 256 + threadIdx.x;
    int e4 = (int)(i % (EE / 4));
    size_t t2 = i / (EE / 4);
    int kl = (int)(t2 % KLEN);
    int b  = (int)(t2 / KLEN);
    float4 v;
    if (kl < MLEN) v = member[((size_t)b * MLEN + kl) * (EE / 4) + e4];
    else           v = w[((size_t)b * QLEN + (kl - MLEN)) * (EE / 4) + e4];
    cat[i] = make_uint2(pack_bf2(v.x, v.y), pack_bf2(v.z, v.w));
}

// ================= all-half GEMM, 3-stage cp.async (R16, proven); z-batched =================
#define ABW 20
#define BBW 68
#define GH2_STG (128 * ABW + 32 * BBW)
#define GH2_SMEM (3 * GH2_STG * 4)
template<int BF, int OUT, int RELU, int QMODE>
__global__ __launch_bounds__(256, 2) void gemm_h2(
    const unsigned short* __restrict__ A0, const unsigned short* __restrict__ A1, int lda,
    const unsigned short* __restrict__ B0, const unsigned short* __restrict__ B1, int ldb,
    float* __restrict__ C0, float* __restrict__ C1, int ldc, int K)
{
    extern __shared__ __align__(16) unsigned dsm[];
    const unsigned sb = (unsigned)__cvta_generic_to_shared(dsm);

    const int z = blockIdx.z;
    const unsigned short* A = z ? A1 : A0;
    const unsigned short* B = z ? B1 : B0;
    float* C = z ? C1 : C0;

    const int t = threadIdx.x;
    const int lane = t & 31, warp = t >> 5;
    const int g = lane >> 2, tig = lane & 3;
    const int wm0 = (warp >> 2) * 64, wn0 = (warp & 3) * 32;
    const int m0 = blockIdx.y * 128, n0 = blockIdx.x * 128;
    const int moff = (QMODE && z == 0) ? (((m0 >> 10) + 1) << 10) : 0;

    const int l15 = lane & 15, lh = lane >> 4;
    const int bkl = (lane & 7) + 8 * ((lane >> 3) & 1);

    auto issue = [&](int kt3, int k0) {
        unsigned base = sb + kt3 * (GH2_STG * 4);
        #pragma unroll
        for (int i = 0; i < 2; i++) {
            int id = t + 256 * i;
            int row = id >> 2, ac = id & 3;
            cpa16(base + (row * ABW + ac * 4) * 4,
                  A + (size_t)(m0 + moff + row) * lda + k0 + ac * 8);
        }
        #pragma unroll
        for (int i = 0; i < 2; i++) {
            int id = t + 256 * i;
            int row = id >> 4, bc = id & 15;
            cpa16(base + (2560 + row * BBW + bc * 4) * 4,
                  B + (size_t)(k0 + row) * ldb + n0 + bc * 8);
        }
    };

    const int nk = K / 32;
    issue(0, 0); cpa_commit();
    issue(1, 32); cpa_commit();

    float c[4][4][4] = {};

    for (int kt = 0; kt < nk; kt++) {
        cpa_wait1();
        __syncthreads();
        if (kt + 2 < nk) issue((kt + 2) % 3, (kt + 2) * 32);
        cpa_commit();

        const unsigned sAb = sb + (kt % 3) * (GH2_STG * 4);
        const unsigned sBb = sAb + 2560 * 4;
        #pragma unroll
        for (int ksx = 0; ksx < 2; ksx++) {
            unsigned af[4][4];
            #pragma unroll
            for (int mi = 0; mi < 4; mi++)
                ldsm4(af[mi], sAb + (((wm0 + mi * 16 + l15) * ABW) + ksx * 8 + lh * 4) * 4);
            #pragma unroll
            for (int nb = 0; nb < 2; nb++) {
                unsigned br4[4];
                ldsm4t(br4, sBb + ((ksx * 16 + bkl) * BBW + (wn0 >> 1) + nb * 8 + 4 * lh) * 4);
                #pragma unroll
                for (int mi = 0; mi < 4; mi++) {
                    mmah<BF>(c[mi][2 * nb],     af[mi], br4);
                    mmah<BF>(c[mi][2 * nb + 1], af[mi], br4 + 2);
                }
            }
        }
    }

    #pragma unroll
    for (int mi = 0; mi < 4; mi++) {
        int row = m0 + wm0 + mi * 16 + g;
        #pragma unroll
        for (int ni = 0; ni < 4; ni++) {
            int col = n0 + wn0 + ni * 8 + 2 * tig;
            float v0 = c[mi][ni][0], v1 = c[mi][ni][1];
            float v2 = c[mi][ni][2], v3 = c[mi][ni][3];
            if (RELU) {
                v0 = fmaxf(v0, 0.f); v1 = fmaxf(v1, 0.f);
                v2 = fmaxf(v2, 0.f); v3 = fmaxf(v3, 0.f);
            }
            if (OUT == 1) {
                unsigned* Cu = (unsigned*)C;
                Cu[((size_t)row * ldc + col) / 2]       = pack_bf2(v0, v1);
                Cu[((size_t)(row + 8) * ldc + col) / 2] = pack_bf2(v2, v3);
            } else if (OUT == 2) {
                unsigned* Cu = (unsigned*)C;
                Cu[((size_t)row * ldc + col) / 2]       = pack2<0>(v0, v1);
                Cu[((size_t)(row + 8) * ldc + col) / 2] = pack2<0>(v2, v3);
            } else {
                *(float2*)&C[(size_t)row * ldc + col]       = make_float2(v0, v1);
                *(float2*)&C[(size_t)(row + 8) * ldc + col] = make_float2(v2, v3);
            }
        }
    }
}

// ================= flash attention: dual q-tile CTA, warp-row ownership =================
#define QS 36
#define GSW 68
#define OFF_QW 0
#define OFF_QR 18432
#define OFF_K  36864
#define OFF_V  73728
#define OFF_R  110592
#define OFF_G  147456
#define GBLK   34816
#define FA_SMEM 221184
#define K2C 0.04508422f   // 0.03125 * log2(e)

__global__ __launch_bounds__(256, 1) void flash_attn(
    const __nv_bfloat16* __restrict__ Qb, const __nv_bfloat16* __restrict__ Kb,
    const __nv_bfloat16* __restrict__ Vb, const __nv_bfloat16* __restrict__ Rb,
    const float* __restrict__ rwb, const float* __restrict__ rrb,
    unsigned* __restrict__ Om)
{
    extern __shared__ __align__(16) char smem[];
    unsigned*  uQw = (unsigned*)(smem + OFF_QW);
    unsigned*  uQr = (unsigned*)(smem + OFF_QR);
    const unsigned sb = (unsigned)__cvta_generic_to_shared(smem);

    const int t = threadIdx.x;
    const int lane = t & 31, warp = t >> 5;
    const int g = lane >> 2, tig = lane & 3;
    const int wm0 = warp * 16;
    const int l15 = lane & 15, lh = lane >> 4;
    const int bkl = (lane & 7) + 8 * ((lane >> 3) & 1);

    const int bh = blockIdx.z, b = bh >> 4, h = bh & 15;

    const __nv_bfloat16* gK = Kb + ((size_t)b * KLEN) * HD + h * DH;
    const __nv_bfloat16* gV = Vb + ((size_t)b * KLEN) * HD + h * DH;
    const __nv_bfloat16* gR = Rb + h * DH;

    const unsigned sQWb = sb + OFF_QW, sQRb = sb + OFF_QR;

    auto qkblock = [&](unsigned saddrA, unsigned saddrB, float (*acc)[4]) {
        #pragma unroll
        for (int ks = 0; ks < 4; ks++) {
            unsigned af[4];
            ldsm4(af, saddrA + ((wm0 + l15) * QS + ks * 8 + lh * 4) * 4);
            #pragma unroll
            for (int nb = 0; nb < 8; nb++) {
                unsigned b4[4];
                ldsm4(b4, saddrB + ((nb * 16 + l15) * QS + ks * 8 + lh * 4) * 4);
                unsigned bf0[2] = {b4[0], b4[2]}, bf1[2] = {b4[1], b4[3]};
                mma16(acc[2 * nb],     af, bf0);
                mma16(acc[2 * nb + 1], af, bf1);
            }
        }
    };

    #pragma unroll 1
    for (int half = 0; half < 2; half++) {
        const int qi = half == 0 ? (7 - (int)blockIdx.y) : (int)blockIdx.y;
        const int q0 = qi * 128;
        const int ntiles = qi + 9;

        __syncthreads();   // previous half's smem reads done before refill

        // prologue: K/V(0) + full 256-row R band
        {
            #pragma unroll
            for (int i = 0; i < 4; i++) {
                int id = t + 256 * i, row = id >> 3, ch = id & 7;
                cpa16(sb + OFF_K + row * 144 + ch * 16, gK + (size_t)row * HD + ch * 8);
                cpa16(sb + OFF_V + row * 144 + ch * 16, gV + (size_t)row * HD + ch * 8);
            }
            cpa_commit();
            int j0 = 0 - q0 + (QLEN - 128);
            #pragma unroll
            for (int i = 0; i < 8; i++) {
                int id = t + 256 * i, row = id >> 3, ch = id & 7;
                int j = j0 + row; if (j > KLEN - 1) j = KLEN - 1;
                cpa16(sb + OFF_R + row * 144 + ch * 16, gR + (size_t)j * HD + ch * 8);
            }
            cpa_commit();
        }

        // Q + biases (pre-scaled domain handled at gather)
        {
            const __nv_bfloat16* qsrc = Qb + ((size_t)b * QLEN + q0) * HD + h * DH;
            int lr = t >> 1, lc0 = (t & 1) * 32;
            #pragma unroll
            for (int i = 0; i < 8; i++) {
                int c = lc0 + i * 4;
                uint2 u = *(const uint2*)&qsrc[(size_t)lr * HD + c];
                __nv_bfloat162 q01 = *(__nv_bfloat162*)&u.x;
                __nv_bfloat162 q23 = *(__nv_bfloat162*)&u.y;
                float4 bw = *(const float4*)&rwb[h * DH + c];
                float4 br = *(const float4*)&rrb[h * DH + c];
                float f0 = __bfloat162float(q01.x), f1 = __bfloat162float(q01.y);
                float f2 = __bfloat162float(q23.x), f3 = __bfloat162float(q23.y);
                uQw[lr * QS + c / 2]     = pack_bf2(f0 + bw.x, f1 + bw.y);
                uQw[lr * QS + c / 2 + 1] = pack_bf2(f2 + bw.z, f3 + bw.w);
                uQr[lr * QS + c / 2]     = pack_bf2(f0 + br.x, f1 + br.y);
                uQr[lr * QS + c / 2 + 1] = pack_bf2(f2 + br.z, f3 + br.w);
            }
        }

        float o[8][4] = {};
        float mrun[2] = {-INFINITY, -INFINITY}, lrun[2] = {0.f, 0.f};

        int buf = 0;
        for (int kt = 0; kt < ntiles; kt++) {
            const int k0 = kt * 128;
            cpa_waitall();
            __syncthreads();

            if (kt + 1 < ntiles) {
                const __nv_bfloat16* nK = gK + (size_t)(k0 + 128) * HD;
                const __nv_bfloat16* nV = gV + (size_t)(k0 + 128) * HD;
                unsigned kb = OFF_K + (buf ^ 1) * 18432, vb2 = OFF_V + (buf ^ 1) * 18432;
                #pragma unroll
                for (int i = 0; i < 4; i++) {
                    int id = t + 256 * i, row = id >> 3, ch = id & 7;
                    cpa16(sb + kb + row * 144 + ch * 16, nK + (size_t)row * HD + ch * 8);
                    cpa16(sb + vb2 + row * 144 + ch * 16, nV + (size_t)row * HD + ch * 8);
                }
                cpa_commit();
            }

            float acc[16][4] = {};
            qkblock(sQWb, sb + OFF_K + buf * 18432, acc);

            auto gblock = [&](unsigned saddrR, unsigned* uGd) {
                float ga[16][4] = {};
                qkblock(sQRb, saddrR, ga);
                #pragma unroll
                for (int ni = 0; ni < 16; ni++)
                    #pragma unroll
                    for (int hh = 0; hh < 2; hh++) {
                        int r = wm0 + g + 8 * hh;
                        int col = ni * 8 + 2 * tig;
                        uGd[r * GSW + col / 2] = pack_bf2(ga[ni][2 * hh], ga[ni][2 * hh + 1]);
                    }
            };
            if (kt == 0)
                gblock(sb + OFF_R, (unsigned*)(smem + OFF_G));
            gblock(sb + OFF_R + ((kt + 1) & 1) * 18432,
                   (unsigned*)(smem + OFF_G + ((kt + 1) & 1) * GBLK));
            __syncthreads();

            if (kt + 1 < ntiles) {
                int jb = (k0 + 128) - q0 + (QLEN - 128) + 128;
                unsigned rb = OFF_R + (kt & 1) * 18432;
                #pragma unroll
                for (int i = 0; i < 4; i++) {
                    int id = t + 256 * i, row = id >> 3, ch = id & 7;
                    int j = jb + row; if (j > KLEN - 1) j = KLEN - 1;
                    cpa16(sb + rb + row * 144 + ch * 16, gR + (size_t)j * HD + ch * 8);
                }
                cpa_commit();
            }

            // gather shifted BD + mask + scale (exp2 domain)
            {
                const __nv_bfloat16* hGL = (const __nv_bfloat16*)(smem + OFF_G + (kt & 1) * GBLK);
                const __nv_bfloat16* hGH = (const __nv_bfloat16*)(smem + OFF_G + ((kt + 1) & 1) * GBLK);
                #pragma unroll
                for (int ni = 0; ni < 16; ni++)
                    #pragma unroll
                    for (int hh = 0; hh < 2; hh++)
                        #pragma unroll
                        for (int e = 0; e < 2; e++) {
                            int r = wm0 + g + 8 * hh;
                            int col = ni * 8 + 2 * tig + e;
                            int c = col - r + 127;
                            float bd = __bfloat162float(
                                (c < 128) ? hGL[r * 136 + c] : hGH[r * 136 + (c - 128)]);
                            float s = acc[ni][2 * hh + e] + bd;
                            acc[ni][2 * hh + e] =
                                ((k0 + col) <= (q0 + r) + MLEN) ? s * K2C : -1e30f;
                        }
            }

            // warp-local softmax (exp2 domain)
            float fsc[2];
            #pragma unroll
            for (int hh = 0; hh < 2; hh++) {
                float m8 = -INFINITY;
                #pragma unroll
                for (int ni = 0; ni < 16; ni++)
                    m8 = fmaxf(m8, fmaxf(acc[ni][2 * hh], acc[ni][2 * hh + 1]));
                m8 = fmaxf(m8, __shfl_xor_sync(0xffffffffu, m8, 1));
                m8 = fmaxf(m8, __shfl_xor_sync(0xffffffffu, m8, 2));
                float sw = 0.f;
                #pragma unroll
                for (int ni = 0; ni < 16; ni++)
                    #pragma unroll
                    for (int e = 0; e < 2; e++) {
                        float p = ex2(acc[ni][2 * hh + e] - m8);
                        acc[ni][2 * hh + e] = p;
                        sw += p;
                    }
                sw += __shfl_xor_sync(0xffffffffu, sw, 1);
                sw += __shfl_xor_sync(0xffffffffu, sw, 2);
                float mnew = fmaxf(mrun[hh], m8);
                float alpha = ex2(mrun[hh] - mnew);
                lrun[hh] = lrun[hh] * alpha + sw * ex2(m8 - mnew);
                mrun[hh] = mnew;
                fsc[hh] = ex2(m8 - mnew);
                #pragma unroll
                for (int ni2 = 0; ni2 < 8; ni2++) {
                    o[ni2][2 * hh]     *= alpha;
                    o[ni2][2 * hh + 1] *= alpha;
                }
            }

            unsigned* uP = (unsigned*)(smem + OFF_G + (kt & 1) * GBLK);
            const unsigned sP = sb + OFF_G + (kt & 1) * GBLK;
            #pragma unroll
            for (int ni = 0; ni < 16; ni++)
                #pragma unroll
                for (int hh = 0; hh < 2; hh++) {
                    int r = wm0 + g + 8 * hh;
                    int col = ni * 8 + 2 * tig;
                    uP[r * GSW + col / 2] = pack_bf2(
                        acc[ni][2 * hh] * fsc[hh], acc[ni][2 * hh + 1] * fsc[hh]);
                }
            __syncwarp();

            {
                const unsigned sV = sb + OFF_V + buf * 18432;
                #pragma unroll
                for (int ks = 0; ks < 8; ks++) {
                    unsigned af[4];
                    ldsm4(af, sP + ((wm0 + l15) * GSW + ks * 8 + lh * 4) * 4);
                    #pragma unroll
                    for (int nb = 0; nb < 4; nb++) {
                        unsigned bv[4];
                        ldsm4t(bv, sV + ((ks * 16 + bkl) * QS + nb * 8 + 4 * lh) * 4);
                        mma16(o[2 * nb],     af, bv);
                        mma16(o[2 * nb + 1], af, bv + 2);
                    }
                }
            }
            buf ^= 1;
        }

        // epilogue: O /= l, write fp16
        #pragma unroll
        for (int ni2 = 0; ni2 < 8; ni2++)
            #pragma unroll
            for (int hh = 0; hh < 2; hh++) {
                int r = wm0 + g + 8 * hh;
                int d = ni2 * 8 + 2 * tig;
                float inv = 1.0f / lrun[hh];
                Om[(((size_t)b * QLEN + q0 + r) * HD + h * DH + d) / 2] =
                    pack2<0>(o[ni2][2 * hh] * inv, o[ni2][2 * hh + 1] * inv);
            }
    }
}

// ---------------- out = LayerNorm(a + b); optional fp16 copy ----------------
__global__ __launch_bounds__(256) void add_ln_kernel(
    const float* __restrict__ A, const float* __restrict__ Bv,
    const float* __restrict__ gamma, const float* __restrict__ beta,
    float* __restrict__ out, unsigned* __restrict__ out16)
{
    __shared__ float red[256];
    const size_t row = blockIdx.x;
    const int t = threadIdx.x;
    float4 va = ((const float4*)(A + row * EE))[t];
    float4 vb = ((const float4*)(Bv + row * EE))[t];
    float4 v = make_float4(va.x + vb.x, va.y + vb.y, va.z + vb.z, va.w + vb.w);

    red[t] = v.x + v.y + v.z + v.w; __syncthreads();
    for (int s = 128; s > 0; s >>= 1) { if (t < s) red[t] += red[t + s]; __syncthreads(); }
    const float mean = red[0] * (1.0f / EE); __syncthreads();

    float dx = v.x - mean, dy = v.y - mean, dz = v.z - mean, dw = v.w - mean;
    red[t] = dx * dx + dy * dy + dz * dz + dw * dw; __syncthreads();
    for (int s = 128; s > 0; s >>= 1) { if (t < s) red[t] += red[t + s]; __syncthreads(); }
    const float inv = rsqrtf(red[0] * (1.0f / EE) + 1e-3f);

    float4 gm = ((const float4*)gamma)[t];
    float4 bt = ((const float4*)beta)[t];
    float4 o;
    o.x = dx * inv * gm.x + bt.x; o.y = dy * inv * gm.y + bt.y;
    o.z = dz * inv * gm.z + bt.z; o.w = dw * inv * gm.w + bt.w;
    ((float4*)(out + row * EE))[t] = o;
    if (out16)
        ((uint2*)(out16 + row * EE / 2))[t] =
            make_uint2(pack2<0>(o.x, o.y), pack2<0>(o.z, o.w));
}

// ---------------- launch ----------------
extern "C" void kernel_launch(void* const* d_in, const int* in_sizes, int n_in,
                              void* d_out, int out_size)
{
    const float* w      = (const float*)d_in[0];
    const float* r      = (const float*)d_in[1];
    const float* member = (const float*)d_in[2];
    const float* Wq  = (const float*)d_in[4];
    const float* Wk  = (const float*)d_in[5];
    const float* Wv  = (const float*)d_in[6];
    const float* Wr  = (const float*)d_in[7];
    const float* Wo  = (const float*)d_in[8];
    const float* rwb = (const float*)d_in[9];
    const float* rrb = (const float*)d_in[10];
    const float* ln1g = (const float*)d_in[11];
    const float* ln1b = (const float*)d_in[12];
    const float* W1  = (const float*)d_in[13];
    const float* W2  = (const float*)d_in[14];
    const float* ln2g = (const float*)d_in[15];
    const float* ln2b = (const float*)d_in[16];
    float* out = (float*)d_out;

    static float *p_cat = nullptr, *p_q, *p_k, *p_v, *p_r,
                 *p_att, *p_o, *p_x, *p_x16, *p_ffn, *p_y,
                 *p_wq, *p_wk, *p_wv, *p_wr, *p_r16, *p_wo, *p_w1, *p_w2;
    if (!p_cat) {
        cudaGetSymbolAddress((void**)&p_cat, g_cat);
        cudaGetSymbolAddress((void**)&p_q,   g_q);
        cudaGetSymbolAddress((void**)&p_k,   g_k);
        cudaGetSymbolAddress((void**)&p_v,   g_v);
        cudaGetSymbolAddress((void**)&p_r,   g_r);
        cudaGetSymbolAddress((void**)&p_att, g_att);
        cudaGetSymbolAddress((void**)&p_o,   g_o);
        cudaGetSymbolAddress((void**)&p_x,   g_x);
        cudaGetSymbolAddress((void**)&p_x16, g_x16);
        cudaGetSymbolAddress((void**)&p_ffn, g_ffn);
        cudaGetSymbolAddress((void**)&p_y,   g_y);
        cudaGetSymbolAddress((void**)&p_wq,  g_wq16);
        cudaGetSymbolAddress((void**)&p_wk,  g_wk16);
        cudaGetSymbolAddress((void**)&p_wv,  g_wv16);
        cudaGetSymbolAddress((void**)&p_wr,  g_wr16);
        cudaGetSymbolAddress((void**)&p_r16, g_r16);
        cudaGetSymbolAddress((void**)&p_wo,  g_wo16);
        cudaGetSymbolAddress((void**)&p_w1,  g_w116);
        cudaGetSymbolAddress((void**)&p_w2,  g_w216);
        cudaFuncSetAttribute(flash_attn, cudaFuncAttributeMaxDynamicSharedMemorySize, FA_SMEM);
        cudaFuncSetAttribute(gemm_h2<1,1,0,0>, cudaFuncAttributeMaxDynamicSharedMemorySize, GH2_SMEM);
        cudaFuncSetAttribute(gemm_h2<1,1,0,1>, cudaFuncAttributeMaxDynamicSharedMemorySize, GH2_SMEM);
        cudaFuncSetAttribute(gemm_h2<0,0,0,0>, cudaFuncAttributeMaxDynamicSharedMemorySize, GH2_SMEM);
        cudaFuncSetAttribute(gemm_h2<0,2,1,0>, cudaFuncAttributeMaxDynamicSharedMemorySize, GH2_SMEM);
    }

    // 0. convert weights + r to 16-bit
    convert_kernel<<<CV_TOTAL / 256, 256>>>(
        (const float4*)Wq, (const float4*)Wk, (const float4*)Wv, (const float4*)Wr,
        (const float4*)r, (const float4*)Wo, (const float4*)W1, (const float4*)W2,
        (uint2*)p_wq, (uint2*)p_wk, (uint2*)p_wv, (uint2*)p_wr,
        (uint2*)p_r16, (uint2*)p_wo, (uint2*)p_w1, (uint2*)p_w2);

    // 1. cat (bf16)
    copy_cat_kernel<<<(BB * KLEN * EE / 4) / 256, 256>>>(
        (const float4*)w, (const float4*)member, (uint2*)p_cat);

    // 2. projections, z-batched: {Wk, Wv} then {Wq(QMODE), Wr}
    gemm_h2<1,1,0,0><<<dim3(HD / 128, (BB * KLEN) / 128, 2), 256, GH2_SMEM>>>(
        (const unsigned short*)p_cat, (const unsigned short*)p_cat, EE,
        (const unsigned short*)p_wk, (const unsigned short*)p_wv, HD,
        p_k, p_v, HD, EE);
    gemm_h2<1,1,0,1><<<dim3(HD / 128, (BB * QLEN) / 128, 2), 256, GH2_SMEM>>>(
        (const unsigned short*)p_cat, (const unsigned short*)p_r16, EE,
        (const unsigned short*)p_wq, (const unsigned short*)p_wr, HD,
        p_q, p_r, HD, EE);

    // 3. fused attention (dual q-tile CTAs, fp16 O out)
    flash_attn<<<dim3(1, 4, BB * HH), 256, FA_SMEM>>>(
        (const __nv_bfloat16*)p_q, (const __nv_bfloat16*)p_k,
        (const __nv_bfloat16*)p_v, (const __nv_bfloat16*)p_r,
        rwb, rrb, (unsigned*)p_att);

    // 4. output projection (fp16) + LN1 (f32 + fp16 copy)
    gemm_h2<0,0,0,0><<<dim3(EE / 128, (BB * QLEN) / 128), 256, GH2_SMEM>>>(
        (const unsigned short*)p_att, nullptr, HD,
        (const unsigned short*)p_wo, nullptr, EE, p_o, nullptr, EE, HD);
    add_ln_kernel<<<BB * QLEN, 256>>>(w, p_o, ln1g, ln1b, p_x, (unsigned*)p_x16);

    // 5. FFN (fp16) + LN2 -> out
    gemm_h2<0,2,1,0><<<dim3(FF / 128, (BB * QLEN) / 128), 256, GH2_SMEM>>>(
        (const unsigned short*)p_x16, nullptr, EE,
        (const unsigned short*)p_w1, nullptr, FF, p_ffn, nullptr, FF, EE);
    gemm_h2<0,0,0,0><<<dim3(EE / 128, (BB * QLEN) / 128), 256, GH2_SMEM>>>(
        (const unsigned short*)p_ffn, nullptr, FF,
        (const unsigned short*)p_w2, nullptr, EE, p_y, nullptr, EE, FF);
    add_ln_kernel<<<BB * QLEN, 256>>>(p_y, p_x, ln2g, ln2b, out, nullptr);
}